// round 6
// baseline (speedup 1.0000x reference)
#include <cuda_runtime.h>
#include <cuda_bf16.h>
#include <math.h>
#include <stdint.h>

#define BDIM 8
#define TDIM 8192
#define BT (BDIM*TDIM)
#define HDIM 512
#define SSDIM 32

typedef unsigned long long u64;

// ---------------- scratch (device globals; no allocations allowed) ----------
__device__ float g_hf[BT*64];
__device__ float g_h[BT*HDIM];
__device__ float g_h2[BT*HDIM];
__device__ float g_gates[BDIM*SSDIM*TDIM];
__device__ float g_drive[BDIM*SSDIM*TDIM];
__device__ float g_states[BDIM*SSDIM*TDIM];
// int8 quantized activations (2-level split) + per-row scale
__device__ int8_t g_qa1[(size_t)BT*512];
__device__ int8_t g_qa2[(size_t)BT*512];
__device__ float  g_sx[BT];
// int8 quantized transposed weights [layer][n*512+k] + per-col scale
__device__ int8_t g_wq1[4][512*512];
__device__ int8_t g_wq2[4][512*512];
__device__ float  g_sw[4][512];

__device__ __forceinline__ float silu_f(float x) { return x / (1.f + __expf(-x)); }

__device__ __forceinline__ u64 pack2(float x) {
    u64 r; asm("mov.b64 %0, {%1, %1};" : "=l"(r) : "f"(x)); return r;
}
__device__ __forceinline__ void ffma2(u64& d, u64 a, u64 b) {
    asm("fma.rn.f32x2 %0, %1, %2, %3;" : "=l"(d) : "l"(a), "l"(b), "l"(d));
}
__device__ __forceinline__ float lo32(u64 v) { return __uint_as_float((unsigned)v); }
__device__ __forceinline__ float hi32(u64 v) { return __uint_as_float((unsigned)(v >> 32)); }

// ---------------- mma.sync / async helpers (arch-agnostic, sm_80+) ----------
__device__ __forceinline__ uint32_t smem_u32(const void* p) {
    uint32_t a;
    asm("{ .reg .u64 t; cvta.to.shared.u64 t, %1; cvt.u32.u64 %0, t; }" : "=r"(a) : "l"(p));
    return a;
}
#define CP_COMMIT()      asm volatile("cp.async.commit_group;" ::: "memory")
#define CP_WAIT1()       asm volatile("cp.async.wait_group 1;" ::: "memory")
#define CP_WAIT0()       asm volatile("cp.async.wait_group 0;" ::: "memory")

__device__ __forceinline__ void cpasync16(uint32_t dst, const void* src) {
    asm volatile("cp.async.cg.shared.global [%0], [%1], 16;" :: "r"(dst), "l"(src));
}
__device__ __forceinline__ void ldmx4(uint32_t* r, uint32_t addr) {
    asm volatile("ldmatrix.sync.aligned.m8n8.x4.shared.b16 {%0,%1,%2,%3}, [%4];"
        : "=r"(r[0]), "=r"(r[1]), "=r"(r[2]), "=r"(r[3]) : "r"(addr));
}
__device__ __forceinline__ void imma(int* c, const uint32_t* a, uint32_t b0, uint32_t b1) {
    asm volatile("mma.sync.aligned.m16n8k32.row.col.s32.s8.s8.s32 "
        "{%0,%1,%2,%3}, {%4,%5,%6,%7}, {%8,%9}, {%0,%1,%2,%3};"
        : "+r"(c[0]), "+r"(c[1]), "+r"(c[2]), "+r"(c[3])
        : "r"(a[0]), "r"(a[1]), "r"(a[2]), "r"(a[3]), "r"(b0), "r"(b1));
}
// 16B-granular XOR swizzle within a 128B row
__device__ __forceinline__ uint32_t tile_addr(uint32_t tbase, int row, int c16) {
    return tbase + row * 128 + ((c16 ^ (row & 7)) << 4);
}

// ---------------------------------------------------------------------------
// K1: rolling hashes + scale attention -> g_hf (verified)
// ---------------------------------------------------------------------------
__global__ void __launch_bounds__(256) k_hashfeat(
    const int* __restrict__ chars, const float* __restrict__ emb_byte,
    const float* __restrict__ htab, const float* __restrict__ Wq,
    const float* __restrict__ bq)
{
    int gw = (blockIdx.x * blockDim.x + threadIdx.x) >> 5;
    if (gw >= BT) return;
    int lane = threadIdx.x & 31;
    int wip  = threadIdx.x >> 5;
    int b = gw / TDIM, t = gw % TDIM;
    const int* cb = chars + b * TDIM;

    int myc = (lane < 16 && t >= lane) ? cb[t - lane] : 0;

    int acc0 = 0, acc1 = 0, acc2 = 0, acc3 = 0;
    int p = 1;
#pragma unroll
    for (int j = 0; j < 16; j++) {
        int cj = __shfl_sync(0xffffffffu, myc, j);
        int term = cj * p;
        if (j < 2) acc0 += term;
        if (j < 4) acc1 += term;
        if (j < 8) acc2 += term;
        acc3 += term;
        p = (p * 257) & 4095;
    }
    int h0 = acc0 & 4095, h1 = acc1 & 4095, h2 = acc2 & 4095, h3 = acc3 & 4095;

    int c0 = lane * 2;
    int ch0 = __shfl_sync(0xffffffffu, myc, 0);
    float2 be = *(const float2*)&emb_byte[ch0 * 64 + c0];

    __shared__ float s_be[8][64];
    s_be[wip][c0]     = be.x;
    s_be[wip][c0 + 1] = be.y;
    __syncwarp();

    float q0 = bq[c0], q1 = bq[c0 + 1];
#pragma unroll 8
    for (int k = 0; k < 64; k++) {
        float bk = s_be[wip][k];
        float2 wv = *(const float2*)&Wq[k * 64 + c0];
        q0 = fmaf(bk, wv.x, q0);
        q1 = fmaf(bk, wv.y, q1);
    }

    float2 se0 = *(const float2*)&htab[(size_t)(0 * 4096 + h0) * 64 + c0];
    float2 se1 = *(const float2*)&htab[(size_t)(1 * 4096 + h1) * 64 + c0];
    float2 se2 = *(const float2*)&htab[(size_t)(2 * 4096 + h2) * 64 + c0];
    float2 se3 = *(const float2*)&htab[(size_t)(3 * 4096 + h3) * 64 + c0];

    float s0 = q0 * se0.x + q1 * se0.y;
    float s1 = q0 * se1.x + q1 * se1.y;
    float s2 = q0 * se2.x + q1 * se2.y;
    float s3 = q0 * se3.x + q1 * se3.y;
#pragma unroll
    for (int off = 16; off; off >>= 1) {
        s0 += __shfl_xor_sync(0xffffffffu, s0, off);
        s1 += __shfl_xor_sync(0xffffffffu, s1, off);
        s2 += __shfl_xor_sync(0xffffffffu, s2, off);
        s3 += __shfl_xor_sync(0xffffffffu, s3, off);
    }
    s0 *= 0.125f; s1 *= 0.125f; s2 *= 0.125f; s3 *= 0.125f;
    float m = fmaxf(fmaxf(s0, s1), fmaxf(s2, s3));
    float e0 = __expf(s0 - m), e1 = __expf(s1 - m), e2 = __expf(s2 - m), e3 = __expf(s3 - m);
    float inv = 1.f / (e0 + e1 + e2 + e3);
    float o0 = (e0 * se0.x + e1 * se1.x + e2 * se2.x + e3 * se3.x) * inv;
    float o1 = (e0 * se0.y + e1 * se1.y + e2 * se2.y + e3 * se3.y) * inv;
    *(float2*)&g_hf[(size_t)gw * 64 + c0] = make_float2(o0, o1);
}

// ---------------------------------------------------------------------------
// K2: features + Win GEMM (verified)
// ---------------------------------------------------------------------------
__global__ void __launch_bounds__(256) k_feat_win(
    const int* __restrict__ chars, const float* __restrict__ emb_byte,
    const float* __restrict__ conv_w, const float* __restrict__ conv_b,
    const float* __restrict__ Win, const float* __restrict__ b_in)
{
    __shared__ float sxt[132][32];
    __shared__ int sch[32];
    int blk = blockIdx.x;
    int b = blk / (TDIM / 32);
    int tBase = (blk % (TDIM / 32)) * 32;
    int tid = threadIdx.x;
    const int* cb = chars + b * TDIM;

    if (tid < 32) sch[tid] = cb[tBase + tid];
    __syncthreads();

    for (int idx = tid; idx < 32 * 64; idx += 256) {
        int tok = idx >> 6, c = idx & 63;
        sxt[c][tok] = emb_byte[sch[tok] * 64 + c];
    }
    for (int idx = tid; idx < 32 * 64; idx += 256) {
        int tok = idx >> 6, c = idx & 63;
        int t = tBase + tok;
        float acc = conv_b[c];
#pragma unroll
        for (int k = 0; k < 4; k++) {
            int tt = t - 3 + k;
            float v = (tt >= 0) ? g_hf[(size_t)(b * TDIM + tt) * 64 + c] : 0.f;
            acc = fmaf(conv_w[c * 4 + k], v, acc);
        }
        sxt[64 + c][tok] = silu_f(acc);
    }
    for (int idx = tid; idx < 128; idx += 256) {
        int tok = idx >> 2, mm = idx & 3;
        int k = 1 << mm;
        int t = tBase + tok;
        float v = 0.f;
        if (t >= k) v = (cb[t] == cb[t - k]) ? 1.f : 0.f;
        sxt[128 + mm][tok] = v;
    }
    __syncthreads();

    u64 acc[16][2];
#pragma unroll
    for (int i = 0; i < 16; i++) { acc[i][0] = 0ull; acc[i][1] = 0ull; }

#pragma unroll 1
    for (int k4 = 0; k4 < 132; k4 += 4) {
        u64 wp[4][2];
#pragma unroll
        for (int j = 0; j < 4; j++) {
            wp[j][0] = pack2(Win[(size_t)(k4 + j) * 512 + tid]);
            wp[j][1] = pack2(Win[(size_t)(k4 + j) * 512 + tid + 256]);
        }
#pragma unroll
        for (int j = 0; j < 4; j++) {
            const ulonglong2* xr = (const ulonglong2*)&sxt[k4 + j][0];
#pragma unroll
            for (int q = 0; q < 8; q++) {
                ulonglong2 x2 = xr[q];
                ffma2(acc[2 * q][0],     x2.x, wp[j][0]);
                ffma2(acc[2 * q][1],     x2.x, wp[j][1]);
                ffma2(acc[2 * q + 1][0], x2.y, wp[j][0]);
                ffma2(acc[2 * q + 1][1], x2.y, wp[j][1]);
            }
        }
    }
#pragma unroll
    for (int cc = 0; cc < 2; cc++) {
        int col = tid + cc * 256;
        float bv = b_in[col];
#pragma unroll
        for (int p = 0; p < 16; p++) {
            size_t r0 = (size_t)(b * TDIM + tBase + 2 * p) * 512 + col;
            g_h[r0]       = silu_f(lo32(acc[p][cc]) + bv);
            g_h[r0 + 512] = silu_f(hi32(acc[p][cc]) + bv);
        }
    }
}

// ---------------------------------------------------------------------------
// K3: gates/drive (verified)
// ---------------------------------------------------------------------------
__global__ void __launch_bounds__(256) k_gates(
    const float* __restrict__ Wg, const float* __restrict__ bg,
    const float* __restrict__ Wi, const float* __restrict__ bi)
{
    __shared__ u64 smbuf[4096];
    float (*sxt)[32] = reinterpret_cast<float(*)[32]>(smbuf);

    int tid = threadIdx.x;
    int col = tid & 63;
    int ks  = tid >> 6;
    int n0 = blockIdx.x * 32;
    int b = n0 / TDIM, t0 = n0 % TDIM;

    u64 acc[16];
#pragma unroll
    for (int i = 0; i < 16; i++) acc[i] = 0ull;

    const float* Wsel = (col < 32) ? Wg : Wi;
    int wcol = col & 31;

    for (int kb = 0; kb < 512; kb += 128) {
        __syncthreads();
        for (int i = tid; i < 32 * 32; i += 256) {
            int tok = i & 31;
            int k4 = (i >> 5) << 2;
            float4 v = *(const float4*)&g_h[(size_t)(n0 + tok) * 512 + kb + k4];
            sxt[k4][tok] = v.x; sxt[k4 + 1][tok] = v.y;
            sxt[k4 + 2][tok] = v.z; sxt[k4 + 3][tok] = v.w;
        }
        __syncthreads();
        int kBase = ks * 32;
#pragma unroll 1
        for (int k = 0; k < 32; k++) {
            u64 wv = pack2(Wsel[(size_t)(kb + kBase + k) * 32 + wcol]);
            const ulonglong2* xr = (const ulonglong2*)&sxt[kBase + k][0];
#pragma unroll
            for (int q = 0; q < 8; q++) {
                ulonglong2 x2 = xr[q];
                ffma2(acc[2 * q],     x2.x, wv);
                ffma2(acc[2 * q + 1], x2.y, wv);
            }
        }
    }
    __syncthreads();
#pragma unroll
    for (int p = 0; p < 16; p++) smbuf[((size_t)ks * 64 + col) * 16 + p] = acc[p];
    __syncthreads();
    if (ks == 0 && col < 32) {
        int j = col;
        float bgv = bg[j], biv = bi[j];
        float* gout = g_gates + (size_t)(b * SSDIM + j) * TDIM + t0;
        float* dout = g_drive + (size_t)(b * SSDIM + j) * TDIM + t0;
#pragma unroll
        for (int p = 0; p < 16; p++) {
            float ag0 = bgv, ag1 = bgv, ai0 = biv, ai1 = biv;
#pragma unroll
            for (int s = 0; s < 4; s++) {
                u64 vg = smbuf[((size_t)s * 64 + j) * 16 + p];
                u64 vi = smbuf[((size_t)s * 64 + 32 + j) * 16 + p];
                ag0 += lo32(vg); ag1 += hi32(vg);
                ai0 += lo32(vi); ai1 += hi32(vi);
            }
            float g0 = 1.f / (1.f + __expf(-ag0));
            float g1 = 1.f / (1.f + __expf(-ag1));
            gout[2 * p]     = g0;
            gout[2 * p + 1] = g1;
            dout[2 * p]     = (1.f - g0) * ai0;
            dout[2 * p + 1] = (1.f - g1) * ai1;
        }
    }
}

// ---------------------------------------------------------------------------
// K4: chunk-parallel TinyScan (verified)
// ---------------------------------------------------------------------------
__global__ void __launch_bounds__(256) k_scan()
{
    int bs = blockIdx.x;
    int j = threadIdx.x;
    const float* ga = g_gates + (size_t)bs * TDIM + j * 32;
    const float* dr = g_drive + (size_t)bs * TDIM + j * 32;
    float a[32], bb[32];
#pragma unroll
    for (int i = 0; i < 32; i++) {
        a[i]  = fmaxf(ga[i], 1e-6f);
        bb[i] = dr[i];
    }
    float cumA = 1.f, cumWB = 0.f;
#pragma unroll
    for (int i = 0; i < 32; i++) {
        cumA *= a[i];
        float inv = 1.f / fmaxf(cumA, 1e-8f);
        cumWB = fmaf(bb[i], inv, cumWB);
    }
    __shared__ float sA[256], sB[256];
    sA[j] = cumA;
    sB[j] = cumA * cumWB;
    __syncthreads();
    for (int d = 1; d < 256; d <<= 1) {
        float a2 = sA[j], b2 = sB[j], a1 = 0.f, b1 = 0.f;
        if (j >= d) { a1 = sA[j - d]; b1 = sB[j - d]; }
        __syncthreads();
        if (j >= d) { sA[j] = a2 * a1; sB[j] = fmaf(a2, b1, b2); }
        __syncthreads();
    }
    float hc = (j == 0) ? 0.f : sB[j - 1];
    cumA = 1.f; cumWB = 0.f;
    float* st = g_states + (size_t)bs * TDIM + j * 32;
#pragma unroll
    for (int i = 0; i < 32; i++) {
        cumA *= a[i];
        float inv = 1.f / fmaxf(cumA, 1e-8f);
        cumWB = fmaf(bb[i], inv, cumWB);
        st[i] = cumA * (hc + cumWB);
    }
}

// ---------------------------------------------------------------------------
// K5a: y = h + states@Wo + bo (verified)
// ---------------------------------------------------------------------------
__global__ void __launch_bounds__(256) k_wo(
    const float* __restrict__ Wo, const float* __restrict__ bo)
{
    __shared__ float sxt[32][32];
    int tid = threadIdx.x;
    int n0 = blockIdx.x * 32;
    int b = n0 / TDIM, t0 = n0 % TDIM;

    for (int i = tid; i < 32 * 8; i += 256) {
        int s = i >> 3, t4 = (i & 7) * 4;
        float4 v = *(const float4*)&g_states[(size_t)(b * SSDIM + s) * TDIM + t0 + t4];
        *(float4*)&sxt[s][t4] = v;
    }
    __syncthreads();

    u64 acc[16][2];
#pragma unroll
    for (int i = 0; i < 16; i++) { acc[i][0] = 0ull; acc[i][1] = 0ull; }

#pragma unroll 1
    for (int k4 = 0; k4 < 32; k4 += 4) {
        u64 wp[4][2];
#pragma unroll
        for (int j = 0; j < 4; j++) {
            wp[j][0] = pack2(Wo[(size_t)(k4 + j) * 512 + tid]);
            wp[j][1] = pack2(Wo[(size_t)(k4 + j) * 512 + tid + 256]);
        }
#pragma unroll
        for (int j = 0; j < 4; j++) {
            const ulonglong2* xr = (const ulonglong2*)&sxt[k4 + j][0];
#pragma unroll
            for (int q = 0; q < 8; q++) {
                ulonglong2 x2 = xr[q];
                ffma2(acc[2 * q][0],     x2.x, wp[j][0]);
                ffma2(acc[2 * q][1],     x2.x, wp[j][1]);
                ffma2(acc[2 * q + 1][0], x2.y, wp[j][0]);
                ffma2(acc[2 * q + 1][1], x2.y, wp[j][1]);
            }
        }
    }
#pragma unroll
    for (int cc = 0; cc < 2; cc++) {
        int col = tid + cc * 256;
        float bv = bo[col];
#pragma unroll
        for (int p = 0; p < 16; p++) {
            size_t r0 = (size_t)(n0 + 2 * p) * 512 + col;
            g_h2[r0]       = lo32(acc[p][cc]) + bv + g_h[r0];
            g_h2[r0 + 512] = hi32(acc[p][cc]) + bv + g_h[r0 + 512];
        }
    }
}

// ---------------------------------------------------------------------------
// K5b: in-place LayerNorm over g_h2 rows
// ---------------------------------------------------------------------------
__global__ void __launch_bounds__(128) k_ln(
    const float* __restrict__ lng, const float* __restrict__ lnb)
{
    int n = blockIdx.x;
    int tid = threadIdx.x;
    int c = tid * 4;
    float4 y = *(const float4*)&g_h2[(size_t)n * 512 + c];
    float lsum = y.x + y.y + y.z + y.w;
    float lsq  = y.x * y.x + y.y * y.y + y.z * y.z + y.w * y.w;
#pragma unroll
    for (int off = 16; off; off >>= 1) {
        lsum += __shfl_xor_sync(0xffffffffu, lsum, off);
        lsq  += __shfl_xor_sync(0xffffffffu, lsq,  off);
    }
    __shared__ float red[4][2];
    int wip = tid >> 5, lane = tid & 31;
    if (lane == 0) { red[wip][0] = lsum; red[wip][1] = lsq; }
    __syncthreads();
    lsum = red[0][0] + red[1][0] + red[2][0] + red[3][0];
    lsq  = red[0][1] + red[1][1] + red[2][1] + red[3][1];
    float mu = lsum * (1.f / 512.f);
    float var = lsq * (1.f / 512.f) - mu * mu;
    float rstd = rsqrtf(var + 1e-5f);
    float4 g4 = *(const float4*)&lng[c];
    float4 b4 = *(const float4*)&lnb[c];
    float4 o;
    o.x = (y.x - mu) * rstd * g4.x + b4.x;
    o.y = (y.y - mu) * rstd * g4.y + b4.y;
    o.z = (y.z - mu) * rstd * g4.z + b4.z;
    o.w = (y.w - mu) * rstd * g4.w + b4.w;
    *(float4*)&g_h2[(size_t)n * 512 + c] = o;
}

// ---------------------------------------------------------------------------
// Activation quantize: warp per token. Xint = round(x/sx), sx = rowmax/16256,
// A1 = round(Xint/128) in [-127,127], A2 = Xint-128*A1 in [-64,64]
// ---------------------------------------------------------------------------
__global__ void __launch_bounds__(256) k_quant(const float* __restrict__ X)
{
    int gw = blockIdx.x * 8 + (threadIdx.x >> 5);
    int lane = threadIdx.x & 31;
    const float* row = X + (size_t)gw * 512;
    int c0 = lane * 16;
    float4 v[4];
    float mx = 0.f;
#pragma unroll
    for (int i = 0; i < 4; i++) {
        v[i] = *(const float4*)&row[c0 + i * 4];
        mx = fmaxf(mx, fmaxf(fmaxf(fabsf(v[i].x), fabsf(v[i].y)),
                             fmaxf(fabsf(v[i].z), fabsf(v[i].w))));
    }
#pragma unroll
    for (int off = 16; off; off >>= 1)
        mx = fmaxf(mx, __shfl_xor_sync(0xffffffffu, mx, off));
    float sx  = mx * (1.f / 16256.f);
    float inv = (mx > 0.f) ? 16256.f / mx : 0.f;
    if (lane == 0) g_sx[gw] = sx;
    char q1[16], q2[16];
#pragma unroll
    for (int i = 0; i < 4; i++) {
        float xs[4] = {v[i].x, v[i].y, v[i].z, v[i].w};
#pragma unroll
        for (int e = 0; e < 4; e++) {
            float xq = rintf(xs[e] * inv);
            float a1 = rintf(xq * (1.f / 128.f));
            float a2 = xq - 128.f * a1;
            q1[i * 4 + e] = (char)(int)a1;
            q2[i * 4 + e] = (char)(int)a2;
        }
    }
    *(int4*)&g_qa1[(size_t)gw * 512 + c0] = *(int4*)q1;
    *(int4*)&g_qa2[(size_t)gw * 512 + c0] = *(int4*)q2;
}

// ---------------------------------------------------------------------------
// Weight quantize (transpose + 2-level int8 split), warp per output col
// ---------------------------------------------------------------------------
__global__ void __launch_bounds__(256) k_prep_wi(
    const float* __restrict__ W, int N, int layer)
{
    int n = blockIdx.x * 8 + (threadIdx.x >> 5);
    int lane = threadIdx.x & 31;
    if (n >= N) return;
    float w[16];
    float mx = 0.f;
#pragma unroll
    for (int i = 0; i < 16; i++) {
        w[i] = W[(size_t)(lane + 32 * i) * N + n];
        mx = fmaxf(mx, fabsf(w[i]));
    }
#pragma unroll
    for (int off = 16; off; off >>= 1)
        mx = fmaxf(mx, __shfl_xor_sync(0xffffffffu, mx, off));
    float inv = (mx > 0.f) ? 16256.f / mx : 0.f;
    if (lane == 0) g_sw[layer][n] = mx * (1.f / 16256.f);
#pragma unroll
    for (int i = 0; i < 16; i++) {
        float wq = rintf(w[i] * inv);
        float b1 = rintf(wq * (1.f / 128.f));
        float b2 = wq - 128.f * b1;
        int k = lane + 32 * i;
        g_wq1[layer][(size_t)n * 512 + k] = (char)(int)b1;
        g_wq2[layer][(size_t)n * 512 + k] = (char)(int)b2;
    }
}

// ---------------------------------------------------------------------------
// Int8 split IMMA GEMM: Xint*Wint = 16384*c1 + 128*c2 (+dropped A2B2)
// CTA: 128 x 128 x K=512; 8 warps 64x32; KT=128 int8/stage, 3-stage cp.async
// EPI: 1 = res + silu(v+bias) -> yf (stride 512); 0 = v+bias -> yf (stride NOUT)
// ---------------------------------------------------------------------------
#define ISTG 65536
#define SMEM_MI (3 * ISTG)

template<int NOUT, int EPI>
__global__ void __launch_bounds__(256) k_mma_i(
    const int8_t* __restrict__ qa1, const int8_t* __restrict__ qa2,
    const float* __restrict__ sxv,
    const int8_t* __restrict__ wq1, const int8_t* __restrict__ wq2,
    const float* __restrict__ swv,
    const float* __restrict__ bias, const float* __restrict__ xres,
    float* __restrict__ yf)
{
    extern __shared__ char dsm[];
    uint32_t smem0 = smem_u32(dsm);
    int tid = threadIdx.x;
    int wid = tid >> 5, lane = tid & 31;
    int wm = wid >> 2, wn = wid & 3;
    int m0 = blockIdx.x * 128;
    int n0 = blockIdx.y * 128;

    int c1a[4][4][4], c2a[4][4][4];
#pragma unroll
    for (int i = 0; i < 4; i++)
#pragma unroll
        for (int j = 0; j < 4; j++)
#pragma unroll
            for (int e = 0; e < 4; e++) { c1a[i][j][e] = 0; c2a[i][j][e] = 0; }

    auto fill = [&](int kt) {
        int stage = kt % 3;
        int kb = kt * 128;
        uint32_t sb = smem0 + stage * ISTG;
#pragma unroll
        for (int j = 0; j < 16; j++) {
            int cidx = tid + 256 * j;
            int tile = cidx >> 10;
            int idx = cidx & 1023;
            int row = idx >> 3;
            int c16 = idx & 7;
            uint32_t dst = sb + tile * 16384 + row * 128 + ((c16 ^ (row & 7)) << 4);
            const int8_t* src;
            if (tile == 0)      src = qa1 + (size_t)(m0 + row) * 512 + kb + c16 * 16;
            else if (tile == 1) src = qa2 + (size_t)(m0 + row) * 512 + kb + c16 * 16;
            else if (tile == 2) src = wq1 + (size_t)(n0 + row) * 512 + kb + c16 * 16;
            else                src = wq2 + (size_t)(n0 + row) * 512 + kb + c16 * 16;
            cpasync16(dst, (const void*)src);
        }
        CP_COMMIT();
    };

    fill(0);
    fill(1);

    int la = lane & 15, lh = lane >> 4;

    for (int i = 0; i < 4; i++) {
        uint32_t sb = smem0 + (i % 3) * ISTG;
        if (i < 3) { CP_WAIT1(); } else { CP_WAIT0(); }
        __syncthreads();
        if (i + 2 < 4) fill(i + 2);

#pragma unroll
        for (int kc = 0; kc < 4; kc++) {
            int c16 = kc * 2 + lh;
            uint32_t a1f[4][4], a2f[4][4], b1f[2][4], b2f[2][4];
#pragma unroll
            for (int mt = 0; mt < 4; mt++)
                ldmx4(a1f[mt], tile_addr(sb,         wm * 64 + mt * 16 + la, c16));
#pragma unroll
            for (int mt = 0; mt < 4; mt++)
                ldmx4(a2f[mt], tile_addr(sb + 16384, wm * 64 + mt * 16 + la, c16));
#pragma unroll
            for (int g = 0; g < 2; g++)
                ldmx4(b1f[g], tile_addr(sb + 32768, wn * 32 + g * 16 + la, c16));
#pragma unroll
            for (int g = 0; g < 2; g++)
                ldmx4(b2f[g], tile_addr(sb + 49152, wn * 32 + g * 16 + la, c16));
#pragma unroll
            for (int mt = 0; mt < 4; mt++) {
#pragma unroll
                for (int j = 0; j < 4; j++) {
                    int g = j >> 1, h = j & 1;
                    imma(c1a[mt][j], a1f[mt], b1f[g][h], b1f[g][2 + h]);
                    imma(c2a[mt][j], a1f[mt], b2f[g][h], b2f[g][2 + h]);
                    imma(c2a[mt][j], a2f[mt], b1f[g][h], b1f[g][2 + h]);
                }
            }
        }
    }

    // ---- epilogue from registers ----
    int r0 = lane >> 2;
    int cp = (lane & 3) * 2;
#pragma unroll
    for (int j = 0; j < 4; j++) {
        int col = n0 + wn * 32 + j * 8 + cp;
        float2 bv = *(const float2*)&bias[col];
        float sw0 = swv[col] * 128.f, sw1 = swv[col + 1] * 128.f;
#pragma unroll
        for (int mt = 0; mt < 4; mt++) {
#pragma unroll
            for (int half = 0; half < 2; half++) {
                int row = m0 + wm * 64 + mt * 16 + r0 + half * 8;
                float sxr = sxv[row];
                int comb0 = c1a[mt][j][2 * half]     * 128 + c2a[mt][j][2 * half];
                int comb1 = c1a[mt][j][2 * half + 1] * 128 + c2a[mt][j][2 * half + 1];
                float v0 = (float)comb0 * (sxr * sw0) + bv.x;
                float v1 = (float)comb1 * (sxr * sw1) + bv.y;
                if (EPI == 1) {
                    float2 xr = *(const float2*)&xres[(size_t)row * 512 + col];
                    v0 = xr.x + silu_f(v0);
                    v1 = xr.y + silu_f(v1);
                }
                *(float2*)&yf[(size_t)row * NOUT + col] = make_float2(v0, v1);
            }
        }
    }
}

// ---------------------------------------------------------------------------
extern "C" void kernel_launch(void* const* d_in, const int* in_sizes, int n_in,
                              void* d_out, int out_size)
{
    const int*   chars    = (const int*)d_in[0];
    const float* emb_byte = (const float*)d_in[1];
    const float* htab     = (const float*)d_in[2];
    const float* Wq       = (const float*)d_in[3];
    const float* bq       = (const float*)d_in[4];
    const float* conv_w   = (const float*)d_in[5];
    const float* conv_b   = (const float*)d_in[6];
    const float* Win      = (const float*)d_in[7];
    const float* b_in     = (const float*)d_in[8];
    const float* Wg       = (const float*)d_in[9];
    const float* bg       = (const float*)d_in[10];
    const float* Wi       = (const float*)d_in[11];
    const float* bi       = (const float*)d_in[12];
    const float* Wo       = (const float*)d_in[13];
    const float* bo       = (const float*)d_in[14];
    const float* lng      = (const float*)d_in[15];
    const float* lnb      = (const float*)d_in[16];
    const float* mlp_w    = (const float*)d_in[17];
    const float* mlp_b    = (const float*)d_in[18];
    const float* Wout     = (const float*)d_in[19];
    const float* bout     = (const float*)d_in[20];
    float* out = (float*)d_out;

    void *p;
    cudaGetSymbolAddress(&p, g_h);   float* gh   = (float*)p;
    cudaGetSymbolAddress(&p, g_h2);  float* gh2  = (float*)p;
    cudaGetSymbolAddress(&p, g_qa1); int8_t* qa1 = (int8_t*)p;
    cudaGetSymbolAddress(&p, g_qa2); int8_t* qa2 = (int8_t*)p;
    cudaGetSymbolAddress(&p, g_sx);  float* sx   = (float*)p;
    cudaGetSymbolAddress(&p, g_wq1); int8_t* wq1 = (int8_t*)p;
    cudaGetSymbolAddress(&p, g_wq2); int8_t* wq2 = (int8_t*)p;
    cudaGetSymbolAddress(&p, g_sw);  float* sw   = (float*)p;

    static int attr_done = 0;
    if (!attr_done) {
        cudaFuncSetAttribute(k_mma_i<512,1>, cudaFuncAttributeMaxDynamicSharedMemorySize, SMEM_MI);
        cudaFuncSetAttribute(k_mma_i<256,0>, cudaFuncAttributeMaxDynamicSharedMemorySize, SMEM_MI);
        attr_done = 1;
    }

    // weight quantization (int8 2-level split + transpose)
    k_prep_wi<<<512 / 8, 256>>>(mlp_w,                 512, 0);
    k_prep_wi<<<512 / 8, 256>>>(mlp_w + 512 * 512,     512, 1);
    k_prep_wi<<<512 / 8, 256>>>(mlp_w + 2 * 512 * 512, 512, 2);
    k_prep_wi<<<256 / 8, 256>>>(Wout,                  256, 3);

    k_hashfeat<<<BT / 8, 256>>>(chars, emb_byte, htab, Wq, bq);
    k_feat_win<<<BT / 32, 256>>>(chars, emb_byte, conv_w, conv_b, Win, b_in);
    k_gates<<<BT / 32, 256>>>(Wg, bg, Wi, bi);
    k_scan<<<BDIM * SSDIM, 256>>>();
    k_wo<<<BT / 32, 256>>>(Wo, bo);
    k_ln<<<BT, 128>>>(lng, lnb);

    dim3 g512(BT / 128, 4), g256(BT / 128, 2);
    // L1: x = ln_out (g_h2) -> y1 = x + silu(x@W0+b) -> g_h
    k_quant<<<BT / 8, 256>>>(gh2);
    k_mma_i<512,1><<<g512, 256, SMEM_MI>>>(qa1, qa2, sx,
        wq1 + 0 * (size_t)512 * 512, wq2 + 0 * (size_t)512 * 512, sw + 0 * 512,
        mlp_b, gh2, gh);
    // L2: g_h -> g_h2
    k_quant<<<BT / 8, 256>>>(gh);
    k_mma_i<512,1><<<g512, 256, SMEM_MI>>>(qa1, qa2, sx,
        wq1 + 1 * (size_t)512 * 512, wq2 + 1 * (size_t)512 * 512, sw + 1 * 512,
        mlp_b + 512, gh, gh2);
    // L3: g_h2 -> g_h
    k_quant<<<BT / 8, 256>>>(gh2);
    k_mma_i<512,1><<<g512, 256, SMEM_MI>>>(qa1, qa2, sx,
        wq1 + 2 * (size_t)512 * 512, wq2 + 2 * (size_t)512 * 512, sw + 2 * 512,
        mlp_b + 1024, gh2, gh);
    // Wout: g_h -> out
    k_quant<<<BT / 8, 256>>>(gh);
    k_mma_i<256,0><<<g256, 256, SMEM_MI>>>(qa1, qa2, sx,
        wq1 + 3 * (size_t)512 * 512, wq2 + 3 * (size_t)512 * 512, sw + 3 * 512,
        bout, 0, out);
}

// round 7
// speedup vs baseline: 1.3344x; 1.3344x over previous
#include <cuda_runtime.h>
#include <cuda_bf16.h>
#include <math.h>
#include <stdint.h>

#define BDIM 8
#define TDIM 8192
#define BT (BDIM*TDIM)
#define HDIM 512
#define SSDIM 32

typedef unsigned long long u64;

// ---------------- scratch (device globals; no allocations allowed) ----------
__device__ float g_hf[BT*64];
__device__ float g_h[BT*HDIM];
__device__ float g_h2[BT*HDIM];
__device__ float g_gates[BDIM*SSDIM*TDIM];
__device__ float g_drive[BDIM*SSDIM*TDIM];
__device__ float g_states[BDIM*SSDIM*TDIM];
// bf16 split activations (ping/pong pairs)
__device__ __nv_bfloat16 g_xh[(size_t)BT*512];
__device__ __nv_bfloat16 g_xl[(size_t)BT*512];
__device__ __nv_bfloat16 g_x2h[(size_t)BT*512];
__device__ __nv_bfloat16 g_x2l[(size_t)BT*512];
// bf16 split transposed weights [layer][n*512+k]
__device__ __nv_bfloat16 g_wbh[4][512*512];
__device__ __nv_bfloat16 g_wbl[4][512*512];

__device__ __forceinline__ float silu_f(float x) { return x / (1.f + __expf(-x)); }

__device__ __forceinline__ u64 pack2(float x) {
    u64 r; asm("mov.b64 %0, {%1, %1};" : "=l"(r) : "f"(x)); return r;
}
__device__ __forceinline__ void ffma2(u64& d, u64 a, u64 b) {
    asm("fma.rn.f32x2 %0, %1, %2, %3;" : "=l"(d) : "l"(a), "l"(b), "l"(d));
}
__device__ __forceinline__ float lo32(u64 v) { return __uint_as_float((unsigned)v); }
__device__ __forceinline__ float hi32(u64 v) { return __uint_as_float((unsigned)(v >> 32)); }

// ---------------- mma.sync / async helpers (arch-agnostic, sm_80+) ----------
__device__ __forceinline__ uint32_t smem_u32(const void* p) {
    uint32_t a;
    asm("{ .reg .u64 t; cvta.to.shared.u64 t, %1; cvt.u32.u64 %0, t; }" : "=r"(a) : "l"(p));
    return a;
}
#define CP_COMMIT()      asm volatile("cp.async.commit_group;" ::: "memory")
#define CP_WAIT1()       asm volatile("cp.async.wait_group 1;" ::: "memory")
#define CP_WAIT0()       asm volatile("cp.async.wait_group 0;" ::: "memory")

__device__ __forceinline__ void cpasync16(uint32_t dst, const void* src) {
    asm volatile("cp.async.cg.shared.global [%0], [%1], 16;" :: "r"(dst), "l"(src));
}
__device__ __forceinline__ void ldmx4(uint32_t* r, uint32_t addr) {
    asm volatile("ldmatrix.sync.aligned.m8n8.x4.shared.b16 {%0,%1,%2,%3}, [%4];"
        : "=r"(r[0]), "=r"(r[1]), "=r"(r[2]), "=r"(r[3]) : "r"(addr));
}
__device__ __forceinline__ void mma16816(float* c, const uint32_t* a,
                                         uint32_t b0, uint32_t b1) {
    asm volatile("mma.sync.aligned.m16n8k16.row.col.f32.bf16.bf16.f32 "
        "{%0,%1,%2,%3}, {%4,%5,%6,%7}, {%8,%9}, {%0,%1,%2,%3};"
        : "+f"(c[0]), "+f"(c[1]), "+f"(c[2]), "+f"(c[3])
        : "r"(a[0]), "r"(a[1]), "r"(a[2]), "r"(a[3]), "r"(b0), "r"(b1));
}
// 16B-granular XOR swizzle within a 128B row (conflict-free ldmatrix)
__device__ __forceinline__ uint32_t tile_addr(uint32_t tbase, int row, int c16) {
    return tbase + row * 128 + ((c16 ^ (row & 7)) << 4);
}

// ---------------------------------------------------------------------------
// K1: rolling hashes + scale attention -> g_hf (verified)
// ---------------------------------------------------------------------------
__global__ void __launch_bounds__(256) k_hashfeat(
    const int* __restrict__ chars, const float* __restrict__ emb_byte,
    const float* __restrict__ htab, const float* __restrict__ Wq,
    const float* __restrict__ bq)
{
    int gw = (blockIdx.x * blockDim.x + threadIdx.x) >> 5;
    if (gw >= BT) return;
    int lane = threadIdx.x & 31;
    int wip  = threadIdx.x >> 5;
    int b = gw / TDIM, t = gw % TDIM;
    const int* cb = chars + b * TDIM;

    int myc = (lane < 16 && t >= lane) ? cb[t - lane] : 0;

    int acc0 = 0, acc1 = 0, acc2 = 0, acc3 = 0;
    int p = 1;
#pragma unroll
    for (int j = 0; j < 16; j++) {
        int cj = __shfl_sync(0xffffffffu, myc, j);
        int term = cj * p;
        if (j < 2) acc0 += term;
        if (j < 4) acc1 += term;
        if (j < 8) acc2 += term;
        acc3 += term;
        p = (p * 257) & 4095;
    }
    int h0 = acc0 & 4095, h1 = acc1 & 4095, h2 = acc2 & 4095, h3 = acc3 & 4095;

    int c0 = lane * 2;
    int ch0 = __shfl_sync(0xffffffffu, myc, 0);
    float2 be = *(const float2*)&emb_byte[ch0 * 64 + c0];

    __shared__ float s_be[8][64];
    s_be[wip][c0]     = be.x;
    s_be[wip][c0 + 1] = be.y;
    __syncwarp();

    float q0 = bq[c0], q1 = bq[c0 + 1];
#pragma unroll 8
    for (int k = 0; k < 64; k++) {
        float bk = s_be[wip][k];
        float2 wv = *(const float2*)&Wq[k * 64 + c0];
        q0 = fmaf(bk, wv.x, q0);
        q1 = fmaf(bk, wv.y, q1);
    }

    float2 se0 = *(const float2*)&htab[(size_t)(0 * 4096 + h0) * 64 + c0];
    float2 se1 = *(const float2*)&htab[(size_t)(1 * 4096 + h1) * 64 + c0];
    float2 se2 = *(const float2*)&htab[(size_t)(2 * 4096 + h2) * 64 + c0];
    float2 se3 = *(const float2*)&htab[(size_t)(3 * 4096 + h3) * 64 + c0];

    float s0 = q0 * se0.x + q1 * se0.y;
    float s1 = q0 * se1.x + q1 * se1.y;
    float s2 = q0 * se2.x + q1 * se2.y;
    float s3 = q0 * se3.x + q1 * se3.y;
#pragma unroll
    for (int off = 16; off; off >>= 1) {
        s0 += __shfl_xor_sync(0xffffffffu, s0, off);
        s1 += __shfl_xor_sync(0xffffffffu, s1, off);
        s2 += __shfl_xor_sync(0xffffffffu, s2, off);
        s3 += __shfl_xor_sync(0xffffffffu, s3, off);
    }
    s0 *= 0.125f; s1 *= 0.125f; s2 *= 0.125f; s3 *= 0.125f;
    float m = fmaxf(fmaxf(s0, s1), fmaxf(s2, s3));
    float e0 = __expf(s0 - m), e1 = __expf(s1 - m), e2 = __expf(s2 - m), e3 = __expf(s3 - m);
    float inv = 1.f / (e0 + e1 + e2 + e3);
    float o0 = (e0 * se0.x + e1 * se1.x + e2 * se2.x + e3 * se3.x) * inv;
    float o1 = (e0 * se0.y + e1 * se1.y + e2 * se2.y + e3 * se3.y) * inv;
    *(float2*)&g_hf[(size_t)gw * 64 + c0] = make_float2(o0, o1);
}

// ---------------------------------------------------------------------------
// K2: features + Win GEMM (verified)
// ---------------------------------------------------------------------------
__global__ void __launch_bounds__(256) k_feat_win(
    const int* __restrict__ chars, const float* __restrict__ emb_byte,
    const float* __restrict__ conv_w, const float* __restrict__ conv_b,
    const float* __restrict__ Win, const float* __restrict__ b_in)
{
    __shared__ float sxt[132][32];
    __shared__ int sch[32];
    int blk = blockIdx.x;
    int b = blk / (TDIM / 32);
    int tBase = (blk % (TDIM / 32)) * 32;
    int tid = threadIdx.x;
    const int* cb = chars + b * TDIM;

    if (tid < 32) sch[tid] = cb[tBase + tid];
    __syncthreads();

    for (int idx = tid; idx < 32 * 64; idx += 256) {
        int tok = idx >> 6, c = idx & 63;
        sxt[c][tok] = emb_byte[sch[tok] * 64 + c];
    }
    for (int idx = tid; idx < 32 * 64; idx += 256) {
        int tok = idx >> 6, c = idx & 63;
        int t = tBase + tok;
        float acc = conv_b[c];
#pragma unroll
        for (int k = 0; k < 4; k++) {
            int tt = t - 3 + k;
            float v = (tt >= 0) ? g_hf[(size_t)(b * TDIM + tt) * 64 + c] : 0.f;
            acc = fmaf(conv_w[c * 4 + k], v, acc);
        }
        sxt[64 + c][tok] = silu_f(acc);
    }
    for (int idx = tid; idx < 128; idx += 256) {
        int tok = idx >> 2, mm = idx & 3;
        int k = 1 << mm;
        int t = tBase + tok;
        float v = 0.f;
        if (t >= k) v = (cb[t] == cb[t - k]) ? 1.f : 0.f;
        sxt[128 + mm][tok] = v;
    }
    __syncthreads();

    u64 acc[16][2];
#pragma unroll
    for (int i = 0; i < 16; i++) { acc[i][0] = 0ull; acc[i][1] = 0ull; }

#pragma unroll 1
    for (int k4 = 0; k4 < 132; k4 += 4) {
        u64 wp[4][2];
#pragma unroll
        for (int j = 0; j < 4; j++) {
            wp[j][0] = pack2(Win[(size_t)(k4 + j) * 512 + tid]);
            wp[j][1] = pack2(Win[(size_t)(k4 + j) * 512 + tid + 256]);
        }
#pragma unroll
        for (int j = 0; j < 4; j++) {
            const ulonglong2* xr = (const ulonglong2*)&sxt[k4 + j][0];
#pragma unroll
            for (int q = 0; q < 8; q++) {
                ulonglong2 x2 = xr[q];
                ffma2(acc[2 * q][0],     x2.x, wp[j][0]);
                ffma2(acc[2 * q][1],     x2.x, wp[j][1]);
                ffma2(acc[2 * q + 1][0], x2.y, wp[j][0]);
                ffma2(acc[2 * q + 1][1], x2.y, wp[j][1]);
            }
        }
    }
#pragma unroll
    for (int cc = 0; cc < 2; cc++) {
        int col = tid + cc * 256;
        float bv = b_in[col];
#pragma unroll
        for (int p = 0; p < 16; p++) {
            size_t r0 = (size_t)(b * TDIM + tBase + 2 * p) * 512 + col;
            g_h[r0]       = silu_f(lo32(acc[p][cc]) + bv);
            g_h[r0 + 512] = silu_f(hi32(acc[p][cc]) + bv);
        }
    }
}

// ---------------------------------------------------------------------------
// K3: gates/drive (verified)
// ---------------------------------------------------------------------------
__global__ void __launch_bounds__(256) k_gates(
    const float* __restrict__ Wg, const float* __restrict__ bg,
    const float* __restrict__ Wi, const float* __restrict__ bi)
{
    __shared__ u64 smbuf[4096];
    float (*sxt)[32] = reinterpret_cast<float(*)[32]>(smbuf);

    int tid = threadIdx.x;
    int col = tid & 63;
    int ks  = tid >> 6;
    int n0 = blockIdx.x * 32;
    int b = n0 / TDIM, t0 = n0 % TDIM;

    u64 acc[16];
#pragma unroll
    for (int i = 0; i < 16; i++) acc[i] = 0ull;

    const float* Wsel = (col < 32) ? Wg : Wi;
    int wcol = col & 31;

    for (int kb = 0; kb < 512; kb += 128) {
        __syncthreads();
        for (int i = tid; i < 32 * 32; i += 256) {
            int tok = i & 31;
            int k4 = (i >> 5) << 2;
            float4 v = *(const float4*)&g_h[(size_t)(n0 + tok) * 512 + kb + k4];
            sxt[k4][tok] = v.x; sxt[k4 + 1][tok] = v.y;
            sxt[k4 + 2][tok] = v.z; sxt[k4 + 3][tok] = v.w;
        }
        __syncthreads();
        int kBase = ks * 32;
#pragma unroll 1
        for (int k = 0; k < 32; k++) {
            u64 wv = pack2(Wsel[(size_t)(kb + kBase + k) * 32 + wcol]);
            const ulonglong2* xr = (const ulonglong2*)&sxt[kBase + k][0];
#pragma unroll
            for (int q = 0; q < 8; q++) {
                ulonglong2 x2 = xr[q];
                ffma2(acc[2 * q],     x2.x, wv);
                ffma2(acc[2 * q + 1], x2.y, wv);
            }
        }
    }
    __syncthreads();
#pragma unroll
    for (int p = 0; p < 16; p++) smbuf[((size_t)ks * 64 + col) * 16 + p] = acc[p];
    __syncthreads();
    if (ks == 0 && col < 32) {
        int j = col;
        float bgv = bg[j], biv = bi[j];
        float* gout = g_gates + (size_t)(b * SSDIM + j) * TDIM + t0;
        float* dout = g_drive + (size_t)(b * SSDIM + j) * TDIM + t0;
#pragma unroll
        for (int p = 0; p < 16; p++) {
            float ag0 = bgv, ag1 = bgv, ai0 = biv, ai1 = biv;
#pragma unroll
            for (int s = 0; s < 4; s++) {
                u64 vg = smbuf[((size_t)s * 64 + j) * 16 + p];
                u64 vi = smbuf[((size_t)s * 64 + 32 + j) * 16 + p];
                ag0 += lo32(vg); ag1 += hi32(vg);
                ai0 += lo32(vi); ai1 += hi32(vi);
            }
            float g0 = 1.f / (1.f + __expf(-ag0));
            float g1 = 1.f / (1.f + __expf(-ag1));
            gout[2 * p]     = g0;
            gout[2 * p + 1] = g1;
            dout[2 * p]     = (1.f - g0) * ai0;
            dout[2 * p + 1] = (1.f - g1) * ai1;
        }
    }
}

// ---------------------------------------------------------------------------
// K4: chunk-parallel TinyScan (verified)
// ---------------------------------------------------------------------------
__global__ void __launch_bounds__(256) k_scan()
{
    int bs = blockIdx.x;
    int j = threadIdx.x;
    const float* ga = g_gates + (size_t)bs * TDIM + j * 32;
    const float* dr = g_drive + (size_t)bs * TDIM + j * 32;
    float a[32], bb[32];
#pragma unroll
    for (int i = 0; i < 32; i++) {
        a[i]  = fmaxf(ga[i], 1e-6f);
        bb[i] = dr[i];
    }
    float cumA = 1.f, cumWB = 0.f;
#pragma unroll
    for (int i = 0; i < 32; i++) {
        cumA *= a[i];
        float inv = 1.f / fmaxf(cumA, 1e-8f);
        cumWB = fmaf(bb[i], inv, cumWB);
    }
    __shared__ float sA[256], sB[256];
    sA[j] = cumA;
    sB[j] = cumA * cumWB;
    __syncthreads();
    for (int d = 1; d < 256; d <<= 1) {
        float a2 = sA[j], b2 = sB[j], a1 = 0.f, b1 = 0.f;
        if (j >= d) { a1 = sA[j - d]; b1 = sB[j - d]; }
        __syncthreads();
        if (j >= d) { sA[j] = a2 * a1; sB[j] = fmaf(a2, b1, b2); }
        __syncthreads();
    }
    float hc = (j == 0) ? 0.f : sB[j - 1];
    cumA = 1.f; cumWB = 0.f;
    float* st = g_states + (size_t)bs * TDIM + j * 32;
#pragma unroll
    for (int i = 0; i < 32; i++) {
        cumA *= a[i];
        float inv = 1.f / fmaxf(cumA, 1e-8f);
        cumWB = fmaf(bb[i], inv, cumWB);
        st[i] = cumA * (hc + cumWB);
    }
}

// ---------------------------------------------------------------------------
// K5a: y = h + states@Wo + bo (verified)
// ---------------------------------------------------------------------------
__global__ void __launch_bounds__(256) k_wo(
    const float* __restrict__ Wo, const float* __restrict__ bo)
{
    __shared__ float sxt[32][32];
    int tid = threadIdx.x;
    int n0 = blockIdx.x * 32;
    int b = n0 / TDIM, t0 = n0 % TDIM;

    for (int i = tid; i < 32 * 8; i += 256) {
        int s = i >> 3, t4 = (i & 7) * 4;
        float4 v = *(const float4*)&g_states[(size_t)(b * SSDIM + s) * TDIM + t0 + t4];
        *(float4*)&sxt[s][t4] = v;
    }
    __syncthreads();

    u64 acc[16][2];
#pragma unroll
    for (int i = 0; i < 16; i++) { acc[i][0] = 0ull; acc[i][1] = 0ull; }

#pragma unroll 1
    for (int k4 = 0; k4 < 32; k4 += 4) {
        u64 wp[4][2];
#pragma unroll
        for (int j = 0; j < 4; j++) {
            wp[j][0] = pack2(Wo[(size_t)(k4 + j) * 512 + tid]);
            wp[j][1] = pack2(Wo[(size_t)(k4 + j) * 512 + tid + 256]);
        }
#pragma unroll
        for (int j = 0; j < 4; j++) {
            const ulonglong2* xr = (const ulonglong2*)&sxt[k4 + j][0];
#pragma unroll
            for (int q = 0; q < 8; q++) {
                ulonglong2 x2 = xr[q];
                ffma2(acc[2 * q][0],     x2.x, wp[j][0]);
                ffma2(acc[2 * q][1],     x2.x, wp[j][1]);
                ffma2(acc[2 * q + 1][0], x2.y, wp[j][0]);
                ffma2(acc[2 * q + 1][1], x2.y, wp[j][1]);
            }
        }
    }
#pragma unroll
    for (int cc = 0; cc < 2; cc++) {
        int col = tid + cc * 256;
        float bv = bo[col];
#pragma unroll
        for (int p = 0; p < 16; p++) {
            size_t r0 = (size_t)(n0 + 2 * p) * 512 + col;
            g_h2[r0]       = lo32(acc[p][cc]) + bv + g_h[r0];
            g_h2[r0 + 512] = hi32(acc[p][cc]) + bv + g_h[r0 + 512];
        }
    }
}

// ---------------------------------------------------------------------------
// K5b: LayerNorm + bf16 hi/lo split write for the tensor path
// ---------------------------------------------------------------------------
__global__ void __launch_bounds__(128) k_ln(
    const float* __restrict__ lng, const float* __restrict__ lnb)
{
    int n = blockIdx.x;
    int tid = threadIdx.x;
    int c = tid * 4;
    float4 y = *(const float4*)&g_h2[(size_t)n * 512 + c];
    float lsum = y.x + y.y + y.z + y.w;
    float lsq  = y.x * y.x + y.y * y.y + y.z * y.z + y.w * y.w;
#pragma unroll
    for (int off = 16; off; off >>= 1) {
        lsum += __shfl_xor_sync(0xffffffffu, lsum, off);
        lsq  += __shfl_xor_sync(0xffffffffu, lsq,  off);
    }
    __shared__ float red[4][2];
    int wip = tid >> 5, lane = tid & 31;
    if (lane == 0) { red[wip][0] = lsum; red[wip][1] = lsq; }
    __syncthreads();
    lsum = red[0][0] + red[1][0] + red[2][0] + red[3][0];
    lsq  = red[0][1] + red[1][1] + red[2][1] + red[3][1];
    float mu = lsum * (1.f / 512.f);
    float var = lsq * (1.f / 512.f) - mu * mu;
    float rstd = rsqrtf(var + 1e-5f);
    float4 g4 = *(const float4*)&lng[c];
    float4 b4 = *(const float4*)&lnb[c];
    float4 o;
    o.x = (y.x - mu) * rstd * g4.x + b4.x;
    o.y = (y.y - mu) * rstd * g4.y + b4.y;
    o.z = (y.z - mu) * rstd * g4.z + b4.z;
    o.w = (y.w - mu) * rstd * g4.w + b4.w;
    *(float4*)&g_h2[(size_t)n * 512 + c] = o;
    float vs[4] = {o.x, o.y, o.z, o.w};
    __nv_bfloat16 bh[4], bl[4];
#pragma unroll
    for (int e = 0; e < 4; e++) {
        bh[e] = __float2bfloat16_rn(vs[e]);
        bl[e] = __float2bfloat16_rn(vs[e] - __bfloat162float(bh[e]));
    }
    size_t base = (size_t)n * 512 + c;
    *(__nv_bfloat162*)&g_xh[base]     = *(__nv_bfloat162*)&bh[0];
    *(__nv_bfloat162*)&g_xh[base + 2] = *(__nv_bfloat162*)&bh[2];
    *(__nv_bfloat162*)&g_xl[base]     = *(__nv_bfloat162*)&bl[0];
    *(__nv_bfloat162*)&g_xl[base + 2] = *(__nv_bfloat162*)&bl[2];
}

// ---------------------------------------------------------------------------
// Weight prep: split W[k][N] f32 into transposed bf16 hi/lo [n*512+k]
// ---------------------------------------------------------------------------
__global__ void __launch_bounds__(256) k_prep_w(
    const float* __restrict__ W, int N, int layer)
{
    int idx = blockIdx.x * 256 + threadIdx.x;
    int k = idx & 511;
    int n = idx >> 9;
    if (n >= N) return;
    float w = W[(size_t)k * N + n];
    __nv_bfloat16 h = __float2bfloat16_rn(w);
    __nv_bfloat16 l = __float2bfloat16_rn(w - __bfloat162float(h));
    g_wbh[layer][(size_t)n * 512 + k] = h;
    g_wbl[layer][(size_t)n * 512 + k] = l;
}

// ---------------------------------------------------------------------------
// Split-bf16 mma.sync GEMM: D = Xh@Wh' + Xl@Wh' + Xh@Wl'  (fp32 accum)
// CTA: 128x128xK512. 4 warps (2x2), warp tile 64x64 -> 96 MMAs per 16 ldmx4
// per kc (MMA-bound, not LDSM-bound). 3-stage cp.async, KT=64.
// ---------------------------------------------------------------------------
#define NKT 8
#define STAGE_BYTES 65536
#define SMEM_MM (3 * STAGE_BYTES)

template<int NOUT, int RESACT, int SPLIT, int WF32>
__global__ void __launch_bounds__(128) k_mma(
    const __nv_bfloat16* __restrict__ xh, const __nv_bfloat16* __restrict__ xl,
    const float* __restrict__ xres,
    const __nv_bfloat16* __restrict__ wh, const __nv_bfloat16* __restrict__ wl,
    const float* __restrict__ bias,
    float* __restrict__ yf, __nv_bfloat16* __restrict__ yh, __nv_bfloat16* __restrict__ yl)
{
    extern __shared__ char dsm[];
    uint32_t smem0 = smem_u32(dsm);
    int tid = threadIdx.x;
    int wid = tid >> 5, lane = tid & 31;
    int wm = wid >> 1, wn = wid & 1;          // warp tile: rows wm*64, cols wn*64
    int m0 = blockIdx.x * 128;
    int n0 = blockIdx.y * 128;

    float c[4][8][4];
#pragma unroll
    for (int i = 0; i < 4; i++)
#pragma unroll
        for (int j = 0; j < 8; j++)
#pragma unroll
            for (int e = 0; e < 4; e++) c[i][j][e] = 0.f;

    // stage fill: 4 tiles (Ah, Al, Bh, Bl), each 128 rows x 64 bf16 (128B/row)
    auto fill = [&](int kt) {
        int stage = kt % 3;
        int kb = kt * 64;
        uint32_t sb = smem0 + stage * STAGE_BYTES;
#pragma unroll
        for (int j = 0; j < 32; j++) {
            int cidx = tid + 128 * j;
            int tile = cidx >> 10;
            int idx = cidx & 1023;
            int row = idx >> 3;
            int c16 = idx & 7;
            uint32_t dst = sb + tile * 16384 + row * 128 + ((c16 ^ (row & 7)) << 4);
            const __nv_bfloat16* src;
            if (tile == 0)      src = xh + (size_t)(m0 + row) * 512 + kb + c16 * 8;
            else if (tile == 1) src = xl + (size_t)(m0 + row) * 512 + kb + c16 * 8;
            else if (tile == 2) src = wh + (size_t)(n0 + row) * 512 + kb + c16 * 8;
            else                src = wl + (size_t)(n0 + row) * 512 + kb + c16 * 8;
            cpasync16(dst, (const void*)src);
        }
        CP_COMMIT();
    };

    fill(0);
    fill(1);

    int la = lane & 15, lh = lane >> 4;

    for (int i = 0; i < NKT; i++) {
        uint32_t sb = smem0 + (i % 3) * STAGE_BYTES;
        if (i < NKT - 1) { CP_WAIT1(); } else { CP_WAIT0(); }
        __syncthreads();
        if (i + 2 < NKT) fill(i + 2);

#pragma unroll
        for (int kc = 0; kc < 4; kc++) {
            int c16 = kc * 2 + lh;
            uint32_t ah[4][4], al[4][4];
#pragma unroll
            for (int mt = 0; mt < 4; mt++)
                ldmx4(ah[mt], tile_addr(sb,         wm * 64 + mt * 16 + la, c16));
#pragma unroll
            for (int mt = 0; mt < 4; mt++)
                ldmx4(al[mt], tile_addr(sb + 16384, wm * 64 + mt * 16 + la, c16));
            // B in two halves of 32 cols each to cap register peak
#pragma unroll
            for (int hb = 0; hb < 2; hb++) {
                uint32_t bhf[2][4], blf[2][4];
#pragma unroll
                for (int g = 0; g < 2; g++)
                    ldmx4(bhf[g], tile_addr(sb + 32768, wn * 64 + (hb * 2 + g) * 16 + la, c16));
#pragma unroll
                for (int g = 0; g < 2; g++)
                    ldmx4(blf[g], tile_addr(sb + 49152, wn * 64 + (hb * 2 + g) * 16 + la, c16));
#pragma unroll
                for (int mt = 0; mt < 4; mt++) {
#pragma unroll
                    for (int nt = 0; nt < 4; nt++) {
                        int g = nt >> 1, h = nt & 1;
                        float* cc = c[mt][hb * 4 + nt];
                        mma16816(cc, ah[mt], bhf[g][h], bhf[g][2 + h]);
                        mma16816(cc, al[mt], bhf[g][h], bhf[g][2 + h]);
                        mma16816(cc, ah[mt], blf[g][h], blf[g][2 + h]);
                    }
                }
            }
        }
    }

    // ---- epilogue straight from registers ----
    int r0 = lane >> 2;
    int cp = (lane & 3) * 2;
#pragma unroll
    for (int nt = 0; nt < 8; nt++) {
        int col = n0 + wn * 64 + nt * 8 + cp;
        float2 bv = *(const float2*)&bias[col];
#pragma unroll
        for (int mt = 0; mt < 4; mt++) {
#pragma unroll
            for (int half = 0; half < 2; half++) {
                int row = m0 + wm * 64 + mt * 16 + r0 + half * 8;
                float v0 = c[mt][nt][2 * half]     + bv.x;
                float v1 = c[mt][nt][2 * half + 1] + bv.y;
                if (RESACT) {
                    float2 xr = *(const float2*)&xres[(size_t)row * 512 + col];
                    v0 = xr.x + silu_f(v0);
                    v1 = xr.y + silu_f(v1);
                }
                if (WF32) {
                    *(float2*)&yf[(size_t)row * NOUT + col] = make_float2(v0, v1);
                }
                if (SPLIT) {
                    __nv_bfloat16 h0 = __float2bfloat16_rn(v0);
                    __nv_bfloat16 h1 = __float2bfloat16_rn(v1);
                    __nv_bfloat16 l0 = __float2bfloat16_rn(v0 - __bfloat162float(h0));
                    __nv_bfloat16 l1 = __float2bfloat16_rn(v1 - __bfloat162float(h1));
                    size_t base = (size_t)row * 512 + col;
                    __nv_bfloat162 hp; hp.x = h0; hp.y = h1;
                    __nv_bfloat162 lp; lp.x = l0; lp.y = l1;
                    *(__nv_bfloat162*)&yh[base] = hp;
                    *(__nv_bfloat162*)&yl[base] = lp;
                }
            }
        }
    }
}

// ---------------------------------------------------------------------------
extern "C" void kernel_launch(void* const* d_in, const int* in_sizes, int n_in,
                              void* d_out, int out_size)
{
    const int*   chars    = (const int*)d_in[0];
    const float* emb_byte = (const float*)d_in[1];
    const float* htab     = (const float*)d_in[2];
    const float* Wq       = (const float*)d_in[3];
    const float* bq       = (const float*)d_in[4];
    const float* conv_w   = (const float*)d_in[5];
    const float* conv_b   = (const float*)d_in[6];
    const float* Win      = (const float*)d_in[7];
    const float* b_in     = (const float*)d_in[8];
    const float* Wg       = (const float*)d_in[9];
    const float* bg       = (const float*)d_in[10];
    const float* Wi       = (const float*)d_in[11];
    const float* bi       = (const float*)d_in[12];
    const float* Wo       = (const float*)d_in[13];
    const float* bo       = (const float*)d_in[14];
    const float* lng      = (const float*)d_in[15];
    const float* lnb      = (const float*)d_in[16];
    const float* mlp_w    = (const float*)d_in[17];
    const float* mlp_b    = (const float*)d_in[18];
    const float* Wout     = (const float*)d_in[19];
    const float* bout     = (const float*)d_in[20];
    float* out = (float*)d_out;

    void *p;
    cudaGetSymbolAddress(&p, g_h);   float* gh  = (float*)p;
    cudaGetSymbolAddress(&p, g_h2);  float* gh2 = (float*)p;
    cudaGetSymbolAddress(&p, g_xh);  __nv_bfloat16* xh  = (__nv_bfloat16*)p;
    cudaGetSymbolAddress(&p, g_xl);  __nv_bfloat16* xl  = (__nv_bfloat16*)p;
    cudaGetSymbolAddress(&p, g_x2h); __nv_bfloat16* x2h = (__nv_bfloat16*)p;
    cudaGetSymbolAddress(&p, g_x2l); __nv_bfloat16* x2l = (__nv_bfloat16*)p;
    cudaGetSymbolAddress(&p, g_wbh); __nv_bfloat16* wbh = (__nv_bfloat16*)p;
    cudaGetSymbolAddress(&p, g_wbl); __nv_bfloat16* wbl = (__nv_bfloat16*)p;

    static int attr_done = 0;
    if (!attr_done) {
        cudaFuncSetAttribute(k_mma<512,1,1,1>, cudaFuncAttributeMaxDynamicSharedMemorySize, SMEM_MM);
        cudaFuncSetAttribute(k_mma<512,1,1,0>, cudaFuncAttributeMaxDynamicSharedMemorySize, SMEM_MM);
        cudaFuncSetAttribute(k_mma<256,0,0,1>, cudaFuncAttributeMaxDynamicSharedMemorySize, SMEM_MM);
        attr_done = 1;
    }

    // weight prep (bf16 split + transpose)
    k_prep_w<<<512 * 512 / 256, 256>>>(mlp_w,                 512, 0);
    k_prep_w<<<512 * 512 / 256, 256>>>(mlp_w + 512 * 512,     512, 1);
    k_prep_w<<<512 * 512 / 256, 256>>>(mlp_w + 2 * 512 * 512, 512, 2);
    k_prep_w<<<256 * 512 / 256, 256>>>(Wout,                  256, 3);

    k_hashfeat<<<BT / 8, 256>>>(chars, emb_byte, htab, Wq, bq);
    k_feat_win<<<BT / 32, 256>>>(chars, emb_byte, conv_w, conv_b, Win, b_in);
    k_gates<<<BT / 32, 256>>>(Wg, bg, Wi, bi);
    k_scan<<<BDIM * SSDIM, 256>>>();
    k_wo<<<BT / 32, 256>>>(Wo, bo);
    k_ln<<<BT, 128>>>(lng, lnb);

    dim3 g512(BT / 128, 4), g256(BT / 128, 2);
    // L1: in (xh,xl), resid g_h2 -> f32 g_h + split x2
    k_mma<512,1,1,1><<<g512, 128, SMEM_MM>>>(xh, xl, gh2,
        wbh + 0 * 512 * 512, wbl + 0 * 512 * 512, mlp_b, gh, x2h, x2l);
    // L2: in (x2h,x2l), resid g_h -> f32 g_h2 + split x
    k_mma<512,1,1,1><<<g512, 128, SMEM_MM>>>(x2h, x2l, gh,
        wbh + 1 * 512 * 512, wbl + 1 * 512 * 512, mlp_b + 512, gh2, xh, xl);
    // L3: in (xh,xl), resid g_h2 -> split x2 only
    k_mma<512,1,1,0><<<g512, 128, SMEM_MM>>>(xh, xl, gh2,
        wbh + 2 * 512 * 512, wbl + 2 * 512 * 512, mlp_b + 1024, 0, x2h, x2l);
    // Wout: in (x2h,x2l) -> out f32 [65536,256]
    k_mma<256,0,0,1><<<g256, 128, SMEM_MM>>>(x2h, x2l, 0,
        wbh + 3 * 512 * 512, wbl + 3 * 512 * 512, bout, out, 0, 0);
}

// round 9
// speedup vs baseline: 1.6845x; 1.2623x over previous
#include <cuda_runtime.h>
#include <cuda_bf16.h>
#include <math.h>
#include <stdint.h>

#define BDIM 8
#define TDIM 8192
#define BT (BDIM*TDIM)
#define HDIM 512
#define SSDIM 32

typedef unsigned long long u64;

// ---------------- scratch (device globals; no allocations allowed) ----------
__device__ float g_hf[BT*64];
__device__ float g_h[BT*HDIM];
__device__ float g_h2[BT*HDIM];
__device__ float g_gates[BDIM*SSDIM*TDIM];
__device__ float g_drive[BDIM*SSDIM*TDIM];
__device__ float g_states[BDIM*SSDIM*TDIM];
// bf16 split activations (ping/pong pairs)
__device__ __nv_bfloat16 g_xh[(size_t)BT*512];
__device__ __nv_bfloat16 g_xl[(size_t)BT*512];
__device__ __nv_bfloat16 g_x2h[(size_t)BT*512];
__device__ __nv_bfloat16 g_x2l[(size_t)BT*512];
// bf16 split transposed weights [layer][n*512+k]
__device__ __nv_bfloat16 g_wbh[4][512*512];
__device__ __nv_bfloat16 g_wbl[4][512*512];

__device__ __forceinline__ float silu_f(float x) { return x / (1.f + __expf(-x)); }

__device__ __forceinline__ u64 pack2(float x) {
    u64 r; asm("mov.b64 %0, {%1, %1};" : "=l"(r) : "f"(x)); return r;
}
__device__ __forceinline__ void ffma2(u64& d, u64 a, u64 b) {
    asm("fma.rn.f32x2 %0, %1, %2, %3;" : "=l"(d) : "l"(a), "l"(b), "l"(d));
}
__device__ __forceinline__ float lo32(u64 v) { return __uint_as_float((unsigned)v); }
__device__ __forceinline__ float hi32(u64 v) { return __uint_as_float((unsigned)(v >> 32)); }

// ---------------- mma.sync / async helpers (arch-agnostic, sm_80+) ----------
__device__ __forceinline__ uint32_t smem_u32(const void* p) {
    uint32_t a;
    asm("{ .reg .u64 t; cvta.to.shared.u64 t, %1; cvt.u32.u64 %0, t; }" : "=r"(a) : "l"(p));
    return a;
}
#define CP_COMMIT()      asm volatile("cp.async.commit_group;" ::: "memory")
#define CP_WAIT1()       asm volatile("cp.async.wait_group 1;" ::: "memory")
#define CP_WAIT0()       asm volatile("cp.async.wait_group 0;" ::: "memory")

__device__ __forceinline__ void cpasync16(uint32_t dst, const void* src) {
    asm volatile("cp.async.cg.shared.global [%0], [%1], 16;" :: "r"(dst), "l"(src));
}
__device__ __forceinline__ void ldmx4(uint32_t* r, uint32_t addr) {
    asm volatile("ldmatrix.sync.aligned.m8n8.x4.shared.b16 {%0,%1,%2,%3}, [%4];"
        : "=r"(r[0]), "=r"(r[1]), "=r"(r[2]), "=r"(r[3]) : "r"(addr));
}
__device__ __forceinline__ void mma16816(float* c, const uint32_t* a,
                                         uint32_t b0, uint32_t b1) {
    asm volatile("mma.sync.aligned.m16n8k16.row.col.f32.bf16.bf16.f32 "
        "{%0,%1,%2,%3}, {%4,%5,%6,%7}, {%8,%9}, {%0,%1,%2,%3};"
        : "+f"(c[0]), "+f"(c[1]), "+f"(c[2]), "+f"(c[3])
        : "r"(a[0]), "r"(a[1]), "r"(a[2]), "r"(a[3]), "r"(b0), "r"(b1));
}
// 16B-granular XOR swizzle within a 128B row (conflict-free ldmatrix)
__device__ __forceinline__ uint32_t tile_addr(uint32_t tbase, int row, int c16) {
    return tbase + row * 128 + ((c16 ^ (row & 7)) << 4);
}

// ---------------------------------------------------------------------------
// K1: rolling hashes + scale attention -> g_hf (verified)
// ---------------------------------------------------------------------------
__global__ void __launch_bounds__(256) k_hashfeat(
    const int* __restrict__ chars, const float* __restrict__ emb_byte,
    const float* __restrict__ htab, const float* __restrict__ Wq,
    const float* __restrict__ bq)
{
    int gw = (blockIdx.x * blockDim.x + threadIdx.x) >> 5;
    if (gw >= BT) return;
    int lane = threadIdx.x & 31;
    int wip  = threadIdx.x >> 5;
    int b = gw / TDIM, t = gw % TDIM;
    const int* cb = chars + b * TDIM;

    int myc = (lane < 16 && t >= lane) ? cb[t - lane] : 0;

    int acc0 = 0, acc1 = 0, acc2 = 0, acc3 = 0;
    int p = 1;
#pragma unroll
    for (int j = 0; j < 16; j++) {
        int cj = __shfl_sync(0xffffffffu, myc, j);
        int term = cj * p;
        if (j < 2) acc0 += term;
        if (j < 4) acc1 += term;
        if (j < 8) acc2 += term;
        acc3 += term;
        p = (p * 257) & 4095;
    }
    int h0 = acc0 & 4095, h1 = acc1 & 4095, h2 = acc2 & 4095, h3 = acc3 & 4095;

    int c0 = lane * 2;
    int ch0 = __shfl_sync(0xffffffffu, myc, 0);
    float2 be = *(const float2*)&emb_byte[ch0 * 64 + c0];

    __shared__ float s_be[8][64];
    s_be[wip][c0]     = be.x;
    s_be[wip][c0 + 1] = be.y;
    __syncwarp();

    float q0 = bq[c0], q1 = bq[c0 + 1];
#pragma unroll 8
    for (int k = 0; k < 64; k++) {
        float bk = s_be[wip][k];
        float2 wv = *(const float2*)&Wq[k * 64 + c0];
        q0 = fmaf(bk, wv.x, q0);
        q1 = fmaf(bk, wv.y, q1);
    }

    float2 se0 = *(const float2*)&htab[(size_t)(0 * 4096 + h0) * 64 + c0];
    float2 se1 = *(const float2*)&htab[(size_t)(1 * 4096 + h1) * 64 + c0];
    float2 se2 = *(const float2*)&htab[(size_t)(2 * 4096 + h2) * 64 + c0];
    float2 se3 = *(const float2*)&htab[(size_t)(3 * 4096 + h3) * 64 + c0];

    float s0 = q0 * se0.x + q1 * se0.y;
    float s1 = q0 * se1.x + q1 * se1.y;
    float s2 = q0 * se2.x + q1 * se2.y;
    float s3 = q0 * se3.x + q1 * se3.y;
#pragma unroll
    for (int off = 16; off; off >>= 1) {
        s0 += __shfl_xor_sync(0xffffffffu, s0, off);
        s1 += __shfl_xor_sync(0xffffffffu, s1, off);
        s2 += __shfl_xor_sync(0xffffffffu, s2, off);
        s3 += __shfl_xor_sync(0xffffffffu, s3, off);
    }
    s0 *= 0.125f; s1 *= 0.125f; s2 *= 0.125f; s3 *= 0.125f;
    float m = fmaxf(fmaxf(s0, s1), fmaxf(s2, s3));
    float e0 = __expf(s0 - m), e1 = __expf(s1 - m), e2 = __expf(s2 - m), e3 = __expf(s3 - m);
    float inv = 1.f / (e0 + e1 + e2 + e3);
    float o0 = (e0 * se0.x + e1 * se1.x + e2 * se2.x + e3 * se3.x) * inv;
    float o1 = (e0 * se0.y + e1 * se1.y + e2 * se2.y + e3 * se3.y) * inv;
    *(float2*)&g_hf[(size_t)gw * 64 + c0] = make_float2(o0, o1);
}

// ---------------------------------------------------------------------------
// K2: features + Win GEMM (verified)
// ---------------------------------------------------------------------------
__global__ void __launch_bounds__(256) k_feat_win(
    const int* __restrict__ chars, const float* __restrict__ emb_byte,
    const float* __restrict__ conv_w, const float* __restrict__ conv_b,
    const float* __restrict__ Win, const float* __restrict__ b_in)
{
    __shared__ float sxt[132][32];
    __shared__ int sch[32];
    int blk = blockIdx.x;
    int b = blk / (TDIM / 32);
    int tBase = (blk % (TDIM / 32)) * 32;
    int tid = threadIdx.x;
    const int* cb = chars + b * TDIM;

    if (tid < 32) sch[tid] = cb[tBase + tid];
    __syncthreads();

    for (int idx = tid; idx < 32 * 64; idx += 256) {
        int tok = idx >> 6, c = idx & 63;
        sxt[c][tok] = emb_byte[sch[tok] * 64 + c];
    }
    for (int idx = tid; idx < 32 * 64; idx += 256) {
        int tok = idx >> 6, c = idx & 63;
        int t = tBase + tok;
        float acc = conv_b[c];
#pragma unroll
        for (int k = 0; k < 4; k++) {
            int tt = t - 3 + k;
            float v = (tt >= 0) ? g_hf[(size_t)(b * TDIM + tt) * 64 + c] : 0.f;
            acc = fmaf(conv_w[c * 4 + k], v, acc);
        }
        sxt[64 + c][tok] = silu_f(acc);
    }
    for (int idx = tid; idx < 128; idx += 256) {
        int tok = idx >> 2, mm = idx & 3;
        int k = 1 << mm;
        int t = tBase + tok;
        float v = 0.f;
        if (t >= k) v = (cb[t] == cb[t - k]) ? 1.f : 0.f;
        sxt[128 + mm][tok] = v;
    }
    __syncthreads();

    u64 acc[16][2];
#pragma unroll
    for (int i = 0; i < 16; i++) { acc[i][0] = 0ull; acc[i][1] = 0ull; }

#pragma unroll 1
    for (int k4 = 0; k4 < 132; k4 += 4) {
        u64 wp[4][2];
#pragma unroll
        for (int j = 0; j < 4; j++) {
            wp[j][0] = pack2(Win[(size_t)(k4 + j) * 512 + tid]);
            wp[j][1] = pack2(Win[(size_t)(k4 + j) * 512 + tid + 256]);
        }
#pragma unroll
        for (int j = 0; j < 4; j++) {
            const ulonglong2* xr = (const ulonglong2*)&sxt[k4 + j][0];
#pragma unroll
            for (int q = 0; q < 8; q++) {
                ulonglong2 x2 = xr[q];
                ffma2(acc[2 * q][0],     x2.x, wp[j][0]);
                ffma2(acc[2 * q][1],     x2.x, wp[j][1]);
                ffma2(acc[2 * q + 1][0], x2.y, wp[j][0]);
                ffma2(acc[2 * q + 1][1], x2.y, wp[j][1]);
            }
        }
    }
#pragma unroll
    for (int cc = 0; cc < 2; cc++) {
        int col = tid + cc * 256;
        float bv = b_in[col];
#pragma unroll
        for (int p = 0; p < 16; p++) {
            size_t r0 = (size_t)(b * TDIM + tBase + 2 * p) * 512 + col;
            g_h[r0]       = silu_f(lo32(acc[p][cc]) + bv);
            g_h[r0 + 512] = silu_f(hi32(acc[p][cc]) + bv);
        }
    }
}

// ---------------------------------------------------------------------------
// K3: gates/drive (verified)
// ---------------------------------------------------------------------------
__global__ void __launch_bounds__(256) k_gates(
    const float* __restrict__ Wg, const float* __restrict__ bg,
    const float* __restrict__ Wi, const float* __restrict__ bi)
{
    __shared__ u64 smbuf[4096];
    float (*sxt)[32] = reinterpret_cast<float(*)[32]>(smbuf);

    int tid = threadIdx.x;
    int col = tid & 63;
    int ks  = tid >> 6;
    int n0 = blockIdx.x * 32;
    int b = n0 / TDIM, t0 = n0 % TDIM;

    u64 acc[16];
#pragma unroll
    for (int i = 0; i < 16; i++) acc[i] = 0ull;

    const float* Wsel = (col < 32) ? Wg : Wi;
    int wcol = col & 31;

    for (int kb = 0; kb < 512; kb += 128) {
        __syncthreads();
        for (int i = tid; i < 32 * 32; i += 256) {
            int tok = i & 31;
            int k4 = (i >> 5) << 2;
            float4 v = *(const float4*)&g_h[(size_t)(n0 + tok) * 512 + kb + k4];
            sxt[k4][tok] = v.x; sxt[k4 + 1][tok] = v.y;
            sxt[k4 + 2][tok] = v.z; sxt[k4 + 3][tok] = v.w;
        }
        __syncthreads();
        int kBase = ks * 32;
#pragma unroll 1
        for (int k = 0; k < 32; k++) {
            u64 wv = pack2(Wsel[(size_t)(kb + kBase + k) * 32 + wcol]);
            const ulonglong2* xr = (const ulonglong2*)&sxt[kBase + k][0];
#pragma unroll
            for (int q = 0; q < 8; q++) {
                ulonglong2 x2 = xr[q];
                ffma2(acc[2 * q],     x2.x, wv);
                ffma2(acc[2 * q + 1], x2.y, wv);
            }
        }
    }
    __syncthreads();
#pragma unroll
    for (int p = 0; p < 16; p++) smbuf[((size_t)ks * 64 + col) * 16 + p] = acc[p];
    __syncthreads();
    if (ks == 0 && col < 32) {
        int j = col;
        float bgv = bg[j], biv = bi[j];
        float* gout = g_gates + (size_t)(b * SSDIM + j) * TDIM + t0;
        float* dout = g_drive + (size_t)(b * SSDIM + j) * TDIM + t0;
#pragma unroll
        for (int p = 0; p < 16; p++) {
            float ag0 = bgv, ag1 = bgv, ai0 = biv, ai1 = biv;
#pragma unroll
            for (int s = 0; s < 4; s++) {
                u64 vg = smbuf[((size_t)s * 64 + j) * 16 + p];
                u64 vi = smbuf[((size_t)s * 64 + 32 + j) * 16 + p];
                ag0 += lo32(vg); ag1 += hi32(vg);
                ai0 += lo32(vi); ai1 += hi32(vi);
            }
            float g0 = 1.f / (1.f + __expf(-ag0));
            float g1 = 1.f / (1.f + __expf(-ag1));
            gout[2 * p]     = g0;
            gout[2 * p + 1] = g1;
            dout[2 * p]     = (1.f - g0) * ai0;
            dout[2 * p + 1] = (1.f - g1) * ai1;
        }
    }
}

// ---------------------------------------------------------------------------
// K4: chunk-parallel TinyScan (verified)
// ---------------------------------------------------------------------------
__global__ void __launch_bounds__(256) k_scan()
{
    int bs = blockIdx.x;
    int j = threadIdx.x;
    const float* ga = g_gates + (size_t)bs * TDIM + j * 32;
    const float* dr = g_drive + (size_t)bs * TDIM + j * 32;
    float a[32], bb[32];
#pragma unroll
    for (int i = 0; i < 32; i++) {
        a[i]  = fmaxf(ga[i], 1e-6f);
        bb[i] = dr[i];
    }
    float cumA = 1.f, cumWB = 0.f;
#pragma unroll
    for (int i = 0; i < 32; i++) {
        cumA *= a[i];
        float inv = 1.f / fmaxf(cumA, 1e-8f);
        cumWB = fmaf(bb[i], inv, cumWB);
    }
    __shared__ float sA[256], sB[256];
    sA[j] = cumA;
    sB[j] = cumA * cumWB;
    __syncthreads();
    for (int d = 1; d < 256; d <<= 1) {
        float a2 = sA[j], b2 = sB[j], a1 = 0.f, b1 = 0.f;
        if (j >= d) { a1 = sA[j - d]; b1 = sB[j - d]; }
        __syncthreads();
        if (j >= d) { sA[j] = a2 * a1; sB[j] = fmaf(a2, b1, b2); }
        __syncthreads();
    }
    float hc = (j == 0) ? 0.f : sB[j - 1];
    cumA = 1.f; cumWB = 0.f;
    float* st = g_states + (size_t)bs * TDIM + j * 32;
#pragma unroll
    for (int i = 0; i < 32; i++) {
        cumA *= a[i];
        float inv = 1.f / fmaxf(cumA, 1e-8f);
        cumWB = fmaf(bb[i], inv, cumWB);
        st[i] = cumA * (hc + cumWB);
    }
}

// ---------------------------------------------------------------------------
// K5a: y = h + states@Wo + bo (verified)
// ---------------------------------------------------------------------------
__global__ void __launch_bounds__(256) k_wo(
    const float* __restrict__ Wo, const float* __restrict__ bo)
{
    __shared__ float sxt[32][32];
    int tid = threadIdx.x;
    int n0 = blockIdx.x * 32;
    int b = n0 / TDIM, t0 = n0 % TDIM;

    for (int i = tid; i < 32 * 8; i += 256) {
        int s = i >> 3, t4 = (i & 7) * 4;
        float4 v = *(const float4*)&g_states[(size_t)(b * SSDIM + s) * TDIM + t0 + t4];
        *(float4*)&sxt[s][t4] = v;
    }
    __syncthreads();

    u64 acc[16][2];
#pragma unroll
    for (int i = 0; i < 16; i++) { acc[i][0] = 0ull; acc[i][1] = 0ull; }

#pragma unroll 1
    for (int k4 = 0; k4 < 32; k4 += 4) {
        u64 wp[4][2];
#pragma unroll
        for (int j = 0; j < 4; j++) {
            wp[j][0] = pack2(Wo[(size_t)(k4 + j) * 512 + tid]);
            wp[j][1] = pack2(Wo[(size_t)(k4 + j) * 512 + tid + 256]);
        }
#pragma unroll
        for (int j = 0; j < 4; j++) {
            const ulonglong2* xr = (const ulonglong2*)&sxt[k4 + j][0];
#pragma unroll
            for (int q = 0; q < 8; q++) {
                ulonglong2 x2 = xr[q];
                ffma2(acc[2 * q][0],     x2.x, wp[j][0]);
                ffma2(acc[2 * q][1],     x2.x, wp[j][1]);
                ffma2(acc[2 * q + 1][0], x2.y, wp[j][0]);
                ffma2(acc[2 * q + 1][1], x2.y, wp[j][1]);
            }
        }
    }
#pragma unroll
    for (int cc = 0; cc < 2; cc++) {
        int col = tid + cc * 256;
        float bv = bo[col];
#pragma unroll
        for (int p = 0; p < 16; p++) {
            size_t r0 = (size_t)(n0 + 2 * p) * 512 + col;
            g_h2[r0]       = lo32(acc[p][cc]) + bv + g_h[r0];
            g_h2[r0 + 512] = hi32(acc[p][cc]) + bv + g_h[r0 + 512];
        }
    }
}

// ---------------------------------------------------------------------------
// K5b: LayerNorm + bf16 hi/lo split write for the tensor path
// ---------------------------------------------------------------------------
__global__ void __launch_bounds__(128) k_ln(
    const float* __restrict__ lng, const float* __restrict__ lnb)
{
    int n = blockIdx.x;
    int tid = threadIdx.x;
    int c = tid * 4;
    float4 y = *(const float4*)&g_h2[(size_t)n * 512 + c];
    float lsum = y.x + y.y + y.z + y.w;
    float lsq  = y.x * y.x + y.y * y.y + y.z * y.z + y.w * y.w;
#pragma unroll
    for (int off = 16; off; off >>= 1) {
        lsum += __shfl_xor_sync(0xffffffffu, lsum, off);
        lsq  += __shfl_xor_sync(0xffffffffu, lsq,  off);
    }
    __shared__ float red[4][2];
    int wip = tid >> 5, lane = tid & 31;
    if (lane == 0) { red[wip][0] = lsum; red[wip][1] = lsq; }
    __syncthreads();
    lsum = red[0][0] + red[1][0] + red[2][0] + red[3][0];
    lsq  = red[0][1] + red[1][1] + red[2][1] + red[3][1];
    float mu = lsum * (1.f / 512.f);
    float var = lsq * (1.f / 512.f) - mu * mu;
    float rstd = rsqrtf(var + 1e-5f);
    float4 g4 = *(const float4*)&lng[c];
    float4 b4 = *(const float4*)&lnb[c];
    float4 o;
    o.x = (y.x - mu) * rstd * g4.x + b4.x;
    o.y = (y.y - mu) * rstd * g4.y + b4.y;
    o.z = (y.z - mu) * rstd * g4.z + b4.z;
    o.w = (y.w - mu) * rstd * g4.w + b4.w;
    *(float4*)&g_h2[(size_t)n * 512 + c] = o;
    float vs[4] = {o.x, o.y, o.z, o.w};
    __nv_bfloat16 bh[4], bl[4];
#pragma unroll
    for (int e = 0; e < 4; e++) {
        bh[e] = __float2bfloat16_rn(vs[e]);
        bl[e] = __float2bfloat16_rn(vs[e] - __bfloat162float(bh[e]));
    }
    size_t base = (size_t)n * 512 + c;
    *(__nv_bfloat162*)&g_xh[base]     = *(__nv_bfloat162*)&bh[0];
    *(__nv_bfloat162*)&g_xh[base + 2] = *(__nv_bfloat162*)&bh[2];
    *(__nv_bfloat162*)&g_xl[base]     = *(__nv_bfloat162*)&bl[0];
    *(__nv_bfloat162*)&g_xl[base + 2] = *(__nv_bfloat162*)&bl[2];
}

// ---------------------------------------------------------------------------
// Weight prep: split W[k][N] f32 into transposed bf16 hi/lo [n*512+k]
// ---------------------------------------------------------------------------
__global__ void __launch_bounds__(256) k_prep_w(
    const float* __restrict__ W, int N, int layer)
{
    int idx = blockIdx.x * 256 + threadIdx.x;
    int k = idx & 511;
    int n = idx >> 9;
    if (n >= N) return;
    float w = W[(size_t)k * N + n];
    __nv_bfloat16 h = __float2bfloat16_rn(w);
    __nv_bfloat16 l = __float2bfloat16_rn(w - __bfloat162float(h));
    g_wbh[layer][(size_t)n * 512 + k] = h;
    g_wbl[layer][(size_t)n * 512 + k] = l;
}

// ---------------------------------------------------------------------------
// Split-bf16 mma.sync GEMM: D = Xh@Wh' + Xl@Wh' + Xh@Wl'  (fp32 accum)
// CTA: 256x128xK512, 8 warps in 4x2 grid, warp tile 64x64 ->
// 96 MMAs per 16 ldmx4 per kc (2:1 better reuse) at full 8-warp occupancy.
// 2-stage cp.async double buffer, KT=64 (96KB/stage, 192KB total).
// ---------------------------------------------------------------------------
#define NKT 8
#define STAGE_BYTES 98304
#define SMEM_MM (2 * STAGE_BYTES)
// stage layout: Ah @0 (32KB, 256x128B), Al @32768, Bh @65536 (16KB), Bl @81920

template<int NOUT, int RESACT, int SPLIT, int WF32>
__global__ void __launch_bounds__(256) k_mma(
    const __nv_bfloat16* __restrict__ xh, const __nv_bfloat16* __restrict__ xl,
    const float* __restrict__ xres,
    const __nv_bfloat16* __restrict__ wh, const __nv_bfloat16* __restrict__ wl,
    const float* __restrict__ bias,
    float* __restrict__ yf, __nv_bfloat16* __restrict__ yh, __nv_bfloat16* __restrict__ yl)
{
    extern __shared__ char dsm[];
    uint32_t smem0 = smem_u32(dsm);
    int tid = threadIdx.x;
    int wid = tid >> 5, lane = tid & 31;
    int wm = wid >> 1, wn = wid & 1;          // warp tile: rows wm*64, cols wn*64
    int m0 = blockIdx.x * 256;
    int n0 = blockIdx.y * 128;

    float c[4][8][4];
#pragma unroll
    for (int i = 0; i < 4; i++)
#pragma unroll
        for (int j = 0; j < 8; j++)
#pragma unroll
            for (int e = 0; e < 4; e++) c[i][j][e] = 0.f;

    // stage fill: Ah/Al 256 rows, Bh/Bl 128 rows; 6144 16B-chunks, 24/thread
    auto fill = [&](int kt) {
        int stage = kt & 1;
        int kb = kt * 64;
        uint32_t sb = smem0 + stage * STAGE_BYTES;
#pragma unroll
        for (int j = 0; j < 24; j++) {
            int cidx = tid + 256 * j;
            const __nv_bfloat16* src;
            uint32_t toff;
            int idx;
            if (cidx < 2048)      { idx = cidx;        toff = 0;     src = xh + (size_t)(m0 + (idx >> 3)) * 512; }
            else if (cidx < 4096) { idx = cidx - 2048; toff = 32768; src = xl + (size_t)(m0 + (idx >> 3)) * 512; }
            else if (cidx < 5120) { idx = cidx - 4096; toff = 65536; src = wh + (size_t)(n0 + (idx >> 3)) * 512; }
            else                  { idx = cidx - 5120; toff = 81920; src = wl + (size_t)(n0 + (idx >> 3)) * 512; }
            int row = idx >> 3;
            int c16 = idx & 7;
            uint32_t dst = sb + toff + row * 128 + ((c16 ^ (row & 7)) << 4);
            cpasync16(dst, (const void*)(src + kb + c16 * 8));
        }
        CP_COMMIT();
    };

    fill(0);

    int la = lane & 15, lh = lane >> 4;

    for (int i = 0; i < NKT; i++) {
        uint32_t sb = smem0 + (i & 1) * STAGE_BYTES;
        if (i + 1 < NKT) { fill(i + 1); CP_WAIT1(); } else { CP_WAIT0(); }
        __syncthreads();

#pragma unroll
        for (int kc = 0; kc < 4; kc++) {
            int c16 = kc * 2 + lh;
            uint32_t ah[4][4], al[4][4];
#pragma unroll
            for (int mt = 0; mt < 4; mt++)
                ldmx4(ah[mt], tile_addr(sb,         wm * 64 + mt * 16 + la, c16));
#pragma unroll
            for (int mt = 0; mt < 4; mt++)
                ldmx4(al[mt], tile_addr(sb + 32768, wm * 64 + mt * 16 + la, c16));
            // B in two halves of 32 cols each to cap register peak
#pragma unroll
            for (int hb = 0; hb < 2; hb++) {
                uint32_t bhf[2][4], blf[2][4];
#pragma unroll
                for (int g = 0; g < 2; g++)
                    ldmx4(bhf[g], tile_addr(sb + 65536, wn * 64 + (hb * 2 + g) * 16 + la, c16));
#pragma unroll
                for (int g = 0; g < 2; g++)
                    ldmx4(blf[g], tile_addr(sb + 81920, wn * 64 + (hb * 2 + g) * 16 + la, c16));
#pragma unroll
                for (int mt = 0; mt < 4; mt++) {
#pragma unroll
                    for (int nt = 0; nt < 4; nt++) {
                        int g = nt >> 1, h = nt & 1;
                        float* cc = c[mt][hb * 4 + nt];
                        mma16816(cc, ah[mt], bhf[g][h], bhf[g][2 + h]);
                        mma16816(cc, al[mt], bhf[g][h], bhf[g][2 + h]);
                        mma16816(cc, ah[mt], blf[g][h], blf[g][2 + h]);
                    }
                }
            }
        }
        __syncthreads();   // all reads of this stage done before next fill overwrites
    }

    // ---- epilogue straight from registers ----
    int r0 = lane >> 2;
    int cp = (lane & 3) * 2;
#pragma unroll
    for (int nt = 0; nt < 8; nt++) {
        int col = n0 + wn * 64 + nt * 8 + cp;
        float2 bv = *(const float2*)&bias[col];
#pragma unroll
        for (int mt = 0; mt < 4; mt++) {
#pragma unroll
            for (int half = 0; half < 2; half++) {
                int row = m0 + wm * 64 + mt * 16 + r0 + half * 8;
                float v0 = c[mt][nt][2 * half]     + bv.x;
                float v1 = c[mt][nt][2 * half + 1] + bv.y;
                if (RESACT) {
                    float2 xr = *(const float2*)&xres[(size_t)row * 512 + col];
                    v0 = xr.x + silu_f(v0);
                    v1 = xr.y + silu_f(v1);
                }
                if (WF32) {
                    *(float2*)&yf[(size_t)row * NOUT + col] = make_float2(v0, v1);
                }
                if (SPLIT) {
                    __nv_bfloat16 h0 = __float2bfloat16_rn(v0);
                    __nv_bfloat16 h1 = __float2bfloat16_rn(v1);
                    __nv_bfloat16 l0 = __float2bfloat16_rn(v0 - __bfloat162float(h0));
                    __nv_bfloat16 l1 = __float2bfloat16_rn(v1 - __bfloat162float(h1));
                    size_t base = (size_t)row * 512 + col;
                    __nv_bfloat162 hp; hp.x = h0; hp.y = h1;
                    __nv_bfloat162 lp; lp.x = l0; lp.y = l1;
                    *(__nv_bfloat162*)&yh[base] = hp;
                    *(__nv_bfloat162*)&yl[base] = lp;
                }
            }
        }
    }
}

// ---------------------------------------------------------------------------
extern "C" void kernel_launch(void* const* d_in, const int* in_sizes, int n_in,
                              void* d_out, int out_size)
{
    const int*   chars    = (const int*)d_in[0];
    const float* emb_byte = (const float*)d_in[1];
    const float* htab     = (const float*)d_in[2];
    const float* Wq       = (const float*)d_in[3];
    const float* bq       = (const float*)d_in[4];
    const float* conv_w   = (const float*)d_in[5];
    const float* conv_b   = (const float*)d_in[6];
    const float* Win      = (const float*)d_in[7];
    const float* b_in     = (const float*)d_in[8];
    const float* Wg       = (const float*)d_in[9];
    const float* bg       = (const float*)d_in[10];
    const float* Wi       = (const float*)d_in[11];
    const float* bi       = (const float*)d_in[12];
    const float* Wo       = (const float*)d_in[13];
    const float* bo       = (const float*)d_in[14];
    const float* lng      = (const float*)d_in[15];
    const float* lnb      = (const float*)d_in[16];
    const float* mlp_w    = (const float*)d_in[17];
    const float* mlp_b    = (const float*)d_in[18];
    const float* Wout     = (const float*)d_in[19];
    const float* bout     = (const float*)d_in[20];
    float* out = (float*)d_out;

    void *p;
    cudaGetSymbolAddress(&p, g_h);   float* gh  = (float*)p;
    cudaGetSymbolAddress(&p, g_h2);  float* gh2 = (float*)p;
    cudaGetSymbolAddress(&p, g_xh);  __nv_bfloat16* xh  = (__nv_bfloat16*)p;
    cudaGetSymbolAddress(&p, g_xl);  __nv_bfloat16* xl  = (__nv_bfloat16*)p;
    cudaGetSymbolAddress(&p, g_x2h); __nv_bfloat16* x2h = (__nv_bfloat16*)p;
    cudaGetSymbolAddress(&p, g_x2l); __nv_bfloat16* x2l = (__nv_bfloat16*)p;
    cudaGetSymbolAddress(&p, g_wbh); __nv_bfloat16* wbh = (__nv_bfloat16*)p;
    cudaGetSymbolAddress(&p, g_wbl); __nv_bfloat16* wbl = (__nv_bfloat16*)p;

    static int attr_done = 0;
    if (!attr_done) {
        cudaFuncSetAttribute(k_mma<512,1,1,1>, cudaFuncAttributeMaxDynamicSharedMemorySize, SMEM_MM);
        cudaFuncSetAttribute(k_mma<512,1,1,0>, cudaFuncAttributeMaxDynamicSharedMemorySize, SMEM_MM);
        cudaFuncSetAttribute(k_mma<256,0,0,1>, cudaFuncAttributeMaxDynamicSharedMemorySize, SMEM_MM);
        attr_done = 1;
    }

    // weight prep (bf16 split + transpose)
    k_prep_w<<<512 * 512 / 256, 256>>>(mlp_w,                 512, 0);
    k_prep_w<<<512 * 512 / 256, 256>>>(mlp_w + 512 * 512,     512, 1);
    k_prep_w<<<512 * 512 / 256, 256>>>(mlp_w + 2 * 512 * 512, 512, 2);
    k_prep_w<<<256 * 512 / 256, 256>>>(Wout,                  256, 3);

    k_hashfeat<<<BT / 8, 256>>>(chars, emb_byte, htab, Wq, bq);
    k_feat_win<<<BT / 32, 256>>>(chars, emb_byte, conv_w, conv_b, Win, b_in);
    k_gates<<<BT / 32, 256>>>(Wg, bg, Wi, bi);
    k_scan<<<BDIM * SSDIM, 256>>>();
    k_wo<<<BT / 32, 256>>>(Wo, bo);
    k_ln<<<BT, 128>>>(lng, lnb);

    dim3 g512(BT / 256, 4), g256(BT / 256, 2);
    // L1: in (xh,xl), resid g_h2 -> f32 g_h + split x2
    k_mma<512,1,1,1><<<g512, 256, SMEM_MM>>>(xh, xl, gh2,
        wbh + 0 * 512 * 512, wbl + 0 * 512 * 512, mlp_b, gh, x2h, x2l);
    // L2: in (x2h,x2l), resid g_h -> f32 g_h2 + split x
    k_mma<512,1,1,1><<<g512, 256, SMEM_MM>>>(x2h, x2l, gh,
        wbh + 1 * 512 * 512, wbl + 1 * 512 * 512, mlp_b + 512, gh2, xh, xl);
    // L3: in (xh,xl), resid g_h2 -> split x2 only
    k_mma<512,1,1,0><<<g512, 256, SMEM_MM>>>(xh, xl, gh2,
        wbh + 2 * 512 * 512, wbl + 2 * 512 * 512, mlp_b + 1024, 0, x2h, x2l);
    // Wout: in (x2h,x2l) -> out f32 [65536,256]
    k_mma<256,0,0,1><<<g256, 256, SMEM_MM>>>(x2h, x2l, 0,
        wbh + 3 * 512 * 512, wbl + 3 * 512 * 512, bout, out, 0, 0);
}

// round 10
// speedup vs baseline: 1.8718x; 1.1112x over previous
#include <cuda_runtime.h>
#include <cuda_fp16.h>
#include <math.h>
#include <stdint.h>

#define BDIM 8
#define TDIM 8192
#define BT (BDIM*TDIM)
#define HDIM 512
#define SSDIM 32

typedef unsigned long long u64;

// ---------------- scratch (device globals; no allocations allowed) ----------
__device__ float g_hf[BT*64];
__device__ float g_h[BT*HDIM];
__device__ float g_h2[BT*HDIM];
__device__ float g_gates[BDIM*SSDIM*TDIM];
__device__ float g_drive[BDIM*SSDIM*TDIM];
__device__ float g_states[BDIM*SSDIM*TDIM];
// fp16 split activations (ping/pong pairs)
__device__ __half g_xh[(size_t)BT*512];
__device__ __half g_xl[(size_t)BT*512];
__device__ __half g_x2h[(size_t)BT*512];
__device__ __half g_x2l[(size_t)BT*512];
// fp16 transposed weights [layer][n*512+k]
__device__ __half g_wh[4][512*512];

__device__ __forceinline__ float silu_f(float x) { return x / (1.f + __expf(-x)); }

__device__ __forceinline__ u64 pack2(float x) {
    u64 r; asm("mov.b64 %0, {%1, %1};" : "=l"(r) : "f"(x)); return r;
}
__device__ __forceinline__ void ffma2(u64& d, u64 a, u64 b) {
    asm("fma.rn.f32x2 %0, %1, %2, %3;" : "=l"(d) : "l"(a), "l"(b), "l"(d));
}
__device__ __forceinline__ float lo32(u64 v) { return __uint_as_float((unsigned)v); }
__device__ __forceinline__ float hi32(u64 v) { return __uint_as_float((unsigned)(v >> 32)); }

// ---------------- mma.sync / async helpers (arch-agnostic, sm_80+) ----------
__device__ __forceinline__ uint32_t smem_u32(const void* p) {
    uint32_t a;
    asm("{ .reg .u64 t; cvta.to.shared.u64 t, %1; cvt.u32.u64 %0, t; }" : "=r"(a) : "l"(p));
    return a;
}
#define CP_COMMIT()      asm volatile("cp.async.commit_group;" ::: "memory")
#define CP_WAIT1()       asm volatile("cp.async.wait_group 1;" ::: "memory")
#define CP_WAIT0()       asm volatile("cp.async.wait_group 0;" ::: "memory")

__device__ __forceinline__ void cpasync16(uint32_t dst, const void* src) {
    asm volatile("cp.async.cg.shared.global [%0], [%1], 16;" :: "r"(dst), "l"(src));
}
__device__ __forceinline__ void ldmx4(uint32_t* r, uint32_t addr) {
    asm volatile("ldmatrix.sync.aligned.m8n8.x4.shared.b16 {%0,%1,%2,%3}, [%4];"
        : "=r"(r[0]), "=r"(r[1]), "=r"(r[2]), "=r"(r[3]) : "r"(addr));
}
__device__ __forceinline__ void mma16816(float* c, const uint32_t* a,
                                         uint32_t b0, uint32_t b1) {
    asm volatile("mma.sync.aligned.m16n8k16.row.col.f32.f16.f16.f32 "
        "{%0,%1,%2,%3}, {%4,%5,%6,%7}, {%8,%9}, {%0,%1,%2,%3};"
        : "+f"(c[0]), "+f"(c[1]), "+f"(c[2]), "+f"(c[3])
        : "r"(a[0]), "r"(a[1]), "r"(a[2]), "r"(a[3]), "r"(b0), "r"(b1));
}
// 16B-granular XOR swizzle within a 128B row (conflict-free ldmatrix)
__device__ __forceinline__ uint32_t tile_addr(uint32_t tbase, int row, int c16) {
    return tbase + row * 128 + ((c16 ^ (row & 7)) << 4);
}

// ---------------------------------------------------------------------------
// K1: rolling hashes + scale attention -> g_hf (verified)
// ---------------------------------------------------------------------------
__global__ void __launch_bounds__(256) k_hashfeat(
    const int* __restrict__ chars, const float* __restrict__ emb_byte,
    const float* __restrict__ htab, const float* __restrict__ Wq,
    const float* __restrict__ bq)
{
    int gw = (blockIdx.x * blockDim.x + threadIdx.x) >> 5;
    if (gw >= BT) return;
    int lane = threadIdx.x & 31;
    int wip  = threadIdx.x >> 5;
    int b = gw / TDIM, t = gw % TDIM;
    const int* cb = chars + b * TDIM;

    int myc = (lane < 16 && t >= lane) ? cb[t - lane] : 0;

    int acc0 = 0, acc1 = 0, acc2 = 0, acc3 = 0;
    int p = 1;
#pragma unroll
    for (int j = 0; j < 16; j++) {
        int cj = __shfl_sync(0xffffffffu, myc, j);
        int term = cj * p;
        if (j < 2) acc0 += term;
        if (j < 4) acc1 += term;
        if (j < 8) acc2 += term;
        acc3 += term;
        p = (p * 257) & 4095;
    }
    int h0 = acc0 & 4095, h1 = acc1 & 4095, h2 = acc2 & 4095, h3 = acc3 & 4095;

    int c0 = lane * 2;
    int ch0 = __shfl_sync(0xffffffffu, myc, 0);
    float2 be = *(const float2*)&emb_byte[ch0 * 64 + c0];

    __shared__ float s_be[8][64];
    s_be[wip][c0]     = be.x;
    s_be[wip][c0 + 1] = be.y;
    __syncwarp();

    float q0 = bq[c0], q1 = bq[c0 + 1];
#pragma unroll 8
    for (int k = 0; k < 64; k++) {
        float bk = s_be[wip][k];
        float2 wv = *(const float2*)&Wq[k * 64 + c0];
        q0 = fmaf(bk, wv.x, q0);
        q1 = fmaf(bk, wv.y, q1);
    }

    float2 se0 = *(const float2*)&htab[(size_t)(0 * 4096 + h0) * 64 + c0];
    float2 se1 = *(const float2*)&htab[(size_t)(1 * 4096 + h1) * 64 + c0];
    float2 se2 = *(const float2*)&htab[(size_t)(2 * 4096 + h2) * 64 + c0];
    float2 se3 = *(const float2*)&htab[(size_t)(3 * 4096 + h3) * 64 + c0];

    float s0 = q0 * se0.x + q1 * se0.y;
    float s1 = q0 * se1.x + q1 * se1.y;
    float s2 = q0 * se2.x + q1 * se2.y;
    float s3 = q0 * se3.x + q1 * se3.y;
#pragma unroll
    for (int off = 16; off; off >>= 1) {
        s0 += __shfl_xor_sync(0xffffffffu, s0, off);
        s1 += __shfl_xor_sync(0xffffffffu, s1, off);
        s2 += __shfl_xor_sync(0xffffffffu, s2, off);
        s3 += __shfl_xor_sync(0xffffffffu, s3, off);
    }
    s0 *= 0.125f; s1 *= 0.125f; s2 *= 0.125f; s3 *= 0.125f;
    float m = fmaxf(fmaxf(s0, s1), fmaxf(s2, s3));
    float e0 = __expf(s0 - m), e1 = __expf(s1 - m), e2 = __expf(s2 - m), e3 = __expf(s3 - m);
    float inv = 1.f / (e0 + e1 + e2 + e3);
    float o0 = (e0 * se0.x + e1 * se1.x + e2 * se2.x + e3 * se3.x) * inv;
    float o1 = (e0 * se0.y + e1 * se1.y + e2 * se2.y + e3 * se3.y) * inv;
    *(float2*)&g_hf[(size_t)gw * 64 + c0] = make_float2(o0, o1);
}

// ---------------------------------------------------------------------------
// K2: features + Win GEMM (verified)
// ---------------------------------------------------------------------------
__global__ void __launch_bounds__(256) k_feat_win(
    const int* __restrict__ chars, const float* __restrict__ emb_byte,
    const float* __restrict__ conv_w, const float* __restrict__ conv_b,
    const float* __restrict__ Win, const float* __restrict__ b_in)
{
    __shared__ float sxt[132][32];
    __shared__ int sch[32];
    int blk = blockIdx.x;
    int b = blk / (TDIM / 32);
    int tBase = (blk % (TDIM / 32)) * 32;
    int tid = threadIdx.x;
    const int* cb = chars + b * TDIM;

    if (tid < 32) sch[tid] = cb[tBase + tid];
    __syncthreads();

    for (int idx = tid; idx < 32 * 64; idx += 256) {
        int tok = idx >> 6, c = idx & 63;
        sxt[c][tok] = emb_byte[sch[tok] * 64 + c];
    }
    for (int idx = tid; idx < 32 * 64; idx += 256) {
        int tok = idx >> 6, c = idx & 63;
        int t = tBase + tok;
        float acc = conv_b[c];
#pragma unroll
        for (int k = 0; k < 4; k++) {
            int tt = t - 3 + k;
            float v = (tt >= 0) ? g_hf[(size_t)(b * TDIM + tt) * 64 + c] : 0.f;
            acc = fmaf(conv_w[c * 4 + k], v, acc);
        }
        sxt[64 + c][tok] = silu_f(acc);
    }
    for (int idx = tid; idx < 128; idx += 256) {
        int tok = idx >> 2, mm = idx & 3;
        int k = 1 << mm;
        int t = tBase + tok;
        float v = 0.f;
        if (t >= k) v = (cb[t] == cb[t - k]) ? 1.f : 0.f;
        sxt[128 + mm][tok] = v;
    }
    __syncthreads();

    u64 acc[16][2];
#pragma unroll
    for (int i = 0; i < 16; i++) { acc[i][0] = 0ull; acc[i][1] = 0ull; }

#pragma unroll 1
    for (int k4 = 0; k4 < 132; k4 += 4) {
        u64 wp[4][2];
#pragma unroll
        for (int j = 0; j < 4; j++) {
            wp[j][0] = pack2(Win[(size_t)(k4 + j) * 512 + tid]);
            wp[j][1] = pack2(Win[(size_t)(k4 + j) * 512 + tid + 256]);
        }
#pragma unroll
        for (int j = 0; j < 4; j++) {
            const ulonglong2* xr = (const ulonglong2*)&sxt[k4 + j][0];
#pragma unroll
            for (int q = 0; q < 8; q++) {
                ulonglong2 x2 = xr[q];
                ffma2(acc[2 * q][0],     x2.x, wp[j][0]);
                ffma2(acc[2 * q][1],     x2.x, wp[j][1]);
                ffma2(acc[2 * q + 1][0], x2.y, wp[j][0]);
                ffma2(acc[2 * q + 1][1], x2.y, wp[j][1]);
            }
        }
    }
#pragma unroll
    for (int cc = 0; cc < 2; cc++) {
        int col = tid + cc * 256;
        float bv = b_in[col];
#pragma unroll
        for (int p = 0; p < 16; p++) {
            size_t r0 = (size_t)(b * TDIM + tBase + 2 * p) * 512 + col;
            g_h[r0]       = silu_f(lo32(acc[p][cc]) + bv);
            g_h[r0 + 512] = silu_f(hi32(acc[p][cc]) + bv);
        }
    }
}

// ---------------------------------------------------------------------------
// K3: gates/drive (verified)
// ---------------------------------------------------------------------------
__global__ void __launch_bounds__(256) k_gates(
    const float* __restrict__ Wg, const float* __restrict__ bg,
    const float* __restrict__ Wi, const float* __restrict__ bi)
{
    __shared__ u64 smbuf[4096];
    float (*sxt)[32] = reinterpret_cast<float(*)[32]>(smbuf);

    int tid = threadIdx.x;
    int col = tid & 63;
    int ks  = tid >> 6;
    int n0 = blockIdx.x * 32;
    int b = n0 / TDIM, t0 = n0 % TDIM;

    u64 acc[16];
#pragma unroll
    for (int i = 0; i < 16; i++) acc[i] = 0ull;

    const float* Wsel = (col < 32) ? Wg : Wi;
    int wcol = col & 31;

    for (int kb = 0; kb < 512; kb += 128) {
        __syncthreads();
        for (int i = tid; i < 32 * 32; i += 256) {
            int tok = i & 31;
            int k4 = (i >> 5) << 2;
            float4 v = *(const float4*)&g_h[(size_t)(n0 + tok) * 512 + kb + k4];
            sxt[k4][tok] = v.x; sxt[k4 + 1][tok] = v.y;
            sxt[k4 + 2][tok] = v.z; sxt[k4 + 3][tok] = v.w;
        }
        __syncthreads();
        int kBase = ks * 32;
#pragma unroll 1
        for (int k = 0; k < 32; k++) {
            u64 wv = pack2(Wsel[(size_t)(kb + kBase + k) * 32 + wcol]);
            const ulonglong2* xr = (const ulonglong2*)&sxt[kBase + k][0];
#pragma unroll
            for (int q = 0; q < 8; q++) {
                ulonglong2 x2 = xr[q];
                ffma2(acc[2 * q],     x2.x, wv);
                ffma2(acc[2 * q + 1], x2.y, wv);
            }
        }
    }
    __syncthreads();
#pragma unroll
    for (int p = 0; p < 16; p++) smbuf[((size_t)ks * 64 + col) * 16 + p] = acc[p];
    __syncthreads();
    if (ks == 0 && col < 32) {
        int j = col;
        float bgv = bg[j], biv = bi[j];
        float* gout = g_gates + (size_t)(b * SSDIM + j) * TDIM + t0;
        float* dout = g_drive + (size_t)(b * SSDIM + j) * TDIM + t0;
#pragma unroll
        for (int p = 0; p < 16; p++) {
            float ag0 = bgv, ag1 = bgv, ai0 = biv, ai1 = biv;
#pragma unroll
            for (int s = 0; s < 4; s++) {
                u64 vg = smbuf[((size_t)s * 64 + j) * 16 + p];
                u64 vi = smbuf[((size_t)s * 64 + 32 + j) * 16 + p];
                ag0 += lo32(vg); ag1 += hi32(vg);
                ai0 += lo32(vi); ai1 += hi32(vi);
            }
            float g0 = 1.f / (1.f + __expf(-ag0));
            float g1 = 1.f / (1.f + __expf(-ag1));
            gout[2 * p]     = g0;
            gout[2 * p + 1] = g1;
            dout[2 * p]     = (1.f - g0) * ai0;
            dout[2 * p + 1] = (1.f - g1) * ai1;
        }
    }
}

// ---------------------------------------------------------------------------
// K4: chunk-parallel TinyScan (verified)
// ---------------------------------------------------------------------------
__global__ void __launch_bounds__(256) k_scan()
{
    int bs = blockIdx.x;
    int j = threadIdx.x;
    const float* ga = g_gates + (size_t)bs * TDIM + j * 32;
    const float* dr = g_drive + (size_t)bs * TDIM + j * 32;
    float a[32], bb[32];
#pragma unroll
    for (int i = 0; i < 32; i++) {
        a[i]  = fmaxf(ga[i], 1e-6f);
        bb[i] = dr[i];
    }
    float cumA = 1.f, cumWB = 0.f;
#pragma unroll
    for (int i = 0; i < 32; i++) {
        cumA *= a[i];
        float inv = 1.f / fmaxf(cumA, 1e-8f);
        cumWB = fmaf(bb[i], inv, cumWB);
    }
    __shared__ float sA[256], sB[256];
    sA[j] = cumA;
    sB[j] = cumA * cumWB;
    __syncthreads();
    for (int d = 1; d < 256; d <<= 1) {
        float a2 = sA[j], b2 = sB[j], a1 = 0.f, b1 = 0.f;
        if (j >= d) { a1 = sA[j - d]; b1 = sB[j - d]; }
        __syncthreads();
        if (j >= d) { sA[j] = a2 * a1; sB[j] = fmaf(a2, b1, b2); }
        __syncthreads();
    }
    float hc = (j == 0) ? 0.f : sB[j - 1];
    cumA = 1.f; cumWB = 0.f;
    float* st = g_states + (size_t)bs * TDIM + j * 32;
#pragma unroll
    for (int i = 0; i < 32; i++) {
        cumA *= a[i];
        float inv = 1.f / fmaxf(cumA, 1e-8f);
        cumWB = fmaf(bb[i], inv, cumWB);
        st[i] = cumA * (hc + cumWB);
    }
}

// ---------------------------------------------------------------------------
// K5a: y = h + states@Wo + bo (verified)
// ---------------------------------------------------------------------------
__global__ void __launch_bounds__(256) k_wo(
    const float* __restrict__ Wo, const float* __restrict__ bo)
{
    __shared__ float sxt[32][32];
    int tid = threadIdx.x;
    int n0 = blockIdx.x * 32;
    int b = n0 / TDIM, t0 = n0 % TDIM;

    for (int i = tid; i < 32 * 8; i += 256) {
        int s = i >> 3, t4 = (i & 7) * 4;
        float4 v = *(const float4*)&g_states[(size_t)(b * SSDIM + s) * TDIM + t0 + t4];
        *(float4*)&sxt[s][t4] = v;
    }
    __syncthreads();

    u64 acc[16][2];
#pragma unroll
    for (int i = 0; i < 16; i++) { acc[i][0] = 0ull; acc[i][1] = 0ull; }

#pragma unroll 1
    for (int k4 = 0; k4 < 32; k4 += 4) {
        u64 wp[4][2];
#pragma unroll
        for (int j = 0; j < 4; j++) {
            wp[j][0] = pack2(Wo[(size_t)(k4 + j) * 512 + tid]);
            wp[j][1] = pack2(Wo[(size_t)(k4 + j) * 512 + tid + 256]);
        }
#pragma unroll
        for (int j = 0; j < 4; j++) {
            const ulonglong2* xr = (const ulonglong2*)&sxt[k4 + j][0];
#pragma unroll
            for (int q = 0; q < 8; q++) {
                ulonglong2 x2 = xr[q];
                ffma2(acc[2 * q][0],     x2.x, wp[j][0]);
                ffma2(acc[2 * q][1],     x2.x, wp[j][1]);
                ffma2(acc[2 * q + 1][0], x2.y, wp[j][0]);
                ffma2(acc[2 * q + 1][1], x2.y, wp[j][1]);
            }
        }
    }
#pragma unroll
    for (int cc = 0; cc < 2; cc++) {
        int col = tid + cc * 256;
        float bv = bo[col];
#pragma unroll
        for (int p = 0; p < 16; p++) {
            size_t r0 = (size_t)(n0 + 2 * p) * 512 + col;
            g_h2[r0]       = lo32(acc[p][cc]) + bv + g_h[r0];
            g_h2[r0 + 512] = hi32(acc[p][cc]) + bv + g_h[r0 + 512];
        }
    }
}

// ---------------------------------------------------------------------------
// K5b: LayerNorm + fp16 hi/lo split write for the tensor path
// ---------------------------------------------------------------------------
__global__ void __launch_bounds__(128) k_ln(
    const float* __restrict__ lng, const float* __restrict__ lnb)
{
    int n = blockIdx.x;
    int tid = threadIdx.x;
    int c = tid * 4;
    float4 y = *(const float4*)&g_h2[(size_t)n * 512 + c];
    float lsum = y.x + y.y + y.z + y.w;
    float lsq  = y.x * y.x + y.y * y.y + y.z * y.z + y.w * y.w;
#pragma unroll
    for (int off = 16; off; off >>= 1) {
        lsum += __shfl_xor_sync(0xffffffffu, lsum, off);
        lsq  += __shfl_xor_sync(0xffffffffu, lsq,  off);
    }
    __shared__ float red[4][2];
    int wip = tid >> 5, lane = tid & 31;
    if (lane == 0) { red[wip][0] = lsum; red[wip][1] = lsq; }
    __syncthreads();
    lsum = red[0][0] + red[1][0] + red[2][0] + red[3][0];
    lsq  = red[0][1] + red[1][1] + red[2][1] + red[3][1];
    float mu = lsum * (1.f / 512.f);
    float var = lsq * (1.f / 512.f) - mu * mu;
    float rstd = rsqrtf(var + 1e-5f);
    float4 g4 = *(const float4*)&lng[c];
    float4 b4 = *(const float4*)&lnb[c];
    float4 o;
    o.x = (y.x - mu) * rstd * g4.x + b4.x;
    o.y = (y.y - mu) * rstd * g4.y + b4.y;
    o.z = (y.z - mu) * rstd * g4.z + b4.z;
    o.w = (y.w - mu) * rstd * g4.w + b4.w;
    *(float4*)&g_h2[(size_t)n * 512 + c] = o;
    float vs[4] = {o.x, o.y, o.z, o.w};
    __half hh[4], hl[4];
#pragma unroll
    for (int e = 0; e < 4; e++) {
        hh[e] = __float2half_rn(vs[e]);
        hl[e] = __float2half_rn(vs[e] - __half2float(hh[e]));
    }
    size_t base = (size_t)n * 512 + c;
    *(__half2*)&g_xh[base]     = *(__half2*)&hh[0];
    *(__half2*)&g_xh[base + 2] = *(__half2*)&hh[2];
    *(__half2*)&g_xl[base]     = *(__half2*)&hl[0];
    *(__half2*)&g_xl[base + 2] = *(__half2*)&hl[2];
}

// ---------------------------------------------------------------------------
// Weight prep: W[k][N] f32 -> transposed fp16 [n*512+k]
// ---------------------------------------------------------------------------
__global__ void __launch_bounds__(256) k_prep_w(
    const float* __restrict__ W, int N, int layer)
{
    int idx = blockIdx.x * 256 + threadIdx.x;
    int k = idx & 511;
    int n = idx >> 9;
    if (n >= N) return;
    float w = W[(size_t)k * N + n];
    g_wh[layer][(size_t)n * 512 + k] = __float2half_rn(w);
}

// ---------------------------------------------------------------------------
// Split-fp16 mma.sync GEMM: D = Xh@Wh' + Xl@Wh'  (fp32 accum; W single fp16)
// CTA: 256x128xK512, 8 warps 4x2, warp tile 64x64 -> 64 MMAs per 12 ldmx4/kc.
// 2-stage cp.async double buffer, KT=64 (80KB/stage, 160KB total).
// stage layout: Ah @0 (32KB, 256x128B), Al @32768, Bh @65536 (16KB)
// ---------------------------------------------------------------------------
#define NKT 8
#define STAGE_BYTES 81920
#define SMEM_MM (2 * STAGE_BYTES)

template<int NOUT, int RESACT, int SPLIT, int WF32>
__global__ void __launch_bounds__(256) k_mma(
    const __half* __restrict__ xh, const __half* __restrict__ xl,
    const float* __restrict__ xres,
    const __half* __restrict__ wh,
    const float* __restrict__ bias,
    float* __restrict__ yf, __half* __restrict__ yh, __half* __restrict__ yl)
{
    extern __shared__ char dsm[];
    uint32_t smem0 = smem_u32(dsm);
    int tid = threadIdx.x;
    int wid = tid >> 5, lane = tid & 31;
    int wm = wid >> 1, wn = wid & 1;          // warp tile: rows wm*64, cols wn*64
    int m0 = blockIdx.x * 256;
    int n0 = blockIdx.y * 128;

    float c[4][8][4];
#pragma unroll
    for (int i = 0; i < 4; i++)
#pragma unroll
        for (int j = 0; j < 8; j++)
#pragma unroll
            for (int e = 0; e < 4; e++) c[i][j][e] = 0.f;

    // stage fill: Ah/Al 256 rows, Bh 128 rows; 5120 16B-chunks, 20/thread
    auto fill = [&](int kt) {
        int stage = kt & 1;
        int kb = kt * 64;
        uint32_t sb = smem0 + stage * STAGE_BYTES;
#pragma unroll
        for (int j = 0; j < 20; j++) {
            int cidx = tid + 256 * j;
            const __half* src;
            uint32_t toff;
            int idx;
            if (cidx < 2048)      { idx = cidx;        toff = 0;     src = xh + (size_t)(m0 + (idx >> 3)) * 512; }
            else if (cidx < 4096) { idx = cidx - 2048; toff = 32768; src = xl + (size_t)(m0 + (idx >> 3)) * 512; }
            else                  { idx = cidx - 4096; toff = 65536; src = wh + (size_t)(n0 + (idx >> 3)) * 512; }
            int row = idx >> 3;
            int c16 = idx & 7;
            uint32_t dst = sb + toff + row * 128 + ((c16 ^ (row & 7)) << 4);
            cpasync16(dst, (const void*)(src + kb + c16 * 8));
        }
        CP_COMMIT();
    };

    fill(0);

    int la = lane & 15, lh = lane >> 4;

    for (int i = 0; i < NKT; i++) {
        uint32_t sb = smem0 + (i & 1) * STAGE_BYTES;
        if (i + 1 < NKT) { fill(i + 1); CP_WAIT1(); } else { CP_WAIT0(); }
        __syncthreads();

#pragma unroll
        for (int kc = 0; kc < 4; kc++) {
            int c16 = kc * 2 + lh;
            uint32_t ah[4][4], al[4][4];
#pragma unroll
            for (int mt = 0; mt < 4; mt++)
                ldmx4(ah[mt], tile_addr(sb,         wm * 64 + mt * 16 + la, c16));
#pragma unroll
            for (int mt = 0; mt < 4; mt++)
                ldmx4(al[mt], tile_addr(sb + 32768, wm * 64 + mt * 16 + la, c16));
            // B in two halves of 32 cols each to cap register peak
#pragma unroll
            for (int hb = 0; hb < 2; hb++) {
                uint32_t bhf[2][4];
#pragma unroll
                for (int g = 0; g < 2; g++)
                    ldmx4(bhf[g], tile_addr(sb + 65536, wn * 64 + (hb * 2 + g) * 16 + la, c16));
#pragma unroll
                for (int mt = 0; mt < 4; mt++) {
#pragma unroll
                    for (int nt = 0; nt < 4; nt++) {
                        int g = nt >> 1, h = nt & 1;
                        float* cc = c[mt][hb * 4 + nt];
                        mma16816(cc, ah[mt], bhf[g][h], bhf[g][2 + h]);
                        mma16816(cc, al[mt], bhf[g][h], bhf[g][2 + h]);
                    }
                }
            }
        }
        __syncthreads();   // all reads of this stage done before next fill overwrites
    }

    // ---- epilogue straight from registers ----
    int r0 = lane >> 2;
    int cp = (lane & 3) * 2;
#pragma unroll
    for (int nt = 0; nt < 8; nt++) {
        int col = n0 + wn * 64 + nt * 8 + cp;
        float2 bv = *(const float2*)&bias[col];
#pragma unroll
        for (int mt = 0; mt < 4; mt++) {
#pragma unroll
            for (int half = 0; half < 2; half++) {
                int row = m0 + wm * 64 + mt * 16 + r0 + half * 8;
                float v0 = c[mt][nt][2 * half]     + bv.x;
                float v1 = c[mt][nt][2 * half + 1] + bv.y;
                if (RESACT) {
                    float2 xr = *(const float2*)&xres[(size_t)row * 512 + col];
                    v0 = xr.x + silu_f(v0);
                    v1 = xr.y + silu_f(v1);
                }
                if (WF32) {
                    *(float2*)&yf[(size_t)row * NOUT + col] = make_float2(v0, v1);
                }
                if (SPLIT) {
                    __half h0 = __float2half_rn(v0);
                    __half h1 = __float2half_rn(v1);
                    __half l0 = __float2half_rn(v0 - __half2float(h0));
                    __half l1 = __float2half_rn(v1 - __half2float(h1));
                    size_t base = (size_t)row * 512 + col;
                    __half2 hp; hp.x = h0; hp.y = h1;
                    __half2 lp; lp.x = l0; lp.y = l1;
                    *(__half2*)&yh[base] = hp;
                    *(__half2*)&yl[base] = lp;
                }
            }
        }
    }
}

// ---------------------------------------------------------------------------
extern "C" void kernel_launch(void* const* d_in, const int* in_sizes, int n_in,
                              void* d_out, int out_size)
{
    const int*   chars    = (const int*)d_in[0];
    const float* emb_byte = (const float*)d_in[1];
    const float* htab     = (const float*)d_in[2];
    const float* Wq       = (const float*)d_in[3];
    const float* bq       = (const float*)d_in[4];
    const float* conv_w   = (const float*)d_in[5];
    const float* conv_b   = (const float*)d_in[6];
    const float* Win      = (const float*)d_in[7];
    const float* b_in     = (const float*)d_in[8];
    const float* Wg       = (const float*)d_in[9];
    const float* bg       = (const float*)d_in[10];
    const float* Wi       = (const float*)d_in[11];
    const float* bi       = (const float*)d_in[12];
    const float* Wo       = (const float*)d_in[13];
    const float* bo       = (const float*)d_in[14];
    const float* lng      = (const float*)d_in[15];
    const float* lnb      = (const float*)d_in[16];
    const float* mlp_w    = (const float*)d_in[17];
    const float* mlp_b    = (const float*)d_in[18];
    const float* Wout     = (const float*)d_in[19];
    const float* bout     = (const float*)d_in[20];
    float* out = (float*)d_out;

    void *p;
    cudaGetSymbolAddress(&p, g_h);   float* gh  = (float*)p;
    cudaGetSymbolAddress(&p, g_h2);  float* gh2 = (float*)p;
    cudaGetSymbolAddress(&p, g_xh);  __half* xh  = (__half*)p;
    cudaGetSymbolAddress(&p, g_xl);  __half* xl  = (__half*)p;
    cudaGetSymbolAddress(&p, g_x2h); __half* x2h = (__half*)p;
    cudaGetSymbolAddress(&p, g_x2l); __half* x2l = (__half*)p;
    cudaGetSymbolAddress(&p, g_wh);  __half* wh  = (__half*)p;

    static int attr_done = 0;
    if (!attr_done) {
        cudaFuncSetAttribute(k_mma<512,1,1,1>, cudaFuncAttributeMaxDynamicSharedMemorySize, SMEM_MM);
        cudaFuncSetAttribute(k_mma<512,1,1,0>, cudaFuncAttributeMaxDynamicSharedMemorySize, SMEM_MM);
        cudaFuncSetAttribute(k_mma<256,0,0,1>, cudaFuncAttributeMaxDynamicSharedMemorySize, SMEM_MM);
        attr_done = 1;
    }

    // weight prep (fp16 transpose)
    k_prep_w<<<512 * 512 / 256, 256>>>(mlp_w,                 512, 0);
    k_prep_w<<<512 * 512 / 256, 256>>>(mlp_w + 512 * 512,     512, 1);
    k_prep_w<<<512 * 512 / 256, 256>>>(mlp_w + 2 * 512 * 512, 512, 2);
    k_prep_w<<<256 * 512 / 256, 256>>>(Wout,                  256, 3);

    k_hashfeat<<<BT / 8, 256>>>(chars, emb_byte, htab, Wq, bq);
    k_feat_win<<<BT / 32, 256>>>(chars, emb_byte, conv_w, conv_b, Win, b_in);
    k_gates<<<BT / 32, 256>>>(Wg, bg, Wi, bi);
    k_scan<<<BDIM * SSDIM, 256>>>();
    k_wo<<<BT / 32, 256>>>(Wo, bo);
    k_ln<<<BT, 128>>>(lng, lnb);

    dim3 g512(BT / 256, 4), g256(BT / 256, 2);
    // L1: in (xh,xl), resid g_h2 -> f32 g_h + split x2
    k_mma<512,1,1,1><<<g512, 256, SMEM_MM>>>(xh, xl, gh2,
        wh + 0 * (size_t)512 * 512, mlp_b, gh, x2h, x2l);
    // L2: in (x2h,x2l), resid g_h -> f32 g_h2 + split x
    k_mma<512,1,1,1><<<g512, 256, SMEM_MM>>>(x2h, x2l, gh,
        wh + 1 * (size_t)512 * 512, mlp_b + 512, gh2, xh, xl);
    // L3: in (xh,xl), resid g_h2 -> split x2 only
    k_mma<512,1,1,0><<<g512, 256, SMEM_MM>>>(xh, xl, gh2,
        wh + 2 * (size_t)512 * 512, mlp_b + 1024, 0, x2h, x2l);
    // Wout: in (x2h,x2l) -> out f32 [65536,256]
    k_mma<256,0,0,1><<<g256, 256, SMEM_MM>>>(x2h, x2l, 0,
        wh + 3 * (size_t)512 * 512, bout, out, 0, 0);
}

// round 12
// speedup vs baseline: 2.5502x; 1.3625x over previous
#include <cuda_runtime.h>
#include <cuda_fp16.h>
#include <math.h>
#include <stdint.h>

#define BDIM 8
#define TDIM 8192
#define BT (BDIM*TDIM)
#define HDIM 512
#define SSDIM 32

typedef unsigned long long u64;

// ---------------- scratch (device globals; no allocations allowed) ----------
__device__ float g_hf[BT*64];
__device__ float g_h[BT*HDIM];
__device__ float g_h2[BT*HDIM];
__device__ float g_gates[BDIM*SSDIM*TDIM];
__device__ float g_drive[BDIM*SSDIM*TDIM];
__device__ float g_states[BDIM*SSDIM*TDIM];
// fp16 activations (ping/pong)
__device__ __half g_xh[(size_t)BT*512];
__device__ __half g_x2h[(size_t)BT*512];
// fp16 transposed weights [layer][n*512+k]
__device__ __half g_wh[4][512*512];

__device__ __forceinline__ float silu_f(float x) { return x / (1.f + __expf(-x)); }

__device__ __forceinline__ u64 pack2(float x) {
    u64 r; asm("mov.b64 %0, {%1, %1};" : "=l"(r) : "f"(x)); return r;
}
__device__ __forceinline__ void ffma2(u64& d, u64 a, u64 b) {
    asm("fma.rn.f32x2 %0, %1, %2, %3;" : "=l"(d) : "l"(a), "l"(b), "l"(d));
}
__device__ __forceinline__ float lo32(u64 v) { return __uint_as_float((unsigned)v); }
__device__ __forceinline__ float hi32(u64 v) { return __uint_as_float((unsigned)(v >> 32)); }

// ---------------- mma.sync / async helpers (arch-agnostic, sm_80+) ----------
__device__ __forceinline__ uint32_t smem_u32(const void* p) {
    uint32_t a;
    asm("{ .reg .u64 t; cvta.to.shared.u64 t, %1; cvt.u32.u64 %0, t; }" : "=r"(a) : "l"(p));
    return a;
}
#define CP_COMMIT()      asm volatile("cp.async.commit_group;" ::: "memory")
#define CP_WAIT1()       asm volatile("cp.async.wait_group 1;" ::: "memory")
#define CP_WAIT0()       asm volatile("cp.async.wait_group 0;" ::: "memory")

__device__ __forceinline__ void cpasync16(uint32_t dst, const void* src) {
    asm volatile("cp.async.cg.shared.global [%0], [%1], 16;" :: "r"(dst), "l"(src));
}
__device__ __forceinline__ void ldmx4(uint32_t* r, uint32_t addr) {
    asm volatile("ldmatrix.sync.aligned.m8n8.x4.shared.b16 {%0,%1,%2,%3}, [%4];"
        : "=r"(r[0]), "=r"(r[1]), "=r"(r[2]), "=r"(r[3]) : "r"(addr));
}
__device__ __forceinline__ void mma16816(float* c, const uint32_t* a,
                                         uint32_t b0, uint32_t b1) {
    asm volatile("mma.sync.aligned.m16n8k16.row.col.f32.f16.f16.f32 "
        "{%0,%1,%2,%3}, {%4,%5,%6,%7}, {%8,%9}, {%0,%1,%2,%3};"
        : "+f"(c[0]), "+f"(c[1]), "+f"(c[2]), "+f"(c[3])
        : "r"(a[0]), "r"(a[1]), "r"(a[2]), "r"(a[3]), "r"(b0), "r"(b1));
}
// 16B-granular XOR swizzle within a 128B row (conflict-free ldmatrix)
__device__ __forceinline__ uint32_t tile_addr(uint32_t tbase, int row, int c16) {
    return tbase + row * 128 + ((c16 ^ (row & 7)) << 4);
}

// ---------------------------------------------------------------------------
// K1: rolling hashes + scale attention -> g_hf (verified)
// ---------------------------------------------------------------------------
__global__ void __launch_bounds__(256) k_hashfeat(
    const int* __restrict__ chars, const float* __restrict__ emb_byte,
    const float* __restrict__ htab, const float* __restrict__ Wq,
    const float* __restrict__ bq)
{
    int gw = (blockIdx.x * blockDim.x + threadIdx.x) >> 5;
    if (gw >= BT) return;
    int lane = threadIdx.x & 31;
    int wip  = threadIdx.x >> 5;
    int b = gw / TDIM, t = gw % TDIM;
    const int* cb = chars + b * TDIM;

    int myc = (lane < 16 && t >= lane) ? cb[t - lane] : 0;

    int acc0 = 0, acc1 = 0, acc2 = 0, acc3 = 0;
    int p = 1;
#pragma unroll
    for (int j = 0; j < 16; j++) {
        int cj = __shfl_sync(0xffffffffu, myc, j);
        int term = cj * p;
        if (j < 2) acc0 += term;
        if (j < 4) acc1 += term;
        if (j < 8) acc2 += term;
        acc3 += term;
        p = (p * 257) & 4095;
    }
    int h0 = acc0 & 4095, h1 = acc1 & 4095, h2 = acc2 & 4095, h3 = acc3 & 4095;

    int c0 = lane * 2;
    int ch0 = __shfl_sync(0xffffffffu, myc, 0);
    float2 be = *(const float2*)&emb_byte[ch0 * 64 + c0];

    __shared__ float s_be[8][64];
    s_be[wip][c0]     = be.x;
    s_be[wip][c0 + 1] = be.y;
    __syncwarp();

    float q0 = bq[c0], q1 = bq[c0 + 1];
#pragma unroll 8
    for (int k = 0; k < 64; k++) {
        float bk = s_be[wip][k];
        float2 wv = *(const float2*)&Wq[k * 64 + c0];
        q0 = fmaf(bk, wv.x, q0);
        q1 = fmaf(bk, wv.y, q1);
    }

    float2 se0 = *(const float2*)&htab[(size_t)(0 * 4096 + h0) * 64 + c0];
    float2 se1 = *(const float2*)&htab[(size_t)(1 * 4096 + h1) * 64 + c0];
    float2 se2 = *(const float2*)&htab[(size_t)(2 * 4096 + h2) * 64 + c0];
    float2 se3 = *(const float2*)&htab[(size_t)(3 * 4096 + h3) * 64 + c0];

    float s0 = q0 * se0.x + q1 * se0.y;
    float s1 = q0 * se1.x + q1 * se1.y;
    float s2 = q0 * se2.x + q1 * se2.y;
    float s3 = q0 * se3.x + q1 * se3.y;
#pragma unroll
    for (int off = 16; off; off >>= 1) {
        s0 += __shfl_xor_sync(0xffffffffu, s0, off);
        s1 += __shfl_xor_sync(0xffffffffu, s1, off);
        s2 += __shfl_xor_sync(0xffffffffu, s2, off);
        s3 += __shfl_xor_sync(0xffffffffu, s3, off);
    }
    s0 *= 0.125f; s1 *= 0.125f; s2 *= 0.125f; s3 *= 0.125f;
    float m = fmaxf(fmaxf(s0, s1), fmaxf(s2, s3));
    float e0 = __expf(s0 - m), e1 = __expf(s1 - m), e2 = __expf(s2 - m), e3 = __expf(s3 - m);
    float inv = 1.f / (e0 + e1 + e2 + e3);
    float o0 = (e0 * se0.x + e1 * se1.x + e2 * se2.x + e3 * se3.x) * inv;
    float o1 = (e0 * se0.y + e1 * se1.y + e2 * se2.y + e3 * se3.y) * inv;
    *(float2*)&g_hf[(size_t)gw * 64 + c0] = make_float2(o0, o1);
}

// ---------------------------------------------------------------------------
// K2: features + Win GEMM (verified)
// ---------------------------------------------------------------------------
__global__ void __launch_bounds__(256) k_feat_win(
    const int* __restrict__ chars, const float* __restrict__ emb_byte,
    const float* __restrict__ conv_w, const float* __restrict__ conv_b,
    const float* __restrict__ Win, const float* __restrict__ b_in)
{
    __shared__ float sxt[132][32];
    __shared__ int sch[32];
    int blk = blockIdx.x;
    int b = blk / (TDIM / 32);
    int tBase = (blk % (TDIM / 32)) * 32;
    int tid = threadIdx.x;
    const int* cb = chars + b * TDIM;

    if (tid < 32) sch[tid] = cb[tBase + tid];
    __syncthreads();

    for (int idx = tid; idx < 32 * 64; idx += 256) {
        int tok = idx >> 6, c = idx & 63;
        sxt[c][tok] = emb_byte[sch[tok] * 64 + c];
    }
    for (int idx = tid; idx < 32 * 64; idx += 256) {
        int tok = idx >> 6, c = idx & 63;
        int t = tBase + tok;
        float acc = conv_b[c];
#pragma unroll
        for (int k = 0; k < 4; k++) {
            int tt = t - 3 + k;
            float v = (tt >= 0) ? g_hf[(size_t)(b * TDIM + tt) * 64 + c] : 0.f;
            acc = fmaf(conv_w[c * 4 + k], v, acc);
        }
        sxt[64 + c][tok] = silu_f(acc);
    }
    for (int idx = tid; idx < 128; idx += 256) {
        int tok = idx >> 2, mm = idx & 3;
        int k = 1 << mm;
        int t = tBase + tok;
        float v = 0.f;
        if (t >= k) v = (cb[t] == cb[t - k]) ? 1.f : 0.f;
        sxt[128 + mm][tok] = v;
    }
    __syncthreads();

    u64 acc[16][2];
#pragma unroll
    for (int i = 0; i < 16; i++) { acc[i][0] = 0ull; acc[i][1] = 0ull; }

#pragma unroll 1
    for (int k4 = 0; k4 < 132; k4 += 4) {
        u64 wp[4][2];
#pragma unroll
        for (int j = 0; j < 4; j++) {
            wp[j][0] = pack2(Win[(size_t)(k4 + j) * 512 + tid]);
            wp[j][1] = pack2(Win[(size_t)(k4 + j) * 512 + tid + 256]);
        }
#pragma unroll
        for (int j = 0; j < 4; j++) {
            const ulonglong2* xr = (const ulonglong2*)&sxt[k4 + j][0];
#pragma unroll
            for (int q = 0; q < 8; q++) {
                ulonglong2 x2 = xr[q];
                ffma2(acc[2 * q][0],     x2.x, wp[j][0]);
                ffma2(acc[2 * q][1],     x2.x, wp[j][1]);
                ffma2(acc[2 * q + 1][0], x2.y, wp[j][0]);
                ffma2(acc[2 * q + 1][1], x2.y, wp[j][1]);
            }
        }
    }
#pragma unroll
    for (int cc = 0; cc < 2; cc++) {
        int col = tid + cc * 256;
        float bv = b_in[col];
#pragma unroll
        for (int p = 0; p < 16; p++) {
            size_t r0 = (size_t)(b * TDIM + tBase + 2 * p) * 512 + col;
            g_h[r0]       = silu_f(lo32(acc[p][cc]) + bv);
            g_h[r0 + 512] = silu_f(hi32(acc[p][cc]) + bv);
        }
    }
}

// ---------------------------------------------------------------------------
// K3: gates/drive (verified)
// ---------------------------------------------------------------------------
__global__ void __launch_bounds__(256) k_gates(
    const float* __restrict__ Wg, const float* __restrict__ bg,
    const float* __restrict__ Wi, const float* __restrict__ bi)
{
    __shared__ u64 smbuf[4096];
    float (*sxt)[32] = reinterpret_cast<float(*)[32]>(smbuf);

    int tid = threadIdx.x;
    int col = tid & 63;
    int ks  = tid >> 6;
    int n0 = blockIdx.x * 32;
    int b = n0 / TDIM, t0 = n0 % TDIM;

    u64 acc[16];
#pragma unroll
    for (int i = 0; i < 16; i++) acc[i] = 0ull;

    const float* Wsel = (col < 32) ? Wg : Wi;
    int wcol = col & 31;

    for (int kb = 0; kb < 512; kb += 128) {
        __syncthreads();
        for (int i = tid; i < 32 * 32; i += 256) {
            int tok = i & 31;
            int k4 = (i >> 5) << 2;
            float4 v = *(const float4*)&g_h[(size_t)(n0 + tok) * 512 + kb + k4];
            sxt[k4][tok] = v.x; sxt[k4 + 1][tok] = v.y;
            sxt[k4 + 2][tok] = v.z; sxt[k4 + 3][tok] = v.w;
        }
        __syncthreads();
        int kBase = ks * 32;
#pragma unroll 1
        for (int k = 0; k < 32; k++) {
            u64 wv = pack2(Wsel[(size_t)(kb + kBase + k) * 32 + wcol]);
            const ulonglong2* xr = (const ulonglong2*)&sxt[kBase + k][0];
#pragma unroll
            for (int q = 0; q < 8; q++) {
                ulonglong2 x2 = xr[q];
                ffma2(acc[2 * q],     x2.x, wv);
                ffma2(acc[2 * q + 1], x2.y, wv);
            }
        }
    }
    __syncthreads();
#pragma unroll
    for (int p = 0; p < 16; p++) smbuf[((size_t)ks * 64 + col) * 16 + p] = acc[p];
    __syncthreads();
    if (ks == 0 && col < 32) {
        int j = col;
        float bgv = bg[j], biv = bi[j];
        float* gout = g_gates + (size_t)(b * SSDIM + j) * TDIM + t0;
        float* dout = g_drive + (size_t)(b * SSDIM + j) * TDIM + t0;
#pragma unroll
        for (int p = 0; p < 16; p++) {
            float ag0 = bgv, ag1 = bgv, ai0 = biv, ai1 = biv;
#pragma unroll
            for (int s = 0; s < 4; s++) {
                u64 vg = smbuf[((size_t)s * 64 + j) * 16 + p];
                u64 vi = smbuf[((size_t)s * 64 + 32 + j) * 16 + p];
                ag0 += lo32(vg); ag1 += hi32(vg);
                ai0 += lo32(vi); ai1 += hi32(vi);
            }
            float g0 = 1.f / (1.f + __expf(-ag0));
            float g1 = 1.f / (1.f + __expf(-ag1));
            gout[2 * p]     = g0;
            gout[2 * p + 1] = g1;
            dout[2 * p]     = (1.f - g0) * ai0;
            dout[2 * p + 1] = (1.f - g1) * ai1;
        }
    }
}

// ---------------------------------------------------------------------------
// K4: chunk-parallel TinyScan (verified)
// ---------------------------------------------------------------------------
__global__ void __launch_bounds__(256) k_scan()
{
    int bs = blockIdx.x;
    int j = threadIdx.x;
    const float* ga = g_gates + (size_t)bs * TDIM + j * 32;
    const float* dr = g_drive + (size_t)bs * TDIM + j * 32;
    float a[32], bb[32];
#pragma unroll
    for (int i = 0; i < 32; i++) {
        a[i]  = fmaxf(ga[i], 1e-6f);
        bb[i] = dr[i];
    }
    float cumA = 1.f, cumWB = 0.f;
#pragma unroll
    for (int i = 0; i < 32; i++) {
        cumA *= a[i];
        float inv = 1.f / fmaxf(cumA, 1e-8f);
        cumWB = fmaf(bb[i], inv, cumWB);
    }
    __shared__ float sA[256], sB[256];
    sA[j] = cumA;
    sB[j] = cumA * cumWB;
    __syncthreads();
    for (int d = 1; d < 256; d <<= 1) {
        float a2 = sA[j], b2 = sB[j], a1 = 0.f, b1 = 0.f;
        if (j >= d) { a1 = sA[j - d]; b1 = sB[j - d]; }
        __syncthreads();
        if (j >= d) { sA[j] = a2 * a1; sB[j] = fmaf(a2, b1, b2); }
        __syncthreads();
    }
    float hc = (j == 0) ? 0.f : sB[j - 1];
    cumA = 1.f; cumWB = 0.f;
    float* st = g_states + (size_t)bs * TDIM + j * 32;
#pragma unroll
    for (int i = 0; i < 32; i++) {
        cumA *= a[i];
        float inv = 1.f / fmaxf(cumA, 1e-8f);
        cumWB = fmaf(bb[i], inv, cumWB);
        st[i] = cumA * (hc + cumWB);
    }
}

// ---------------------------------------------------------------------------
// K5a: y = h + states@Wo + bo (verified)
// ---------------------------------------------------------------------------
__global__ void __launch_bounds__(256) k_wo(
    const float* __restrict__ Wo, const float* __restrict__ bo)
{
    __shared__ float sxt[32][32];
    int tid = threadIdx.x;
    int n0 = blockIdx.x * 32;
    int b = n0 / TDIM, t0 = n0 % TDIM;

    for (int i = tid; i < 32 * 8; i += 256) {
        int s = i >> 3, t4 = (i & 7) * 4;
        float4 v = *(const float4*)&g_states[(size_t)(b * SSDIM + s) * TDIM + t0 + t4];
        *(float4*)&sxt[s][t4] = v;
    }
    __syncthreads();

    u64 acc[16][2];
#pragma unroll
    for (int i = 0; i < 16; i++) { acc[i][0] = 0ull; acc[i][1] = 0ull; }

#pragma unroll 1
    for (int k4 = 0; k4 < 32; k4 += 4) {
        u64 wp[4][2];
#pragma unroll
        for (int j = 0; j < 4; j++) {
            wp[j][0] = pack2(Wo[(size_t)(k4 + j) * 512 + tid]);
            wp[j][1] = pack2(Wo[(size_t)(k4 + j) * 512 + tid + 256]);
        }
#pragma unroll
        for (int j = 0; j < 4; j++) {
            const ulonglong2* xr = (const ulonglong2*)&sxt[k4 + j][0];
#pragma unroll
            for (int q = 0; q < 8; q++) {
                ulonglong2 x2 = xr[q];
                ffma2(acc[2 * q][0],     x2.x, wp[j][0]);
                ffma2(acc[2 * q][1],     x2.x, wp[j][1]);
                ffma2(acc[2 * q + 1][0], x2.y, wp[j][0]);
                ffma2(acc[2 * q + 1][1], x2.y, wp[j][1]);
            }
        }
    }
#pragma unroll
    for (int cc = 0; cc < 2; cc++) {
        int col = tid + cc * 256;
        float bv = bo[col];
#pragma unroll
        for (int p = 0; p < 16; p++) {
            size_t r0 = (size_t)(n0 + 2 * p) * 512 + col;
            g_h2[r0]       = lo32(acc[p][cc]) + bv + g_h[r0];
            g_h2[r0 + 512] = hi32(acc[p][cc]) + bv + g_h[r0 + 512];
        }
    }
}

// ---------------------------------------------------------------------------
// K5b: LayerNorm + single-fp16 activation write for the tensor path
// ---------------------------------------------------------------------------
__global__ void __launch_bounds__(128) k_ln(
    const float* __restrict__ lng, const float* __restrict__ lnb)
{
    int n = blockIdx.x;
    int tid = threadIdx.x;
    int c = tid * 4;
    float4 y = *(const float4*)&g_h2[(size_t)n * 512 + c];
    float lsum = y.x + y.y + y.z + y.w;
    float lsq  = y.x * y.x + y.y * y.y + y.z * y.z + y.w * y.w;
#pragma unroll
    for (int off = 16; off; off >>= 1) {
        lsum += __shfl_xor_sync(0xffffffffu, lsum, off);
        lsq  += __shfl_xor_sync(0xffffffffu, lsq,  off);
    }
    __shared__ float red[4][2];
    int wip = tid >> 5, lane = tid & 31;
    if (lane == 0) { red[wip][0] = lsum; red[wip][1] = lsq; }
    __syncthreads();
    lsum = red[0][0] + red[1][0] + red[2][0] + red[3][0];
    lsq  = red[0][1] + red[1][1] + red[2][1] + red[3][1];
    float mu = lsum * (1.f / 512.f);
    float var = lsq * (1.f / 512.f) - mu * mu;
    float rstd = rsqrtf(var + 1e-5f);
    float4 g4 = *(const float4*)&lng[c];
    float4 b4 = *(const float4*)&lnb[c];
    float4 o;
    o.x = (y.x - mu) * rstd * g4.x + b4.x;
    o.y = (y.y - mu) * rstd * g4.y + b4.y;
    o.z = (y.z - mu) * rstd * g4.z + b4.z;
    o.w = (y.w - mu) * rstd * g4.w + b4.w;
    __half hh[4];
    hh[0] = __float2half_rn(o.x);
    hh[1] = __float2half_rn(o.y);
    hh[2] = __float2half_rn(o.z);
    hh[3] = __float2half_rn(o.w);
    size_t base = (size_t)n * 512 + c;
    *(__half2*)&g_xh[base]     = *(__half2*)&hh[0];
    *(__half2*)&g_xh[base + 2] = *(__half2*)&hh[2];
}

// ---------------------------------------------------------------------------
// Weight prep: W[k][N] f32 -> transposed fp16 [n*512+k]
// ---------------------------------------------------------------------------
__global__ void __launch_bounds__(256) k_prep_w(
    const float* __restrict__ W, int N, int layer)
{
    int idx = blockIdx.x * 256 + threadIdx.x;
    int k = idx & 511;
    int n = idx >> 9;
    if (n >= N) return;
    float w = W[(size_t)k * N + n];
    g_wh[layer][(size_t)n * 512 + k] = __float2half_rn(w);
}

// ---------------------------------------------------------------------------
// fp16 1-term mma.sync GEMM: D = X16@W16' (fp32 accum)
// CTA: 256x128xK512, 8 warps 4x2, warp tile 64x64 -> 32 MMAs per 8 ldmx4/kc.
// 2-stage cp.async double buffer, KT=64 (48KB/stage, 96KB total).
// stage layout: A @0 (32KB, 256x128B), B @32768 (16KB)
// grid: blockIdx.x = n (fastest) so the 4 CTAs sharing an A tile are
// wave-adjacent -> A served from L2.
// Epilogue: RESACT reads resid from the SAME fp16 input x (self-consistent).
// ---------------------------------------------------------------------------
#define NKT 8
#define STAGE_BYTES 49152
#define SMEM_MM (2 * STAGE_BYTES)

template<int NOUT, int RESACT, int WF16, int WF32>
__global__ void __launch_bounds__(256) k_mma(
    const __half* __restrict__ xh,
    const __half* __restrict__ wh,
    const float* __restrict__ bias,
    float* __restrict__ yf, __half* __restrict__ yh)
{
    extern __shared__ char dsm[];
    uint32_t smem0 = smem_u32(dsm);
    int tid = threadIdx.x;
    int wid = tid >> 5, lane = tid & 31;
    int wm = wid >> 1, wn = wid & 1;          // warp tile: rows wm*64, cols wn*64
    int n0 = blockIdx.x * 128;
    int m0 = blockIdx.y * 256;

    float c[4][8][4];
#pragma unroll
    for (int i = 0; i < 4; i++)
#pragma unroll
        for (int j = 0; j < 8; j++)
#pragma unroll
            for (int e = 0; e < 4; e++) c[i][j][e] = 0.f;

    // stage fill: A 256 rows, B 128 rows; 3072 16B-chunks, 12/thread
    auto fill = [&](int kt) {
        int stage = kt & 1;
        int kb = kt * 64;
        uint32_t sb = smem0 + stage * STAGE_BYTES;
#pragma unroll
        for (int j = 0; j < 12; j++) {
            int cidx = tid + 256 * j;
            const __half* src;
            uint32_t toff;
            int idx;
            if (cidx < 2048) { idx = cidx;        toff = 0;     src = xh + (size_t)(m0 + (idx >> 3)) * 512; }
            else             { idx = cidx - 2048; toff = 32768; src = wh + (size_t)(n0 + (idx >> 3)) * 512; }
            int row = idx >> 3;
            int c16 = idx & 7;
            uint32_t dst = sb + toff + row * 128 + ((c16 ^ (row & 7)) << 4);
            cpasync16(dst, (const void*)(src + kb + c16 * 8));
        }
        CP_COMMIT();
    };

    fill(0);

    int la = lane & 15, lh = lane >> 4;

    for (int i = 0; i < NKT; i++) {
        uint32_t sb = smem0 + (i & 1) * STAGE_BYTES;
        if (i + 1 < NKT) { fill(i + 1); CP_WAIT1(); } else { CP_WAIT0(); }
        __syncthreads();

#pragma unroll
        for (int kc = 0; kc < 4; kc++) {
            int c16 = kc * 2 + lh;
            uint32_t ah[4][4];
#pragma unroll
            for (int mt = 0; mt < 4; mt++)
                ldmx4(ah[mt], tile_addr(sb, wm * 64 + mt * 16 + la, c16));
#pragma unroll
            for (int hb = 0; hb < 2; hb++) {
                uint32_t bhf[2][4];
#pragma unroll
                for (int g = 0; g < 2; g++)
                    ldmx4(bhf[g], tile_addr(sb + 32768, wn * 64 + (hb * 2 + g) * 16 + la, c16));
#pragma unroll
                for (int mt = 0; mt < 4; mt++) {
#pragma unroll
                    for (int nt = 0; nt < 4; nt++) {
                        int g = nt >> 1, h = nt & 1;
                        mma16816(c[mt][hb * 4 + nt], ah[mt], bhf[g][h], bhf[g][2 + h]);
                    }
                }
            }
        }
        __syncthreads();   // all reads of this stage done before next fill overwrites
    }

    // ---- epilogue straight from registers ----
    int r0 = lane >> 2;
    int cp = (lane & 3) * 2;
#pragma unroll
    for (int nt = 0; nt < 8; nt++) {
        int col = n0 + wn * 64 + nt * 8 + cp;
        float2 bv = *(const float2*)&bias[col];
#pragma unroll
        for (int mt = 0; mt < 4; mt++) {
#pragma unroll
            for (int half = 0; half < 2; half++) {
                int row = m0 + wm * 64 + mt * 16 + r0 + half * 8;
                float v0 = c[mt][nt][2 * half]     + bv.x;
                float v1 = c[mt][nt][2 * half + 1] + bv.y;
                if (RESACT) {
                    __half2 xr = *(const __half2*)&xh[(size_t)row * 512 + col];
                    v0 = __half2float(xr.x) + silu_f(v0);
                    v1 = __half2float(xr.y) + silu_f(v1);
                }
                if (WF32) {
                    *(float2*)&yf[(size_t)row * NOUT + col] = make_float2(v0, v1);
                }
                if (WF16) {
                    __half2 hp;
                    hp.x = __float2half_rn(v0);
                    hp.y = __float2half_rn(v1);
                    *(__half2*)&yh[(size_t)row * 512 + col] = hp;
                }
            }
        }
    }
}

// ---------------------------------------------------------------------------
extern "C" void kernel_launch(void* const* d_in, const int* in_sizes, int n_in,
                              void* d_out, int out_size)
{
    const int*   chars    = (const int*)d_in[0];
    const float* emb_byte = (const float*)d_in[1];
    const float* htab     = (const float*)d_in[2];
    const float* Wq       = (const float*)d_in[3];
    const float* bq       = (const float*)d_in[4];
    const float* conv_w   = (const float*)d_in[5];
    const float* conv_b   = (const float*)d_in[6];
    const float* Win      = (const float*)d_in[7];
    const float* b_in     = (const float*)d_in[8];
    const float* Wg       = (const float*)d_in[9];
    const float* bg       = (const float*)d_in[10];
    const float* Wi       = (const float*)d_in[11];
    const float* bi       = (const float*)d_in[12];
    const float* Wo       = (const float*)d_in[13];
    const float* bo       = (const float*)d_in[14];
    const float* lng      = (const float*)d_in[15];
    const float* lnb      = (const float*)d_in[16];
    const float* mlp_w    = (const float*)d_in[17];
    const float* mlp_b    = (const float*)d_in[18];
    const float* Wout     = (const float*)d_in[19];
    const float* bout     = (const float*)d_in[20];
    float* out = (float*)d_out;

    void *p;
    cudaGetSymbolAddress(&p, g_h);   float* gh  = (float*)p;
    cudaGetSymbolAddress(&p, g_h2);  float* gh2 = (float*)p;
    cudaGetSymbolAddress(&p, g_xh);  __half* xh  = (__half*)p;
    cudaGetSymbolAddress(&p, g_x2h); __half* x2h = (__half*)p;
    cudaGetSymbolAddress(&p, g_wh);  __half* wh  = (__half*)p;

    static int attr_done = 0;
    if (!attr_done) {
        cudaFuncSetAttribute(k_mma<512,1,1,0>, cudaFuncAttributeMaxDynamicSharedMemorySize, SMEM_MM);
        cudaFuncSetAttribute(k_mma<256,0,0,1>, cudaFuncAttributeMaxDynamicSharedMemorySize, SMEM_MM);
        attr_done = 1;
    }

    // weight prep (fp16 transpose)
    k_prep_w<<<512 * 512 / 256, 256>>>(mlp_w,                 512, 0);
    k_prep_w<<<512 * 512 / 256, 256>>>(mlp_w + 512 * 512,     512, 1);
    k_prep_w<<<512 * 512 / 256, 256>>>(mlp_w + 2 * 512 * 512, 512, 2);
    k_prep_w<<<256 * 512 / 256, 256>>>(Wout,                  256, 3);

    k_hashfeat<<<BT / 8, 256>>>(chars, emb_byte, htab, Wq, bq);
    k_feat_win<<<BT / 32, 256>>>(chars, emb_byte, conv_w, conv_b, Win, b_in);
    k_gates<<<BT / 32, 256>>>(Wg, bg, Wi, bi);
    k_scan<<<BDIM * SSDIM, 256>>>();
    k_wo<<<BT / 32, 256>>>(Wo, bo);
    k_ln<<<BT, 128>>>(lng, lnb);

    dim3 g512(4, BT / 256), g256(2, BT / 256);
    // L1: x = xh -> y1 = x + silu(x@W0+b) -> x2h (fp16 only)
    k_mma<512,1,1,0><<<g512, 256, SMEM_MM>>>(xh,
        wh + 0 * (size_t)512 * 512, mlp_b, 0, x2h);
    // L2: x2h -> xh
    k_mma<512,1,1,0><<<g512, 256, SMEM_MM>>>(x2h,
        wh + 1 * (size_t)512 * 512, mlp_b + 512, 0, xh);
    // L3: xh -> x2h
    k_mma<512,1,1,0><<<g512, 256, SMEM_MM>>>(xh,
        wh + 2 * (size_t)512 * 512, mlp_b + 1024, 0, x2h);
    // Wout: x2h -> out f32 [65536,256]
    k_mma<256,0,0,1><<<g256, 256, SMEM_MM>>>(x2h,
        wh + 3 * (size_t)512 * 512, bout, out, 0);
}

// round 13
// speedup vs baseline: 2.7692x; 1.0859x over previous
#include <cuda_runtime.h>
#include <cuda_fp16.h>
#include <math.h>
#include <stdint.h>

#define BDIM 8
#define TDIM 8192
#define BT (BDIM*TDIM)
#define HDIM 512
#define SSDIM 32

typedef unsigned long long u64;

// ---------------- scratch (device globals; no allocations allowed) ----------
__device__ float g_hf[BT*64];
__device__ float g_h[BT*HDIM];
__device__ float g_h2[BT*HDIM];
__device__ float g_gates[BDIM*SSDIM*TDIM];
__device__ float g_drive[BDIM*SSDIM*TDIM];
__device__ float g_states[BDIM*SSDIM*TDIM];
// fp16 activations (ping/pong)
__device__ __half g_xh[(size_t)BT*512];
__device__ __half g_x2h[(size_t)BT*512];
// fp16 features padded to 192 cols (132 real + 60 zero)
__device__ __half g_feat[(size_t)BT*192];
// fp16 transposed weights
__device__ __half g_wh[4][512*512];     // MLP x3 + Wout
__device__ __half g_wf[512*192];        // Win transposed+padded

__device__ __forceinline__ float silu_f(float x) { return x / (1.f + __expf(-x)); }

__device__ __forceinline__ u64 pack2(float x) {
    u64 r; asm("mov.b64 %0, {%1, %1};" : "=l"(r) : "f"(x)); return r;
}
__device__ __forceinline__ void ffma2(u64& d, u64 a, u64 b) {
    asm("fma.rn.f32x2 %0, %1, %2, %3;" : "=l"(d) : "l"(a), "l"(b), "l"(d));
}
__device__ __forceinline__ float lo32(u64 v) { return __uint_as_float((unsigned)v); }
__device__ __forceinline__ float hi32(u64 v) { return __uint_as_float((unsigned)(v >> 32)); }

// ---------------- mma.sync / async helpers (arch-agnostic, sm_80+) ----------
__device__ __forceinline__ uint32_t smem_u32(const void* p) {
    uint32_t a;
    asm("{ .reg .u64 t; cvta.to.shared.u64 t, %1; cvt.u32.u64 %0, t; }" : "=r"(a) : "l"(p));
    return a;
}
#define CP_COMMIT()      asm volatile("cp.async.commit_group;" ::: "memory")
#define CP_WAIT1()       asm volatile("cp.async.wait_group 1;" ::: "memory")
#define CP_WAIT0()       asm volatile("cp.async.wait_group 0;" ::: "memory")

__device__ __forceinline__ void cpasync16(uint32_t dst, const void* src) {
    asm volatile("cp.async.cg.shared.global [%0], [%1], 16;" :: "r"(dst), "l"(src));
}
__device__ __forceinline__ void ldmx4(uint32_t* r, uint32_t addr) {
    asm volatile("ldmatrix.sync.aligned.m8n8.x4.shared.b16 {%0,%1,%2,%3}, [%4];"
        : "=r"(r[0]), "=r"(r[1]), "=r"(r[2]), "=r"(r[3]) : "r"(addr));
}
__device__ __forceinline__ void mma16816(float* c, const uint32_t* a,
                                         uint32_t b0, uint32_t b1) {
    asm volatile("mma.sync.aligned.m16n8k16.row.col.f32.f16.f16.f32 "
        "{%0,%1,%2,%3}, {%4,%5,%6,%7}, {%8,%9}, {%0,%1,%2,%3};"
        : "+f"(c[0]), "+f"(c[1]), "+f"(c[2]), "+f"(c[3])
        : "r"(a[0]), "r"(a[1]), "r"(a[2]), "r"(a[3]), "r"(b0), "r"(b1));
}
// 16B-granular XOR swizzle within a 128B row (conflict-free ldmatrix)
__device__ __forceinline__ uint32_t tile_addr(uint32_t tbase, int row, int c16) {
    return tbase + row * 128 + ((c16 ^ (row & 7)) << 4);
}

// ---------------------------------------------------------------------------
// K1: rolling hashes + scale attention -> g_hf (verified)
// ---------------------------------------------------------------------------
__global__ void __launch_bounds__(256) k_hashfeat(
    const int* __restrict__ chars, const float* __restrict__ emb_byte,
    const float* __restrict__ htab, const float* __restrict__ Wq,
    const float* __restrict__ bq)
{
    int gw = (blockIdx.x * blockDim.x + threadIdx.x) >> 5;
    if (gw >= BT) return;
    int lane = threadIdx.x & 31;
    int wip  = threadIdx.x >> 5;
    int b = gw / TDIM, t = gw % TDIM;
    const int* cb = chars + b * TDIM;

    int myc = (lane < 16 && t >= lane) ? cb[t - lane] : 0;

    int acc0 = 0, acc1 = 0, acc2 = 0, acc3 = 0;
    int p = 1;
#pragma unroll
    for (int j = 0; j < 16; j++) {
        int cj = __shfl_sync(0xffffffffu, myc, j);
        int term = cj * p;
        if (j < 2) acc0 += term;
        if (j < 4) acc1 += term;
        if (j < 8) acc2 += term;
        acc3 += term;
        p = (p * 257) & 4095;
    }
    int h0 = acc0 & 4095, h1 = acc1 & 4095, h2 = acc2 & 4095, h3 = acc3 & 4095;

    int c0 = lane * 2;
    int ch0 = __shfl_sync(0xffffffffu, myc, 0);
    float2 be = *(const float2*)&emb_byte[ch0 * 64 + c0];

    __shared__ float s_be[8][64];
    s_be[wip][c0]     = be.x;
    s_be[wip][c0 + 1] = be.y;
    __syncwarp();

    float q0 = bq[c0], q1 = bq[c0 + 1];
#pragma unroll 8
    for (int k = 0; k < 64; k++) {
        float bk = s_be[wip][k];
        float2 wv = *(const float2*)&Wq[k * 64 + c0];
        q0 = fmaf(bk, wv.x, q0);
        q1 = fmaf(bk, wv.y, q1);
    }

    float2 se0 = *(const float2*)&htab[(size_t)(0 * 4096 + h0) * 64 + c0];
    float2 se1 = *(const float2*)&htab[(size_t)(1 * 4096 + h1) * 64 + c0];
    float2 se2 = *(const float2*)&htab[(size_t)(2 * 4096 + h2) * 64 + c0];
    float2 se3 = *(const float2*)&htab[(size_t)(3 * 4096 + h3) * 64 + c0];

    float s0 = q0 * se0.x + q1 * se0.y;
    float s1 = q0 * se1.x + q1 * se1.y;
    float s2 = q0 * se2.x + q1 * se2.y;
    float s3 = q0 * se3.x + q1 * se3.y;
#pragma unroll
    for (int off = 16; off; off >>= 1) {
        s0 += __shfl_xor_sync(0xffffffffu, s0, off);
        s1 += __shfl_xor_sync(0xffffffffu, s1, off);
        s2 += __shfl_xor_sync(0xffffffffu, s2, off);
        s3 += __shfl_xor_sync(0xffffffffu, s3, off);
    }
    s0 *= 0.125f; s1 *= 0.125f; s2 *= 0.125f; s3 *= 0.125f;
    float m = fmaxf(fmaxf(s0, s1), fmaxf(s2, s3));
    float e0 = __expf(s0 - m), e1 = __expf(s1 - m), e2 = __expf(s2 - m), e3 = __expf(s3 - m);
    float inv = 1.f / (e0 + e1 + e2 + e3);
    float o0 = (e0 * se0.x + e1 * se1.x + e2 * se2.x + e3 * se3.x) * inv;
    float o1 = (e0 * se0.y + e1 * se1.y + e2 * se2.y + e3 * se3.y) * inv;
    *(float2*)&g_hf[(size_t)gw * 64 + c0] = make_float2(o0, o1);
}

// ---------------------------------------------------------------------------
// K2: features only -> fp16 g_feat [BT, 192] (132 real cols + zero pad)
// block = 32 tokens, 256 threads
// ---------------------------------------------------------------------------
__global__ void __launch_bounds__(256) k_feat(
    const int* __restrict__ chars, const float* __restrict__ emb_byte,
    const float* __restrict__ conv_w, const float* __restrict__ conv_b)
{
    __shared__ int sch[32];
    int blk = blockIdx.x;
    int b = blk / (TDIM / 32);
    int tBase = (blk % (TDIM / 32)) * 32;
    int tid = threadIdx.x;
    const int* cb = chars + b * TDIM;

    if (tid < 32) sch[tid] = cb[tBase + tid];
    __syncthreads();

    // byte emb -> cols 0..63
    for (int idx = tid; idx < 32 * 64; idx += 256) {
        int tok = idx >> 6, c = idx & 63;
        g_feat[(size_t)(b * TDIM + tBase + tok) * 192 + c] =
            __float2half_rn(emb_byte[sch[tok] * 64 + c]);
    }
    // causal conv + silu -> cols 64..127
    for (int idx = tid; idx < 32 * 64; idx += 256) {
        int tok = idx >> 6, c = idx & 63;
        int t = tBase + tok;
        float acc = conv_b[c];
#pragma unroll
        for (int k = 0; k < 4; k++) {
            int tt = t - 3 + k;
            float v = (tt >= 0) ? g_hf[(size_t)(b * TDIM + tt) * 64 + c] : 0.f;
            acc = fmaf(conv_w[c * 4 + k], v, acc);
        }
        g_feat[(size_t)(b * TDIM + t) * 192 + 64 + c] = __float2half_rn(silu_f(acc));
    }
    // match feats (cols 128..131) + zero pad (cols 132..191)
    for (int idx = tid; idx < 32 * 64; idx += 256) {
        int tok = idx >> 6, m = idx & 63;
        int t = tBase + tok;
        float v = 0.f;
        if (m < 4) {
            int k = 1 << m;
            if (t >= k) v = (cb[t] == cb[t - k]) ? 1.f : 0.f;
        }
        g_feat[(size_t)(b * TDIM + t) * 192 + 128 + m] = __float2half_rn(v);
    }
}

// ---------------------------------------------------------------------------
// K3: gates/drive (verified; FFMA2, reads f32 g_h)
// ---------------------------------------------------------------------------
__global__ void __launch_bounds__(256) k_gates(
    const float* __restrict__ Wg, const float* __restrict__ bg,
    const float* __restrict__ Wi, const float* __restrict__ bi)
{
    __shared__ u64 smbuf[4096];
    float (*sxt)[32] = reinterpret_cast<float(*)[32]>(smbuf);

    int tid = threadIdx.x;
    int col = tid & 63;
    int ks  = tid >> 6;
    int n0 = blockIdx.x * 32;
    int b = n0 / TDIM, t0 = n0 % TDIM;

    u64 acc[16];
#pragma unroll
    for (int i = 0; i < 16; i++) acc[i] = 0ull;

    const float* Wsel = (col < 32) ? Wg : Wi;
    int wcol = col & 31;

    for (int kb = 0; kb < 512; kb += 128) {
        __syncthreads();
        for (int i = tid; i < 32 * 32; i += 256) {
            int tok = i & 31;
            int k4 = (i >> 5) << 2;
            float4 v = *(const float4*)&g_h[(size_t)(n0 + tok) * 512 + kb + k4];
            sxt[k4][tok] = v.x; sxt[k4 + 1][tok] = v.y;
            sxt[k4 + 2][tok] = v.z; sxt[k4 + 3][tok] = v.w;
        }
        __syncthreads();
        int kBase = ks * 32;
#pragma unroll 1
        for (int k = 0; k < 32; k++) {
            u64 wv = pack2(Wsel[(size_t)(kb + kBase + k) * 32 + wcol]);
            const ulonglong2* xr = (const ulonglong2*)&sxt[kBase + k][0];
#pragma unroll
            for (int q = 0; q < 8; q++) {
                ulonglong2 x2 = xr[q];
                ffma2(acc[2 * q],     x2.x, wv);
                ffma2(acc[2 * q + 1], x2.y, wv);
            }
        }
    }
    __syncthreads();
#pragma unroll
    for (int p = 0; p < 16; p++) smbuf[((size_t)ks * 64 + col) * 16 + p] = acc[p];
    __syncthreads();
    if (ks == 0 && col < 32) {
        int j = col;
        float bgv = bg[j], biv = bi[j];
        float* gout = g_gates + (size_t)(b * SSDIM + j) * TDIM + t0;
        float* dout = g_drive + (size_t)(b * SSDIM + j) * TDIM + t0;
#pragma unroll
        for (int p = 0; p < 16; p++) {
            float ag0 = bgv, ag1 = bgv, ai0 = biv, ai1 = biv;
#pragma unroll
            for (int s = 0; s < 4; s++) {
                u64 vg = smbuf[((size_t)s * 64 + j) * 16 + p];
                u64 vi = smbuf[((size_t)s * 64 + 32 + j) * 16 + p];
                ag0 += lo32(vg); ag1 += hi32(vg);
                ai0 += lo32(vi); ai1 += hi32(vi);
            }
            float g0 = 1.f / (1.f + __expf(-ag0));
            float g1 = 1.f / (1.f + __expf(-ag1));
            gout[2 * p]     = g0;
            gout[2 * p + 1] = g1;
            dout[2 * p]     = (1.f - g0) * ai0;
            dout[2 * p + 1] = (1.f - g1) * ai1;
        }
    }
}

// ---------------------------------------------------------------------------
// K4: chunk-parallel TinyScan (verified)
// ---------------------------------------------------------------------------
__global__ void __launch_bounds__(256) k_scan()
{
    int bs = blockIdx.x;
    int j = threadIdx.x;
    const float* ga = g_gates + (size_t)bs * TDIM + j * 32;
    const float* dr = g_drive + (size_t)bs * TDIM + j * 32;
    float a[32], bb[32];
#pragma unroll
    for (int i = 0; i < 32; i++) {
        a[i]  = fmaxf(ga[i], 1e-6f);
        bb[i] = dr[i];
    }
    float cumA = 1.f, cumWB = 0.f;
#pragma unroll
    for (int i = 0; i < 32; i++) {
        cumA *= a[i];
        float inv = 1.f / fmaxf(cumA, 1e-8f);
        cumWB = fmaf(bb[i], inv, cumWB);
    }
    __shared__ float sA[256], sB[256];
    sA[j] = cumA;
    sB[j] = cumA * cumWB;
    __syncthreads();
    for (int d = 1; d < 256; d <<= 1) {
        float a2 = sA[j], b2 = sB[j], a1 = 0.f, b1 = 0.f;
        if (j >= d) { a1 = sA[j - d]; b1 = sB[j - d]; }
        __syncthreads();
        if (j >= d) { sA[j] = a2 * a1; sB[j] = fmaf(a2, b1, b2); }
        __syncthreads();
    }
    float hc = (j == 0) ? 0.f : sB[j - 1];
    cumA = 1.f; cumWB = 0.f;
    float* st = g_states + (size_t)bs * TDIM + j * 32;
#pragma unroll
    for (int i = 0; i < 32; i++) {
        cumA *= a[i];
        float inv = 1.f / fmaxf(cumA, 1e-8f);
        cumWB = fmaf(bb[i], inv, cumWB);
        st[i] = cumA * (hc + cumWB);
    }
}

// ---------------------------------------------------------------------------
// K5a: y = h + states@Wo + bo (verified, FFMA2)
// ---------------------------------------------------------------------------
__global__ void __launch_bounds__(256) k_wo(
    const float* __restrict__ Wo, const float* __restrict__ bo)
{
    __shared__ float sxt[32][32];
    int tid = threadIdx.x;
    int n0 = blockIdx.x * 32;
    int b = n0 / TDIM, t0 = n0 % TDIM;

    for (int i = tid; i < 32 * 8; i += 256) {
        int s = i >> 3, t4 = (i & 7) * 4;
        float4 v = *(const float4*)&g_states[(size_t)(b * SSDIM + s) * TDIM + t0 + t4];
        *(float4*)&sxt[s][t4] = v;
    }
    __syncthreads();

    u64 acc[16][2];
#pragma unroll
    for (int i = 0; i < 16; i++) { acc[i][0] = 0ull; acc[i][1] = 0ull; }

#pragma unroll 1
    for (int k4 = 0; k4 < 32; k4 += 4) {
        u64 wp[4][2];
#pragma unroll
        for (int j = 0; j < 4; j++) {
            wp[j][0] = pack2(Wo[(size_t)(k4 + j) * 512 + tid]);
            wp[j][1] = pack2(Wo[(size_t)(k4 + j) * 512 + tid + 256]);
        }
#pragma unroll
        for (int j = 0; j < 4; j++) {
            const ulonglong2* xr = (const ulonglong2*)&sxt[k4 + j][0];
#pragma unroll
            for (int q = 0; q < 8; q++) {
                ulonglong2 x2 = xr[q];
                ffma2(acc[2 * q][0],     x2.x, wp[j][0]);
                ffma2(acc[2 * q][1],     x2.x, wp[j][1]);
                ffma2(acc[2 * q + 1][0], x2.y, wp[j][0]);
                ffma2(acc[2 * q + 1][1], x2.y, wp[j][1]);
            }
        }
    }
#pragma unroll
    for (int cc = 0; cc < 2; cc++) {
        int col = tid + cc * 256;
        float bv = bo[col];
#pragma unroll
        for (int p = 0; p < 16; p++) {
            size_t r0 = (size_t)(n0 + 2 * p) * 512 + col;
            g_h2[r0]       = lo32(acc[p][cc]) + bv + g_h[r0];
            g_h2[r0 + 512] = hi32(acc[p][cc]) + bv + g_h[r0 + 512];
        }
    }
}

// ---------------------------------------------------------------------------
// K5b: LayerNorm + single-fp16 activation write for the tensor path
// ---------------------------------------------------------------------------
__global__ void __launch_bounds__(128) k_ln(
    const float* __restrict__ lng, const float* __restrict__ lnb)
{
    int n = blockIdx.x;
    int tid = threadIdx.x;
    int c = tid * 4;
    float4 y = *(const float4*)&g_h2[(size_t)n * 512 + c];
    float lsum = y.x + y.y + y.z + y.w;
    float lsq  = y.x * y.x + y.y * y.y + y.z * y.z + y.w * y.w;
#pragma unroll
    for (int off = 16; off; off >>= 1) {
        lsum += __shfl_xor_sync(0xffffffffu, lsum, off);
        lsq  += __shfl_xor_sync(0xffffffffu, lsq,  off);
    }
    __shared__ float red[4][2];
    int wip = tid >> 5, lane = tid & 31;
    if (lane == 0) { red[wip][0] = lsum; red[wip][1] = lsq; }
    __syncthreads();
    lsum = red[0][0] + red[1][0] + red[2][0] + red[3][0];
    lsq  = red[0][1] + red[1][1] + red[2][1] + red[3][1];
    float mu = lsum * (1.f / 512.f);
    float var = lsq * (1.f / 512.f) - mu * mu;
    float rstd = rsqrtf(var + 1e-5f);
    float4 g4 = *(const float4*)&lng[c];
    float4 b4 = *(const float4*)&lnb[c];
    float4 o;
    o.x = (y.x - mu) * rstd * g4.x + b4.x;
    o.y = (y.y - mu) * rstd * g4.y + b4.y;
    o.z = (y.z - mu) * rstd * g4.z + b4.z;
    o.w = (y.w - mu) * rstd * g4.w + b4.w;
    __half hh[4];
    hh[0] = __float2half_rn(o.x);
    hh[1] = __float2half_rn(o.y);
    hh[2] = __float2half_rn(o.z);
    hh[3] = __float2half_rn(o.w);
    size_t base = (size_t)n * 512 + c;
    *(__half2*)&g_xh[base]     = *(__half2*)&hh[0];
    *(__half2*)&g_xh[base + 2] = *(__half2*)&hh[2];
}

// ---------------------------------------------------------------------------
// Weight prep: W[k][N] f32 -> transposed fp16 [n*512+k] (MLP/Wout)
// ---------------------------------------------------------------------------
__global__ void __launch_bounds__(256) k_prep_w(
    const float* __restrict__ W, int N, int layer)
{
    int idx = blockIdx.x * 256 + threadIdx.x;
    int k = idx & 511;
    int n = idx >> 9;
    if (n >= N) return;
    float w = W[(size_t)k * N + n];
    g_wh[layer][(size_t)n * 512 + k] = __float2half_rn(w);
}

// Win prep: Win[k][512] f32 (k<132) -> transposed fp16 [n*192+k], zero pad
__global__ void __launch_bounds__(256) k_prep_wf(const float* __restrict__ Win)
{
    int idx = blockIdx.x * 256 + threadIdx.x;   // over 512*192
    int k = idx % 192;
    int n = idx / 192;
    if (n >= 512) return;
    float w = (k < 132) ? Win[(size_t)k * 512 + n] : 0.f;
    g_wf[(size_t)n * 192 + k] = __float2half_rn(w);
}

// ---------------------------------------------------------------------------
// fp16 1-term mma.sync GEMM: D = X16@W16' (fp32 accum)
// CTA: 256xNc128xK(KDIM); 8 warps 4x2, warp tile 64x64.
// 2-stage cp.async double buffer, KT=64 (48KB/stage).
// grid: blockIdx.x = n (fastest) -> A served from L2 across the n-CTAs.
// EPI: 0 = v+bias -> yf f32 (stride NOUT)          [Wout]
//      1 = fp16resid + silu(v+bias) -> yh fp16     [MLP layers]
//      2 = silu(v+bias) -> yf f32 (stride NOUT)    [Win]
// ---------------------------------------------------------------------------
#define STAGE_BYTES 49152
#define SMEM_MM (2 * STAGE_BYTES)

template<int KDIM, int NKT, int NOUT, int EPI>
__global__ void __launch_bounds__(256) k_mma(
    const __half* __restrict__ xh,
    const __half* __restrict__ wh,
    const float* __restrict__ bias,
    float* __restrict__ yf, __half* __restrict__ yh)
{
    extern __shared__ char dsm[];
    uint32_t smem0 = smem_u32(dsm);
    int tid = threadIdx.x;
    int wid = tid >> 5, lane = tid & 31;
    int wm = wid >> 1, wn = wid & 1;          // warp tile: rows wm*64, cols wn*64
    int n0 = blockIdx.x * 128;
    int m0 = blockIdx.y * 256;

    float c[4][8][4];
#pragma unroll
    for (int i = 0; i < 4; i++)
#pragma unroll
        for (int j = 0; j < 8; j++)
#pragma unroll
            for (int e = 0; e < 4; e++) c[i][j][e] = 0.f;

    // stage fill: A 256 rows, B 128 rows; 3072 16B-chunks, 12/thread
    auto fill = [&](int kt) {
        int stage = kt & 1;
        int kb = kt * 64;
        uint32_t sb = smem0 + stage * STAGE_BYTES;
#pragma unroll
        for (int j = 0; j < 12; j++) {
            int cidx = tid + 256 * j;
            const __half* src;
            uint32_t toff;
            int idx;
            if (cidx < 2048) { idx = cidx;        toff = 0;     src = xh + (size_t)(m0 + (idx >> 3)) * KDIM; }
            else             { idx = cidx - 2048; toff = 32768; src = wh + (size_t)(n0 + (idx >> 3)) * KDIM; }
            int row = idx >> 3;
            int c16 = idx & 7;
            uint32_t dst = sb + toff + row * 128 + ((c16 ^ (row & 7)) << 4);
            cpasync16(dst, (const void*)(src + kb + c16 * 8));
        }
        CP_COMMIT();
    };

    fill(0);

    int la = lane & 15, lh = lane >> 4;

    for (int i = 0; i < NKT; i++) {
        uint32_t sb = smem0 + (i & 1) * STAGE_BYTES;
        if (i + 1 < NKT) { fill(i + 1); CP_WAIT1(); } else { CP_WAIT0(); }
        __syncthreads();

#pragma unroll
        for (int kc = 0; kc < 4; kc++) {
            int c16 = kc * 2 + lh;
            uint32_t ah[4][4];
#pragma unroll
            for (int mt = 0; mt < 4; mt++)
                ldmx4(ah[mt], tile_addr(sb, wm * 64 + mt * 16 + la, c16));
#pragma unroll
            for (int hb = 0; hb < 2; hb++) {
                uint32_t bhf[2][4];
#pragma unroll
                for (int g = 0; g < 2; g++)
                    ldmx4(bhf[g], tile_addr(sb + 32768, wn * 64 + (hb * 2 + g) * 16 + la, c16));
#pragma unroll
                for (int mt = 0; mt < 4; mt++) {
#pragma unroll
                    for (int nt = 0; nt < 4; nt++) {
                        int g = nt >> 1, h = nt & 1;
                        mma16816(c[mt][hb * 4 + nt], ah[mt], bhf[g][h], bhf[g][2 + h]);
                    }
                }
            }
        }
        __syncthreads();   // all reads of this stage done before next fill overwrites
    }

    // ---- epilogue straight from registers ----
    int r0 = lane >> 2;
    int cp = (lane & 3) * 2;
#pragma unroll
    for (int nt = 0; nt < 8; nt++) {
        int col = n0 + wn * 64 + nt * 8 + cp;
        float2 bv = *(const float2*)&bias[col];
#pragma unroll
        for (int mt = 0; mt < 4; mt++) {
#pragma unroll
            for (int half = 0; half < 2; half++) {
                int row = m0 + wm * 64 + mt * 16 + r0 + half * 8;
                float v0 = c[mt][nt][2 * half]     + bv.x;
                float v1 = c[mt][nt][2 * half + 1] + bv.y;
                if (EPI == 1) {
                    __half2 xr = *(const __half2*)&xh[(size_t)row * KDIM + col];
                    v0 = __half2float(xr.x) + silu_f(v0);
                    v1 = __half2float(xr.y) + silu_f(v1);
                    __half2 hp;
                    hp.x = __float2half_rn(v0);
                    hp.y = __float2half_rn(v1);
                    *(__half2*)&yh[(size_t)row * 512 + col] = hp;
                } else if (EPI == 2) {
                    v0 = silu_f(v0);
                    v1 = silu_f(v1);
                    *(float2*)&yf[(size_t)row * NOUT + col] = make_float2(v0, v1);
                } else {
                    *(float2*)&yf[(size_t)row * NOUT + col] = make_float2(v0, v1);
                }
            }
        }
    }
}

// ---------------------------------------------------------------------------
extern "C" void kernel_launch(void* const* d_in, const int* in_sizes, int n_in,
                              void* d_out, int out_size)
{
    const int*   chars    = (const int*)d_in[0];
    const float* emb_byte = (const float*)d_in[1];
    const float* htab     = (const float*)d_in[2];
    const float* Wq       = (const float*)d_in[3];
    const float* bq       = (const float*)d_in[4];
    const float* conv_w   = (const float*)d_in[5];
    const float* conv_b   = (const float*)d_in[6];
    const float* Win      = (const float*)d_in[7];
    const float* b_in     = (const float*)d_in[8];
    const float* Wg       = (const float*)d_in[9];
    const float* bg       = (const float*)d_in[10];
    const float* Wi       = (const float*)d_in[11];
    const float* bi       = (const float*)d_in[12];
    const float* Wo       = (const float*)d_in[13];
    const float* bo       = (const float*)d_in[14];
    const float* lng      = (const float*)d_in[15];
    const float* lnb      = (const float*)d_in[16];
    const float* mlp_w    = (const float*)d_in[17];
    const float* mlp_b    = (const float*)d_in[18];
    const float* Wout     = (const float*)d_in[19];
    const float* bout     = (const float*)d_in[20];
    float* out = (float*)d_out;

    void *p;
    cudaGetSymbolAddress(&p, g_h);    float* gh  = (float*)p;
    cudaGetSymbolAddress(&p, g_xh);   __half* xh  = (__half*)p;
    cudaGetSymbolAddress(&p, g_x2h);  __half* x2h = (__half*)p;
    cudaGetSymbolAddress(&p, g_wh);   __half* wh  = (__half*)p;
    cudaGetSymbolAddress(&p, g_feat); __half* feat = (__half*)p;
    cudaGetSymbolAddress(&p, g_wf);   __half* wf  = (__half*)p;

    static int attr_done = 0;
    if (!attr_done) {
        cudaFuncSetAttribute(k_mma<512,8,512,1>, cudaFuncAttributeMaxDynamicSharedMemorySize, SMEM_MM);
        cudaFuncSetAttribute(k_mma<512,8,256,0>, cudaFuncAttributeMaxDynamicSharedMemorySize, SMEM_MM);
        cudaFuncSetAttribute(k_mma<192,3,512,2>, cudaFuncAttributeMaxDynamicSharedMemorySize, SMEM_MM);
        attr_done = 1;
    }

    // weight prep (fp16 transpose)
    k_prep_w<<<512 * 512 / 256, 256>>>(mlp_w,                 512, 0);
    k_prep_w<<<512 * 512 / 256, 256>>>(mlp_w + 512 * 512,     512, 1);
    k_prep_w<<<512 * 512 / 256, 256>>>(mlp_w + 2 * 512 * 512, 512, 2);
    k_prep_w<<<256 * 512 / 256, 256>>>(Wout,                  256, 3);
    k_prep_wf<<<512 * 192 / 256, 256>>>(Win);

    k_hashfeat<<<BT / 8, 256>>>(chars, emb_byte, htab, Wq, bq);
    k_feat<<<BT / 32, 256>>>(chars, emb_byte, conv_w, conv_b);

    dim3 gwin(4, BT / 256);
    // Win: feat[BT,192] @ Win -> silu -> f32 g_h
    k_mma<192,3,512,2><<<gwin, 256, SMEM_MM>>>(feat, wf, b_in, gh, 0);

    k_gates<<<BT / 32, 256>>>(Wg, bg, Wi, bi);
    k_scan<<<BDIM * SSDIM, 256>>>();
    k_wo<<<BT / 32, 256>>>(Wo, bo);
    k_ln<<<BT, 128>>>(lng, lnb);

    dim3 g512(4, BT / 256), g256(2, BT / 256);
    // L1: x = xh -> y1 = x + silu(x@W0+b) -> x2h (fp16 only)
    k_mma<512,8,512,1><<<g512, 256, SMEM_MM>>>(xh,
        wh + 0 * (size_t)512 * 512, mlp_b, 0, x2h);
    // L2: x2h -> xh
    k_mma<512,8,512,1><<<g512, 256, SMEM_MM>>>(x2h,
        wh + 1 * (size_t)512 * 512, mlp_b + 512, 0, xh);
    // L3: xh -> x2h
    k_mma<512,8,512,1><<<g512, 256, SMEM_MM>>>(xh,
        wh + 2 * (size_t)512 * 512, mlp_b + 1024, 0, x2h);
    // Wout: x2h -> out f32 [65536,256]
    k_mma<512,8,256,0><<<g256, 256, SMEM_MM>>>(x2h,
        wh + 3 * (size_t)512 * 512, bout, out, 0);
}

// round 15
// speedup vs baseline: 3.9572x; 1.4290x over previous
#include <cuda_runtime.h>
#include <cuda_fp16.h>
#include <math.h>
#include <stdint.h>

#define BDIM 8
#define TDIM 8192
#define BT (BDIM*TDIM)
#define HDIM 512
#define SSDIM 32

typedef unsigned long long u64;

// ---------------- scratch (device globals; no allocations allowed) ----------
__device__ float g_hf[BT*64];
__device__ float g_h[BT*HDIM];              // f32 h (post-Win silu)
__device__ float g_gates[BDIM*SSDIM*TDIM];
__device__ float g_drive[BDIM*SSDIM*TDIM];
__device__ float g_states[BDIM*SSDIM*TDIM];
// fp16 activations
__device__ __half g_hh[(size_t)BT*512];     // fp16 h (gates GEMM input)
__device__ __half g_xh[(size_t)BT*512];     // ln output / MLP ping
__device__ __half g_x2h[(size_t)BT*512];    // MLP pong
__device__ __half g_feat[(size_t)BT*192];   // features padded to 192
// fp16 transposed weights
__device__ __half g_wh[4][512*512];         // MLP x3 + Wout
__device__ __half g_wf[512*192];            // Win transposed+padded
__device__ __half g_wgi[64*512];            // [Wg|Wi] interleaved cols

__device__ __forceinline__ float silu_f(float x) { return x / (1.f + __expf(-x)); }

__device__ __forceinline__ u64 pack2(float x) {
    u64 r; asm("mov.b64 %0, {%1, %1};" : "=l"(r) : "f"(x)); return r;
}
__device__ __forceinline__ void ffma2(u64& d, u64 a, u64 b) {
    asm("fma.rn.f32x2 %0, %1, %2, %3;" : "=l"(d) : "l"(a), "l"(b), "l"(d));
}
__device__ __forceinline__ float lo32(u64 v) { return __uint_as_float((unsigned)v); }
__device__ __forceinline__ float hi32(u64 v) { return __uint_as_float((unsigned)(v >> 32)); }

// ---------------- mma.sync / async helpers (arch-agnostic, sm_80+) ----------
__device__ __forceinline__ uint32_t smem_u32(const void* p) {
    uint32_t a;
    asm("{ .reg .u64 t; cvta.to.shared.u64 t, %1; cvt.u32.u64 %0, t; }" : "=r"(a) : "l"(p));
    return a;
}
#define CP_COMMIT()      asm volatile("cp.async.commit_group;" ::: "memory")
#define CP_WAIT1()       asm volatile("cp.async.wait_group 1;" ::: "memory")
#define CP_WAIT0()       asm volatile("cp.async.wait_group 0;" ::: "memory")

__device__ __forceinline__ void cpasync16(uint32_t dst, const void* src) {
    asm volatile("cp.async.cg.shared.global [%0], [%1], 16;" :: "r"(dst), "l"(src));
}
__device__ __forceinline__ void ldmx4(uint32_t* r, uint32_t addr) {
    asm volatile("ldmatrix.sync.aligned.m8n8.x4.shared.b16 {%0,%1,%2,%3}, [%4];"
        : "=r"(r[0]), "=r"(r[1]), "=r"(r[2]), "=r"(r[3]) : "r"(addr));
}
__device__ __forceinline__ void mma16816(float* c, const uint32_t* a,
                                         uint32_t b0, uint32_t b1) {
    asm volatile("mma.sync.aligned.m16n8k16.row.col.f32.f16.f16.f32 "
        "{%0,%1,%2,%3}, {%4,%5,%6,%7}, {%8,%9}, {%0,%1,%2,%3};"
        : "+f"(c[0]), "+f"(c[1]), "+f"(c[2]), "+f"(c[3])
        : "r"(a[0]), "r"(a[1]), "r"(a[2]), "r"(a[3]), "r"(b0), "r"(b1));
}
// 16B-granular XOR swizzle within a 128B row (conflict-free ldmatrix)
__device__ __forceinline__ uint32_t tile_addr(uint32_t tbase, int row, int c16) {
    return tbase + row * 128 + ((c16 ^ (row & 7)) << 4);
}

// ---------------------------------------------------------------------------
// K1: rolling hashes + scale attention -> g_hf (verified)
// ---------------------------------------------------------------------------
__global__ void __launch_bounds__(256) k_hashfeat(
    const int* __restrict__ chars, const float* __restrict__ emb_byte,
    const float* __restrict__ htab, const float* __restrict__ Wq,
    const float* __restrict__ bq)
{
    int gw = (blockIdx.x * blockDim.x + threadIdx.x) >> 5;
    if (gw >= BT) return;
    int lane = threadIdx.x & 31;
    int wip  = threadIdx.x >> 5;
    int b = gw / TDIM, t = gw % TDIM;
    const int* cb = chars + b * TDIM;

    int myc = (lane < 16 && t >= lane) ? cb[t - lane] : 0;

    int acc0 = 0, acc1 = 0, acc2 = 0, acc3 = 0;
    int p = 1;
#pragma unroll
    for (int j = 0; j < 16; j++) {
        int cj = __shfl_sync(0xffffffffu, myc, j);
        int term = cj * p;
        if (j < 2) acc0 += term;
        if (j < 4) acc1 += term;
        if (j < 8) acc2 += term;
        acc3 += term;
        p = (p * 257) & 4095;
    }
    int h0 = acc0 & 4095, h1 = acc1 & 4095, h2 = acc2 & 4095, h3 = acc3 & 4095;

    int c0 = lane * 2;
    int ch0 = __shfl_sync(0xffffffffu, myc, 0);
    float2 be = *(const float2*)&emb_byte[ch0 * 64 + c0];

    __shared__ float s_be[8][64];
    s_be[wip][c0]     = be.x;
    s_be[wip][c0 + 1] = be.y;
    __syncwarp();

    float q0 = bq[c0], q1 = bq[c0 + 1];
#pragma unroll 8
    for (int k = 0; k < 64; k++) {
        float bk = s_be[wip][k];
        float2 wv = *(const float2*)&Wq[k * 64 + c0];
        q0 = fmaf(bk, wv.x, q0);
        q1 = fmaf(bk, wv.y, q1);
    }

    float2 se0 = *(const float2*)&htab[(size_t)(0 * 4096 + h0) * 64 + c0];
    float2 se1 = *(const float2*)&htab[(size_t)(1 * 4096 + h1) * 64 + c0];
    float2 se2 = *(const float2*)&htab[(size_t)(2 * 4096 + h2) * 64 + c0];
    float2 se3 = *(const float2*)&htab[(size_t)(3 * 4096 + h3) * 64 + c0];

    float s0 = q0 * se0.x + q1 * se0.y;
    float s1 = q0 * se1.x + q1 * se1.y;
    float s2 = q0 * se2.x + q1 * se2.y;
    float s3 = q0 * se3.x + q1 * se3.y;
#pragma unroll
    for (int off = 16; off; off >>= 1) {
        s0 += __shfl_xor_sync(0xffffffffu, s0, off);
        s1 += __shfl_xor_sync(0xffffffffu, s1, off);
        s2 += __shfl_xor_sync(0xffffffffu, s2, off);
        s3 += __shfl_xor_sync(0xffffffffu, s3, off);
    }
    s0 *= 0.125f; s1 *= 0.125f; s2 *= 0.125f; s3 *= 0.125f;
    float m = fmaxf(fmaxf(s0, s1), fmaxf(s2, s3));
    float e0 = __expf(s0 - m), e1 = __expf(s1 - m), e2 = __expf(s2 - m), e3 = __expf(s3 - m);
    float inv = 1.f / (e0 + e1 + e2 + e3);
    float o0 = (e0 * se0.x + e1 * se1.x + e2 * se2.x + e3 * se3.x) * inv;
    float o1 = (e0 * se0.y + e1 * se1.y + e2 * se2.y + e3 * se3.y) * inv;
    *(float2*)&g_hf[(size_t)gw * 64 + c0] = make_float2(o0, o1);
}

// ---------------------------------------------------------------------------
// K2: features only -> fp16 g_feat [BT, 192] (132 real cols + zero pad)
// ---------------------------------------------------------------------------
__global__ void __launch_bounds__(256) k_feat(
    const int* __restrict__ chars, const float* __restrict__ emb_byte,
    const float* __restrict__ conv_w, const float* __restrict__ conv_b)
{
    __shared__ int sch[32];
    int blk = blockIdx.x;
    int b = blk / (TDIM / 32);
    int tBase = (blk % (TDIM / 32)) * 32;
    int tid = threadIdx.x;
    const int* cb = chars + b * TDIM;

    if (tid < 32) sch[tid] = cb[tBase + tid];
    __syncthreads();

    for (int idx = tid; idx < 32 * 64; idx += 256) {
        int tok = idx >> 6, c = idx & 63;
        g_feat[(size_t)(b * TDIM + tBase + tok) * 192 + c] =
            __float2half_rn(emb_byte[sch[tok] * 64 + c]);
    }
    for (int idx = tid; idx < 32 * 64; idx += 256) {
        int tok = idx >> 6, c = idx & 63;
        int t = tBase + tok;
        float acc = conv_b[c];
#pragma unroll
        for (int k = 0; k < 4; k++) {
            int tt = t - 3 + k;
            float v = (tt >= 0) ? g_hf[(size_t)(b * TDIM + tt) * 64 + c] : 0.f;
            acc = fmaf(conv_w[c * 4 + k], v, acc);
        }
        g_feat[(size_t)(b * TDIM + t) * 192 + 64 + c] = __float2half_rn(silu_f(acc));
    }
    for (int idx = tid; idx < 32 * 64; idx += 256) {
        int tok = idx >> 6, m = idx & 63;
        int t = tBase + tok;
        float v = 0.f;
        if (m < 4) {
            int k = 1 << m;
            if (t >= k) v = (cb[t] == cb[t - k]) ? 1.f : 0.f;
        }
        g_feat[(size_t)(b * TDIM + t) * 192 + 128 + m] = __float2half_rn(v);
    }
}

// ---------------------------------------------------------------------------
// K4: chunk-parallel TinyScan (verified)
// ---------------------------------------------------------------------------
__global__ void __launch_bounds__(256) k_scan()
{
    int bs = blockIdx.x;
    int j = threadIdx.x;
    const float* ga = g_gates + (size_t)bs * TDIM + j * 32;
    const float* dr = g_drive + (size_t)bs * TDIM + j * 32;
    float a[32], bb[32];
#pragma unroll
    for (int i = 0; i < 32; i++) {
        a[i]  = fmaxf(ga[i], 1e-6f);
        bb[i] = dr[i];
    }
    float cumA = 1.f, cumWB = 0.f;
#pragma unroll
    for (int i = 0; i < 32; i++) {
        cumA *= a[i];
        float inv = 1.f / fmaxf(cumA, 1e-8f);
        cumWB = fmaf(bb[i], inv, cumWB);
    }
    __shared__ float sA[256], sB[256];
    sA[j] = cumA;
    sB[j] = cumA * cumWB;
    __syncthreads();
    for (int d = 1; d < 256; d <<= 1) {
        float a2 = sA[j], b2 = sB[j], a1 = 0.f, b1 = 0.f;
        if (j >= d) { a1 = sA[j - d]; b1 = sB[j - d]; }
        __syncthreads();
        if (j >= d) { sA[j] = a2 * a1; sB[j] = fmaf(a2, b1, b2); }
        __syncthreads();
    }
    float hc = (j == 0) ? 0.f : sB[j - 1];
    cumA = 1.f; cumWB = 0.f;
    float* st = g_states + (size_t)bs * TDIM + j * 32;
#pragma unroll
    for (int i = 0; i < 32; i++) {
        cumA *= a[i];
        float inv = 1.f / fmaxf(cumA, 1e-8f);
        cumWB = fmaf(bb[i], inv, cumWB);
        st[i] = cumA * (hc + cumWB);
    }
}

// ---------------------------------------------------------------------------
// K5: fused y = h + states@Wo + bo, then LayerNorm, write fp16 g_xh.
// block = 32 tokens, 256 threads, dynamic smem: sxt[32][32] + sy[32][520]
// ---------------------------------------------------------------------------
#define WOLN_SMEM (32*32*4 + 32*520*4)
__global__ void __launch_bounds__(256) k_wo_ln(
    const float* __restrict__ Wo, const float* __restrict__ bo,
    const float* __restrict__ lng, const float* __restrict__ lnb)
{
    extern __shared__ float dyn[];
    float (*sxt)[32] = (float(*)[32])dyn;       // [32][32]
    float* sy = dyn + 32 * 32;                  // [32][520]
    int tid = threadIdx.x;
    int n0 = blockIdx.x * 32;
    int b = n0 / TDIM, t0 = n0 % TDIM;

    for (int i = tid; i < 32 * 8; i += 256) {
        int s = i >> 3, t4 = (i & 7) * 4;
        float4 v = *(const float4*)&g_states[(size_t)(b * SSDIM + s) * TDIM + t0 + t4];
        *(float4*)&sxt[s][t4] = v;
    }
    __syncthreads();

    u64 acc[16][2];
#pragma unroll
    for (int i = 0; i < 16; i++) { acc[i][0] = 0ull; acc[i][1] = 0ull; }

#pragma unroll 1
    for (int k4 = 0; k4 < 32; k4 += 4) {
        u64 wp[4][2];
#pragma unroll
        for (int j = 0; j < 4; j++) {
            wp[j][0] = pack2(Wo[(size_t)(k4 + j) * 512 + tid]);
            wp[j][1] = pack2(Wo[(size_t)(k4 + j) * 512 + tid + 256]);
        }
#pragma unroll
        for (int j = 0; j < 4; j++) {
            const ulonglong2* xr = (const ulonglong2*)&sxt[k4 + j][0];
#pragma unroll
            for (int q = 0; q < 8; q++) {
                ulonglong2 x2 = xr[q];
                ffma2(acc[2 * q][0],     x2.x, wp[j][0]);
                ffma2(acc[2 * q][1],     x2.x, wp[j][1]);
                ffma2(acc[2 * q + 1][0], x2.y, wp[j][0]);
                ffma2(acc[2 * q + 1][1], x2.y, wp[j][1]);
            }
        }
    }
#pragma unroll
    for (int cc = 0; cc < 2; cc++) {
        int col = tid + cc * 256;
        float bv = bo[col];
#pragma unroll
        for (int p = 0; p < 16; p++) {
            size_t r0 = (size_t)(n0 + 2 * p) * 512 + col;
            sy[(2 * p) * 520 + col]     = lo32(acc[p][cc]) + bv + g_h[r0];
            sy[(2 * p + 1) * 520 + col] = hi32(acc[p][cc]) + bv + g_h[r0 + 512];
        }
    }
    __syncthreads();

    // LN: warp per 4 tokens
    int wid = tid >> 5, lane = tid & 31;
#pragma unroll
    for (int q = 0; q < 4; q++) {
        int tok = wid * 4 + q;
        const float* row = sy + tok * 520;
        float4 v[4];
        float lsum = 0.f, lsq = 0.f;
#pragma unroll
        for (int i = 0; i < 4; i++) {
            v[i] = *(const float4*)&row[lane * 16 + i * 4];
            lsum += v[i].x + v[i].y + v[i].z + v[i].w;
            lsq  += v[i].x * v[i].x + v[i].y * v[i].y + v[i].z * v[i].z + v[i].w * v[i].w;
        }
#pragma unroll
        for (int off = 16; off; off >>= 1) {
            lsum += __shfl_xor_sync(0xffffffffu, lsum, off);
            lsq  += __shfl_xor_sync(0xffffffffu, lsq,  off);
        }
        float mu = lsum * (1.f / 512.f);
        float var = lsq * (1.f / 512.f) - mu * mu;
        float rstd = rsqrtf(var + 1e-5f);
        __half hh[16];
#pragma unroll
        for (int i = 0; i < 4; i++) {
            float4 g4 = *(const float4*)&lng[lane * 16 + i * 4];
            float4 b4 = *(const float4*)&lnb[lane * 16 + i * 4];
            hh[i * 4 + 0] = __float2half_rn((v[i].x - mu) * rstd * g4.x + b4.x);
            hh[i * 4 + 1] = __float2half_rn((v[i].y - mu) * rstd * g4.y + b4.y);
            hh[i * 4 + 2] = __float2half_rn((v[i].z - mu) * rstd * g4.z + b4.z);
            hh[i * 4 + 3] = __float2half_rn((v[i].w - mu) * rstd * g4.w + b4.w);
        }
        *(int4*)&g_xh[(size_t)(n0 + tok) * 512 + lane * 16]     = *(int4*)&hh[0];
        *(int4*)&g_xh[(size_t)(n0 + tok) * 512 + lane * 16 + 8] = *(int4*)&hh[8];
    }
}

// ---------------------------------------------------------------------------
// Weight prep
// ---------------------------------------------------------------------------
__global__ void __launch_bounds__(256) k_prep_w(
    const float* __restrict__ W, int N, int layer)
{
    int idx = blockIdx.x * 256 + threadIdx.x;
    int k = idx & 511;
    int n = idx >> 9;
    if (n >= N) return;
    float w = W[(size_t)k * N + n];
    g_wh[layer][(size_t)n * 512 + k] = __float2half_rn(w);
}
__global__ void __launch_bounds__(256) k_prep_wf(const float* __restrict__ Win)
{
    int idx = blockIdx.x * 256 + threadIdx.x;
    int k = idx % 192;
    int n = idx / 192;
    if (n >= 512) return;
    float w = (k < 132) ? Win[(size_t)k * 512 + n] : 0.f;
    g_wf[(size_t)n * 192 + k] = __float2half_rn(w);
}
// [Wg|Wi] interleaved: col n even -> Wg[n/2], odd -> Wi[n/2]
__global__ void __launch_bounds__(256) k_prep_wgi(
    const float* __restrict__ Wg, const float* __restrict__ Wi)
{
    int idx = blockIdx.x * 256 + threadIdx.x;   // over 64*512
    int k = idx & 511;
    int n = idx >> 9;
    if (n >= 64) return;
    float w = (n & 1) ? Wi[(size_t)k * 32 + (n >> 1)] : Wg[(size_t)k * 32 + (n >> 1)];
    g_wgi[(size_t)n * 512 + k] = __float2half_rn(w);
}

// ---------------------------------------------------------------------------
// fp16 1-term mma.sync GEMM: D = X16@W16' (fp32 accum)
// CTA: 256xNc128xK(KDIM); 8 warps 4x2, warp tile 64x64; 2-stage cp.async.
// EPI: 0 = v+bias -> yf f32 (stride NOUT)                 [Wout]
//      1 = fp16resid + silu(v+bias) -> yh fp16            [MLP layers]
//      3 = silu(v+bias) -> yf f32 + yh fp16               [Win]
// ---------------------------------------------------------------------------
#define STAGE_BYTES 49152
#define SMEM_MM (2 * STAGE_BYTES)

template<int KDIM, int NKT, int NOUT, int EPI>
__global__ void __launch_bounds__(256) k_mma(
    const __half* __restrict__ xh,
    const __half* __restrict__ wh,
    const float* __restrict__ bias,
    float* __restrict__ yf, __half* __restrict__ yh)
{
    extern __shared__ char dsm[];
    uint32_t smem0 = smem_u32(dsm);
    int tid = threadIdx.x;
    int wid = tid >> 5, lane = tid & 31;
    int wm = wid >> 1, wn = wid & 1;
    int n0 = blockIdx.x * 128;
    int m0 = blockIdx.y * 256;

    float c[4][8][4];
#pragma unroll
    for (int i = 0; i < 4; i++)
#pragma unroll
        for (int j = 0; j < 8; j++)
#pragma unroll
            for (int e = 0; e < 4; e++) c[i][j][e] = 0.f;

    auto fill = [&](int kt) {
        int stage = kt & 1;
        int kb = kt * 64;
        uint32_t sb = smem0 + stage * STAGE_BYTES;
#pragma unroll
        for (int j = 0; j < 12; j++) {
            int cidx = tid + 256 * j;
            const __half* src;
            uint32_t toff;
            int idx;
            if (cidx < 2048) { idx = cidx;        toff = 0;     src = xh + (size_t)(m0 + (idx >> 3)) * KDIM; }
            else             { idx = cidx - 2048; toff = 32768; src = wh + (size_t)(n0 + (idx >> 3)) * KDIM; }
            int row = idx >> 3;
            int c16 = idx & 7;
            uint32_t dst = sb + toff + row * 128 + ((c16 ^ (row & 7)) << 4);
            cpasync16(dst, (const void*)(src + kb + c16 * 8));
        }
        CP_COMMIT();
    };

    fill(0);

    int la = lane & 15, lh = lane >> 4;

    for (int i = 0; i < NKT; i++) {
        uint32_t sb = smem0 + (i & 1) * STAGE_BYTES;
        if (i + 1 < NKT) { fill(i + 1); CP_WAIT1(); } else { CP_WAIT0(); }
        __syncthreads();

#pragma unroll
        for (int kc = 0; kc < 4; kc++) {
            int c16 = kc * 2 + lh;
            uint32_t ah[4][4];
#pragma unroll
            for (int mt = 0; mt < 4; mt++)
                ldmx4(ah[mt], tile_addr(sb, wm * 64 + mt * 16 + la, c16));
#pragma unroll
            for (int hb = 0; hb < 2; hb++) {
                uint32_t bhf[2][4];
#pragma unroll
                for (int g = 0; g < 2; g++)
                    ldmx4(bhf[g], tile_addr(sb + 32768, wn * 64 + (hb * 2 + g) * 16 + la, c16));
#pragma unroll
                for (int mt = 0; mt < 4; mt++) {
#pragma unroll
                    for (int nt = 0; nt < 4; nt++) {
                        int g = nt >> 1, h = nt & 1;
                        mma16816(c[mt][hb * 4 + nt], ah[mt], bhf[g][h], bhf[g][2 + h]);
                    }
                }
            }
        }
        __syncthreads();
    }

    int r0 = lane >> 2;
    int cp = (lane & 3) * 2;
#pragma unroll
    for (int nt = 0; nt < 8; nt++) {
        int col = n0 + wn * 64 + nt * 8 + cp;
        float2 bv = *(const float2*)&bias[col];
#pragma unroll
        for (int mt = 0; mt < 4; mt++) {
#pragma unroll
            for (int half = 0; half < 2; half++) {
                int row = m0 + wm * 64 + mt * 16 + r0 + half * 8;
                float v0 = c[mt][nt][2 * half]     + bv.x;
                float v1 = c[mt][nt][2 * half + 1] + bv.y;
                if (EPI == 1) {
                    __half2 xr = *(const __half2*)&xh[(size_t)row * KDIM + col];
                    v0 = __half2float(xr.x) + silu_f(v0);
                    v1 = __half2float(xr.y) + silu_f(v1);
                    __half2 hp;
                    hp.x = __float2half_rn(v0);
                    hp.y = __float2half_rn(v1);
                    *(__half2*)&yh[(size_t)row * 512 + col] = hp;
                } else if (EPI == 3) {
                    v0 = silu_f(v0);
                    v1 = silu_f(v1);
                    *(float2*)&yf[(size_t)row * NOUT + col] = make_float2(v0, v1);
                    __half2 hp;
                    hp.x = __float2half_rn(v0);
                    hp.y = __float2half_rn(v1);
                    *(__half2*)&yh[(size_t)row * 512 + col] = hp;
                } else {
                    *(float2*)&yf[(size_t)row * NOUT + col] = make_float2(v0, v1);
                }
            }
        }
    }
}

// ---------------------------------------------------------------------------
// Gates MMA: hh[BT,512] @ wgi[64,512]' -> sigmoid/drive -> (B,S,T) layout
// CTA: 256 tok x 64 cols, 4 warps (wm=wid), warp 64x64. 2-stage cp.async.
// cols interleaved: even = Wg[s], odd = Wi[s], s = col/2.
// ---------------------------------------------------------------------------
#define GSTG (32768 + 8192)
#define SMEM_G (2 * GSTG)
__global__ void __launch_bounds__(128) k_mma_g(
    const __half* __restrict__ xh,
    const float* __restrict__ bg, const float* __restrict__ bi)
{
    extern __shared__ char dsm[];
    uint32_t smem0 = smem_u32(dsm);
    int tid = threadIdx.x;
    int wid = tid >> 5, lane = tid & 31;
    int m0 = blockIdx.x * 256;
    int b = m0 / TDIM, t0 = m0 % TDIM;

    float c[4][8][4];
#pragma unroll
    for (int i = 0; i < 4; i++)
#pragma unroll
        for (int j = 0; j < 8; j++)
#pragma unroll
            for (int e = 0; e < 4; e++) c[i][j][e] = 0.f;

    auto fill = [&](int kt) {
        int stage = kt & 1;
        int kb = kt * 64;
        uint32_t sb = smem0 + stage * GSTG;
#pragma unroll
        for (int j = 0; j < 20; j++) {
            int cidx = tid + 128 * j;
            const __half* src;
            uint32_t toff;
            int idx;
            if (cidx < 2048) { idx = cidx;        toff = 0;     src = xh + (size_t)(m0 + (idx >> 3)) * 512; }
            else             { idx = cidx - 2048; toff = 32768; src = g_wgi + (size_t)(idx >> 3) * 512; }
            int row = idx >> 3;
            int c16 = idx & 7;
            uint32_t dst = sb + toff + row * 128 + ((c16 ^ (row & 7)) << 4);
            cpasync16(dst, (const void*)(src + kb + c16 * 8));
        }
        CP_COMMIT();
    };

    fill(0);

    int la = lane & 15, lh = lane >> 4;

    for (int i = 0; i < 8; i++) {
        uint32_t sb = smem0 + (i & 1) * GSTG;
        if (i + 1 < 8) { fill(i + 1); CP_WAIT1(); } else { CP_WAIT0(); }
        __syncthreads();

#pragma unroll
        for (int kc = 0; kc < 4; kc++) {
            int c16 = kc * 2 + lh;
            uint32_t ah[4][4];
#pragma unroll
            for (int mt = 0; mt < 4; mt++)
                ldmx4(ah[mt], tile_addr(sb, wid * 64 + mt * 16 + la, c16));
            uint32_t bhf[4][4];
#pragma unroll
            for (int g = 0; g < 4; g++)
                ldmx4(bhf[g], tile_addr(sb + 32768, g * 16 + la, c16));
#pragma unroll
            for (int mt = 0; mt < 4; mt++) {
#pragma unroll
                for (int nt = 0; nt < 8; nt++) {
                    int g = nt >> 1, h = nt & 1;
                    mma16816(c[mt][nt], ah[mt], bhf[g][h], bhf[g][2 + h]);
                }
            }
        }
        __syncthreads();
    }

    int r0 = lane >> 2;
    int cp = (lane & 3) * 2;
#pragma unroll
    for (int nt = 0; nt < 8; nt++) {
        int col = nt * 8 + cp;         // even: Wg logit; col+1 odd: Wi logit
        int s = col >> 1;
        float bgv = bg[s], biv = bi[s];
        float* gout = g_gates + (size_t)(b * SSDIM + s) * TDIM + t0;
        float* dout = g_drive + (size_t)(b * SSDIM + s) * TDIM + t0;
#pragma unroll
        for (int mt = 0; mt < 4; mt++) {
#pragma unroll
            for (int half = 0; half < 2; half++) {
                int tt = wid * 64 + mt * 16 + r0 + half * 8;
                float ag = c[mt][nt][2 * half]     + bgv;
                float ai = c[mt][nt][2 * half + 1] + biv;
                float g = 1.f / (1.f + __expf(-ag));
                gout[tt] = g;
                dout[tt] = (1.f - g) * ai;
            }
        }
    }
}

// ---------------------------------------------------------------------------
extern "C" void kernel_launch(void* const* d_in, const int* in_sizes, int n_in,
                              void* d_out, int out_size)
{
    const int*   chars    = (const int*)d_in[0];
    const float* emb_byte = (const float*)d_in[1];
    const float* htab     = (const float*)d_in[2];
    const float* Wq       = (const float*)d_in[3];
    const float* bq       = (const float*)d_in[4];
    const float* conv_w   = (const float*)d_in[5];
    const float* conv_b   = (const float*)d_in[6];
    const float* Win      = (const float*)d_in[7];
    const float* b_in     = (const float*)d_in[8];
    const float* Wg       = (const float*)d_in[9];
    const float* bg       = (const float*)d_in[10];
    const float* Wi       = (const float*)d_in[11];
    const float* bi       = (const float*)d_in[12];
    const float* Wo       = (const float*)d_in[13];
    const float* bo       = (const float*)d_in[14];
    const float* lng      = (const float*)d_in[15];
    const float* lnb      = (const float*)d_in[16];
    const float* mlp_w    = (const float*)d_in[17];
    const float* mlp_b    = (const float*)d_in[18];
    const float* Wout     = (const float*)d_in[19];
    const float* bout     = (const float*)d_in[20];
    float* out = (float*)d_out;

    void *p;
    cudaGetSymbolAddress(&p, g_h);    float* gh  = (float*)p;
    cudaGetSymbolAddress(&p, g_hh);   __half* hh = (__half*)p;
    cudaGetSymbolAddress(&p, g_xh);   __half* xh  = (__half*)p;
    cudaGetSymbolAddress(&p, g_x2h);  __half* x2h = (__half*)p;
    cudaGetSymbolAddress(&p, g_wh);   __half* wh  = (__half*)p;
    cudaGetSymbolAddress(&p, g_feat); __half* feat = (__half*)p;
    cudaGetSymbolAddress(&p, g_wf);   __half* wf  = (__half*)p;

    static int attr_done = 0;
    if (!attr_done) {
        cudaFuncSetAttribute(k_mma<512,8,512,1>, cudaFuncAttributeMaxDynamicSharedMemorySize, SMEM_MM);
        cudaFuncSetAttribute(k_mma<512,8,256,0>, cudaFuncAttributeMaxDynamicSharedMemorySize, SMEM_MM);
        cudaFuncSetAttribute(k_mma<192,3,512,3>, cudaFuncAttributeMaxDynamicSharedMemorySize, SMEM_MM);
        cudaFuncSetAttribute(k_mma_g, cudaFuncAttributeMaxDynamicSharedMemorySize, SMEM_G);
        cudaFuncSetAttribute(k_wo_ln, cudaFuncAttributeMaxDynamicSharedMemorySize, WOLN_SMEM);
        attr_done = 1;
    }

    // weight prep (fp16 transpose)
    k_prep_w<<<512 * 512 / 256, 256>>>(mlp_w,                 512, 0);
    k_prep_w<<<512 * 512 / 256, 256>>>(mlp_w + 512 * 512,     512, 1);
    k_prep_w<<<512 * 512 / 256, 256>>>(mlp_w + 2 * 512 * 512, 512, 2);
    k_prep_w<<<256 * 512 / 256, 256>>>(Wout,                  256, 3);
    k_prep_wf<<<512 * 192 / 256, 256>>>(Win);
    k_prep_wgi<<<64 * 512 / 256, 256>>>(Wg, Wi);

    k_hashfeat<<<BT / 8, 256>>>(chars, emb_byte, htab, Wq, bq);
    k_feat<<<BT / 32, 256>>>(chars, emb_byte, conv_w, conv_b);

    dim3 gwin(4, BT / 256);
    // Win: feat @ Win -> silu -> f32 g_h + fp16 g_hh
    k_mma<192,3,512,3><<<gwin, 256, SMEM_MM>>>(feat, wf, b_in, gh, hh);

    // gates/drive on tensor cores
    k_mma_g<<<BT / 256, 128, SMEM_G>>>(hh, bg, bi);
    k_scan<<<BDIM * SSDIM, 256>>>();
    k_wo_ln<<<BT / 32, 256, WOLN_SMEM>>>(Wo, bo, lng, lnb);

    dim3 g512(4, BT / 256), g256(2, BT / 256);
    // L1: x = xh -> y1 = x + silu(x@W0+b) -> x2h (fp16 only)
    k_mma<512,8,512,1><<<g512, 256, SMEM_MM>>>(xh,
        wh + 0 * (size_t)512 * 512, mlp_b, 0, x2h);
    // L2: x2h -> xh
    k_mma<512,8,512,1><<<g512, 256, SMEM_MM>>>(x2h,
        wh + 1 * (size_t)512 * 512, mlp_b + 512, 0, xh);
    // L3: xh -> x2h
    k_mma<512,8,512,1><<<g512, 256, SMEM_MM>>>(xh,
        wh + 2 * (size_t)512 * 512, mlp_b + 1024, 0, x2h);
    // Wout: x2h -> out f32 [65536,256]
    k_mma<512,8,256,0><<<g256, 256, SMEM_MM>>>(x2h,
        wh + 3 * (size_t)512 * 512, bout, out, 0);
}